// round 4
// baseline (speedup 1.0000x reference)
#include <cuda_runtime.h>

// ---------------------------------------------------------------------------
// Problem constants (B=2, T=2048, H=4096, S=1024, F=9984, G=6)
// ---------------------------------------------------------------------------
#define M_TOK 4096           // B*T
#define H_DIM 4096
#define S_DIM 1024
#define F_DIM 9984
#define KU    (7 * S_DIM)    // 7168 : concat K for the fused Taylor GEMM

typedef unsigned long long ull;

// ---------------------------------------------------------------------------
// Device-global scratch (no allocations allowed anywhere)
// ---------------------------------------------------------------------------
__device__ float g_approx_up[(size_t)M_TOK * S_DIM];   //  16 MB
__device__ float g_gate_pre [(size_t)M_TOK * S_DIM];   //  16 MB
__device__ float g_U        [(size_t)M_TOK * KU];      // 117 MB
__device__ float g_W        [(size_t)H_DIM * KU];      // 117 MB
__device__ float g_gatebuf  [(size_t)M_TOK * F_DIM];   // 164 MB (silu*up in place)
__device__ float g_upbuf    [(size_t)M_TOK * F_DIM];   // 164 MB

// ---------------------------------------------------------------------------
// Packed f32x2 helpers (Blackwell FFMA2 path — 2x fp32 FMA rate vs FFMA-3reg)
// ---------------------------------------------------------------------------
__device__ __forceinline__ ull pack2(float lo, float hi) {
    ull r;
    asm("mov.b64 %0, {%1, %2};" : "=l"(r) : "f"(lo), "f"(hi));
    return r;
}
__device__ __forceinline__ void fma2(ull& d, ull a, ull b) {
    asm("fma.rn.f32x2 %0, %1, %2, %0;" : "+l"(d) : "l"(a), "l"(b));
}
__device__ __forceinline__ float2 unpack2(ull v) {
    float2 f;
    asm("mov.b64 {%0, %1}, %2;" : "=f"(f.x), "=f"(f.y) : "l"(v));
    return f;
}

// ---------------------------------------------------------------------------
// Generic GEMM: C[M,N] (+)= A[M,K] * B[N,K]^T   (A, B, C row-major)
// 128x128 tile, BK=8, 256 threads, 8x8 per-thread microtile, FFMA2 core.
// All shapes are exact multiples of the tile — no bounds checks.
// ---------------------------------------------------------------------------
__global__ __launch_bounds__(256, 2)
void gemm_nt(const float* __restrict__ A, const float* __restrict__ B,
             float* __restrict__ C, int N_, int K_, int accum)
{
    __shared__ float As[8][128];
    __shared__ float Bs[8][128];

    const int tid = threadIdx.x;
    const int tx  = tid & 15;        // 0..15 -> 8 output cols each
    const int ty  = tid >> 4;        // 0..15 -> 8 output rows each
    const int m0  = blockIdx.y << 7;
    const int n0  = blockIdx.x << 7;

    const int lr = tid >> 1;         // 0..127 : tile row loaded by this thread
    const int lc = (tid & 1) << 2;   // 0 or 4 : k-offset of its float4

    const float* Ap = A + (size_t)(m0 + lr) * K_ + lc;
    const float* Bp = B + (size_t)(n0 + lr) * K_ + lc;

    ull acc[8][4];
#pragma unroll
    for (int i = 0; i < 8; i++)
#pragma unroll
        for (int j = 0; j < 4; j++) acc[i][j] = 0ull;

    // preload tile 0
    float4 ra = *(const float4*)Ap;
    float4 rb = *(const float4*)Bp;
    As[lc + 0][lr] = ra.x; As[lc + 1][lr] = ra.y; As[lc + 2][lr] = ra.z; As[lc + 3][lr] = ra.w;
    Bs[lc + 0][lr] = rb.x; Bs[lc + 1][lr] = rb.y; Bs[lc + 2][lr] = rb.z; Bs[lc + 3][lr] = rb.w;
    __syncthreads();

    const int NK = K_ >> 3;
    for (int kt = 0; kt < NK; kt++) {
        if (kt + 1 < NK) {  // prefetch next tile into registers
            ra = *(const float4*)(Ap + ((size_t)(kt + 1) << 3));
            rb = *(const float4*)(Bp + ((size_t)(kt + 1) << 3));
        }
#pragma unroll
        for (int k = 0; k < 8; k++) {
            float4 a0 = *(const float4*)&As[k][ty << 3];
            float4 a1 = *(const float4*)&As[k][(ty << 3) + 4];
            float4 b0 = *(const float4*)&Bs[k][tx << 3];
            float4 b1 = *(const float4*)&Bs[k][(tx << 3) + 4];
            ull b2[4] = { pack2(b0.x, b0.y), pack2(b0.z, b0.w),
                          pack2(b1.x, b1.y), pack2(b1.z, b1.w) };
            ull a2[8] = { pack2(a0.x, a0.x), pack2(a0.y, a0.y),
                          pack2(a0.z, a0.z), pack2(a0.w, a0.w),
                          pack2(a1.x, a1.x), pack2(a1.y, a1.y),
                          pack2(a1.z, a1.z), pack2(a1.w, a1.w) };
#pragma unroll
            for (int i = 0; i < 8; i++)
#pragma unroll
                for (int j = 0; j < 4; j++)
                    fma2(acc[i][j], a2[i], b2[j]);
        }
        __syncthreads();
        if (kt + 1 < NK) {
            As[lc + 0][lr] = ra.x; As[lc + 1][lr] = ra.y; As[lc + 2][lr] = ra.z; As[lc + 3][lr] = ra.w;
            Bs[lc + 0][lr] = rb.x; Bs[lc + 1][lr] = rb.y; Bs[lc + 2][lr] = rb.z; Bs[lc + 3][lr] = rb.w;
            __syncthreads();
        }
    }

#pragma unroll
    for (int i = 0; i < 8; i++) {
        float* Cp = C + (size_t)(m0 + (ty << 3) + i) * N_ + n0 + (tx << 3);
        float2 v0 = unpack2(acc[i][0]);
        float2 v1 = unpack2(acc[i][1]);
        float2 v2 = unpack2(acc[i][2]);
        float2 v3 = unpack2(acc[i][3]);
        float4 o0 = make_float4(v0.x, v0.y, v1.x, v1.y);
        float4 o1 = make_float4(v2.x, v2.y, v3.x, v3.y);
        if (accum) {
            float4 c0 = *(const float4*)Cp;
            float4 c1 = *(const float4*)(Cp + 4);
            o0.x += c0.x; o0.y += c0.y; o0.z += c0.z; o0.w += c0.w;
            o1.x += c1.x; o1.y += c1.y; o1.z += c1.z; o1.w += c1.w;
        }
        *(float4*)Cp       = o0;
        *(float4*)(Cp + 4) = o1;
    }
}

// ---------------------------------------------------------------------------
// Build U[M, 7S]: block j=0 is approx_up; block j=m holds (delta^m/m!)*approx_up
// with the trust-region cutoff (|delta| <= 2.5) applied to orders m=5,6.
// Signed powers computed iteratively == exp(m*log|d| - log m!) * sign^m exactly.
// ---------------------------------------------------------------------------
__global__ void pack_U_kernel(const float* __restrict__ local_point)
{
    int i = blockIdx.x * blockDim.x + threadIdx.x;     // over M*S
    if (i >= M_TOK * S_DIM) return;
    int s = i & (S_DIM - 1);
    int m = i >> 10;

    float au    = g_approx_up[i];
    float delta = g_gate_pre[i] - local_point[s];
    float keep  = (fabsf(delta) <= 2.5f) ? 1.0f : 0.0f;

    float* Urow = g_U + (size_t)m * KU + s;
    Urow[0 * S_DIM] = au;
    float p = delta;
    Urow[1 * S_DIM] = p * au;                               // d^1/1!
    p *= delta; Urow[2 * S_DIM] = p * (1.0f / 2.0f)   * au; // d^2/2!
    p *= delta; Urow[3 * S_DIM] = p * (1.0f / 6.0f)   * au;
    p *= delta; Urow[4 * S_DIM] = p * (1.0f / 24.0f)  * au;
    p *= delta; Urow[5 * S_DIM] = p * (1.0f / 120.0f) * au * keep;
    p *= delta; Urow[6 * S_DIM] = p * (1.0f / 720.0f) * au * keep;
}

// ---------------------------------------------------------------------------
// Build Wcat[H, 7S]: block 0 = local_approx_output[H,S];
// block (idx+1) = fuse_weight[:, :, idx]  (fuse_weight is [H, S, G] row-major)
// ---------------------------------------------------------------------------
__global__ void pack_W_kernel(const float* __restrict__ lao,
                              const float* __restrict__ fuse)
{
    int i = blockIdx.x * blockDim.x + threadIdx.x;     // over H*S
    if (i >= H_DIM * S_DIM) return;
    int s = i & (S_DIM - 1);
    int h = i >> 10;

    float* Wrow = g_W + (size_t)h * KU + s;
    Wrow[0] = lao[i];
    const float* f = fuse + (size_t)i * 6;             // 24 contiguous bytes/thread
#pragma unroll
    for (int idx = 0; idx < 6; idx++)
        Wrow[(idx + 1) * S_DIM] = f[idx];
}

// ---------------------------------------------------------------------------
// act = silu(gate) * up, in place into g_gatebuf
// ---------------------------------------------------------------------------
__global__ void silu_mul_kernel()
{
    int i = blockIdx.x * blockDim.x + threadIdx.x;     // over M*F
    if (i >= M_TOK * F_DIM) return;
    float g = g_gatebuf[i];
    float u = g_upbuf[i];
    g_gatebuf[i] = u * g / (1.0f + expf(-g));
}

// ---------------------------------------------------------------------------
// Launch: 9 graph-capturable kernels, default stream, no allocations.
// ---------------------------------------------------------------------------
extern "C" void kernel_launch(void* const* d_in, const int* in_sizes, int n_in,
                              void* d_out, int out_size)
{
    const float* X   = (const float*)d_in[0];  // [M, H]
    const float* upw = (const float*)d_in[1];  // [S, H]
    const float* gw  = (const float*)d_in[2];  // [S, H]
    const float* lp  = (const float*)d_in[3];  // [S]
    const float* lao = (const float*)d_in[4];  // [H, S]
    const float* fw  = (const float*)d_in[5];  // [H, S, G]
    // d_in[6] = discount_factor (log m!) — folded in as exact 1/m! constants
    const float* fg  = (const float*)d_in[7];  // [F, H]
    const float* fu  = (const float*)d_in[8];  // [F, H]
    const float* fd  = (const float*)d_in[9];  // [H, F]
    float* out = (float*)d_out;                // [M, H]

    float *p_au, *p_gp, *p_U, *p_W, *p_g, *p_u;
    cudaGetSymbolAddress((void**)&p_au, g_approx_up);
    cudaGetSymbolAddress((void**)&p_gp, g_gate_pre);
    cudaGetSymbolAddress((void**)&p_U,  g_U);
    cudaGetSymbolAddress((void**)&p_W,  g_W);
    cudaGetSymbolAddress((void**)&p_g,  g_gatebuf);
    cudaGetSymbolAddress((void**)&p_u,  g_upbuf);

    const dim3 blk(256);
    const dim3 gS(S_DIM / 128, M_TOK / 128);   // [M,S]  outputs
    const dim3 gH(H_DIM / 128, M_TOK / 128);   // [M,H]  outputs
    const dim3 gF(F_DIM / 128, M_TOK / 128);   // [M,F]  outputs

    // Sampled path pre-GEMMs
    gemm_nt<<<gS, blk>>>(X, upw, p_au, S_DIM, H_DIM, 0);   // approx_up
    gemm_nt<<<gS, blk>>>(X, gw,  p_gp, S_DIM, H_DIM, 0);   // gate_pre

    // Pack concatenated operands for the fused Taylor GEMM
    pack_W_kernel<<<(H_DIM * S_DIM) / 256, blk>>>(lao, fw);
    pack_U_kernel<<<(M_TOK * S_DIM) / 256, blk>>>(lp);

    // approx_out = U @ Wcat^T   (zeroth + all 6 orders in one GEMM)
    gemm_nt<<<gH, blk>>>(p_U, p_W, out, H_DIM, KU, 0);

    // FFN path
    gemm_nt<<<gF, blk>>>(X, fg, p_g, F_DIM, H_DIM, 0);     // gate
    gemm_nt<<<gF, blk>>>(X, fu, p_u, F_DIM, H_DIM, 0);     // up
    silu_mul_kernel<<<(M_TOK * F_DIM) / 256, blk>>>();     // act in place
    gemm_nt<<<gH, blk>>>(p_g, fd, out, H_DIM, F_DIM, 1);   // out += act @ down^T
}

// round 6
// speedup vs baseline: 3.0281x; 3.0281x over previous
#include <cuda_runtime.h>
#include <cuda_fp16.h>
#include <cstdint>

// ---------------------------------------------------------------------------
// Problem constants (B=2, T=2048, H=4096, S=1024, F=9984, G=6)
// ---------------------------------------------------------------------------
#define M_TOK 4096
#define H_DIM 4096
#define S_DIM 1024
#define F_DIM 9984
#define KU    7168          // 7*S : concat K for the fused Taylor GEMM

typedef unsigned long long ull;

// ---------------------------------------------------------------------------
// Device-global scratch (no allocations allowed anywhere)
// ---------------------------------------------------------------------------
__device__ float g_approx_up[(size_t)M_TOK * S_DIM];
__device__ float g_gate_pre [(size_t)M_TOK * S_DIM];
__device__ float g_gatebuf  [(size_t)M_TOK * F_DIM];
__device__ float g_upbuf    [(size_t)M_TOK * F_DIM];

__device__ __half g_Xhi [(size_t)M_TOK * H_DIM];
__device__ __half g_Xlo [(size_t)M_TOK * H_DIM];
__device__ __half g_fghi[(size_t)F_DIM * H_DIM];
__device__ __half g_fglo[(size_t)F_DIM * H_DIM];
__device__ __half g_fuhi[(size_t)F_DIM * H_DIM];
__device__ __half g_fulo[(size_t)F_DIM * H_DIM];
__device__ __half g_fdhi[(size_t)H_DIM * F_DIM];
__device__ __half g_fdlo[(size_t)H_DIM * F_DIM];
__device__ __half g_Uhi [(size_t)M_TOK * KU];
__device__ __half g_Ulo [(size_t)M_TOK * KU];
__device__ __half g_Whi [(size_t)H_DIM * KU];
__device__ __half g_Wlo [(size_t)H_DIM * KU];
__device__ __half g_acthi[(size_t)M_TOK * F_DIM];
__device__ __half g_actlo[(size_t)M_TOK * F_DIM];

// ---------------------------------------------------------------------------
// PTX helpers (baseline sm_103 only — NO tcgen05/'a' features)
// ---------------------------------------------------------------------------
__device__ __forceinline__ uint32_t smem_u32(const void* p) {
    uint32_t a;
    asm("{ .reg .u64 t; cvta.to.shared.u64 t, %1; cvt.u32.u64 %0, t; }" : "=r"(a) : "l"(p));
    return a;
}
__device__ __forceinline__ void cp16(uint32_t so, const void* gp) {
    asm volatile("cp.async.cg.shared.global [%0], [%1], 16;" :: "r"(so), "l"(gp));
}
__device__ __forceinline__ void ldsm4(uint32_t& r0, uint32_t& r1, uint32_t& r2, uint32_t& r3,
                                      uint32_t addr) {
    asm volatile("ldmatrix.sync.aligned.m8n8.x4.shared.b16 {%0,%1,%2,%3}, [%4];"
                 : "=r"(r0), "=r"(r1), "=r"(r2), "=r"(r3) : "r"(addr));
}
__device__ __forceinline__ void hmma(float* c, const uint32_t* a, const uint32_t* b) {
    asm volatile(
        "mma.sync.aligned.m16n8k16.row.col.f32.f16.f16.f32 "
        "{%0,%1,%2,%3}, {%4,%5,%6,%7}, {%8,%9}, {%0,%1,%2,%3};"
        : "+f"(c[0]), "+f"(c[1]), "+f"(c[2]), "+f"(c[3])
        : "r"(a[0]), "r"(a[1]), "r"(a[2]), "r"(a[3]), "r"(b[0]), "r"(b[1]));
}

// ---------------------------------------------------------------------------
// fp16x3 split-precision tensor GEMM via mma.sync:
//   C[M,N] (+)= (Ahi+Alo)[M,K] * (Bhi+Blo)[N,K]^T  (lo*lo dropped)
// CTA tile 128x128, warp tile 64x32 (2x4 warps), K-slab 64, 3-stage cp.async.
// Smem slab layout: [Ahi 16K][Alo 16K][Bhi 16K][Blo 16K] = 64KB, 128B rows,
// SW128 swizzle: off = row*128 + ((kb ^ (row&7))<<4), kb = 16B unit.
// ---------------------------------------------------------------------------
#define STAGE_BYTES 65536
#define NSTAGE 3
#define H16_SMEM (NSTAGE * STAGE_BYTES)

__global__ __launch_bounds__(256, 1)
void gemm_h16(const __half* __restrict__ Ahi, const __half* __restrict__ Alo,
              const __half* __restrict__ Bhi, const __half* __restrict__ Blo,
              float* __restrict__ C, int N_, int K_, int accum)
{
    extern __shared__ char smem[];
    const uint32_t sb = smem_u32(smem);
    const int tid  = threadIdx.x;
    const int wid  = tid >> 5;
    const int lane = tid & 31;
    const int m0 = blockIdx.y << 7;
    const int n0 = blockIdx.x << 7;
    const int wm = (wid >> 2) * 64;     // warp m offset (0/64)
    const int wn = (wid & 3) * 32;      // warp n offset (0..96)

    const int NC = K_ >> 6;             // number of 64-wide K slabs

    auto load_chunk = [&](int kt, int s) {
        const uint32_t st = sb + (uint32_t)s * STAGE_BYTES;
        const size_t kof = (size_t)kt << 6;
#pragma unroll
        for (int i = 0; i < 8; i++) {               // A planes: 2048 16B units
            int e = i * 256 + tid;
            int p = e >> 10, row = (e >> 3) & 127, kb = e & 7;
            const __half* src = (p ? Alo : Ahi) + (size_t)(m0 + row) * K_ + kof + kb * 8;
            cp16(st + p * 16384 + row * 128 + ((kb ^ (row & 7)) << 4), src);
        }
#pragma unroll
        for (int i = 0; i < 8; i++) {               // B planes
            int e = i * 256 + tid;
            int p = e >> 10, row = (e >> 3) & 127, kb = e & 7;
            const __half* src = (p ? Blo : Bhi) + (size_t)(n0 + row) * K_ + kof + kb * 8;
            cp16(st + 32768 + p * 16384 + row * 128 + ((kb ^ (row & 7)) << 4), src);
        }
    };

    load_chunk(0, 0);
    asm volatile("cp.async.commit_group;" ::: "memory");
    load_chunk(1, 1);
    asm volatile("cp.async.commit_group;" ::: "memory");
    load_chunk(2, 2);
    asm volatile("cp.async.commit_group;" ::: "memory");

    float acc[4][4][4];
#pragma unroll
    for (int i = 0; i < 4; i++)
#pragma unroll
        for (int j = 0; j < 4; j++)
#pragma unroll
            for (int q = 0; q < 4; q++) acc[i][j][q] = 0.0f;

    // ldmatrix lane-address components (row/col selectors are lane-fixed)
    const int a_rsel = lane & 15;            // A row within 16
    const int a_ksel = lane >> 4;            // A kb half (0/1)
    const int b_rsel = (lane & 7) + (((lane >> 4) & 1) << 3);  // B n within 16
    const int b_ksel = (lane >> 3) & 1;      // B kb half

    for (int kt = 0; kt < NC; kt++) {
        const int s = kt % NSTAGE;
        asm volatile("cp.async.wait_group %0;" :: "n"(NSTAGE - 1) : "memory");
        __syncthreads();

        const uint32_t stA = sb + (uint32_t)s * STAGE_BYTES;
        const uint32_t stB = stA + 32768;

#pragma unroll
        for (int kk = 0; kk < 4; kk++) {
            uint32_t Ah[4][4], Al[4][4], Bh[4][2], Bl[4][2];
            const int akb = kk * 2 + a_ksel;
            const int bkb = kk * 2 + b_ksel;
#pragma unroll
            for (int mi = 0; mi < 4; mi++) {
                int row = wm + mi * 16 + a_rsel;
                uint32_t off = row * 128 + (((akb) ^ (row & 7)) << 4);
                ldsm4(Ah[mi][0], Ah[mi][1], Ah[mi][2], Ah[mi][3], stA + off);
                ldsm4(Al[mi][0], Al[mi][1], Al[mi][2], Al[mi][3], stA + 16384 + off);
            }
#pragma unroll
            for (int nt = 0; nt < 2; nt++) {     // each x4 covers 2 n-tiles (16 cols)
                int nrow = wn + nt * 16 + b_rsel;
                uint32_t off = nrow * 128 + (((bkb) ^ (nrow & 7)) << 4);
                ldsm4(Bh[2 * nt][0], Bh[2 * nt][1], Bh[2 * nt + 1][0], Bh[2 * nt + 1][1],
                      stB + off);
                ldsm4(Bl[2 * nt][0], Bl[2 * nt][1], Bl[2 * nt + 1][0], Bl[2 * nt + 1][1],
                      stB + 16384 + off);
            }
#pragma unroll
            for (int mi = 0; mi < 4; mi++)
#pragma unroll
                for (int ni = 0; ni < 4; ni++) {
                    hmma(acc[mi][ni], Ah[mi], Bh[ni]);
                    hmma(acc[mi][ni], Ah[mi], Bl[ni]);
                    hmma(acc[mi][ni], Al[mi], Bh[ni]);
                }
        }
        __syncthreads();
        if (kt + NSTAGE < NC) load_chunk(kt + NSTAGE, s);
        asm volatile("cp.async.commit_group;" ::: "memory");
    }

    // Epilogue: acc -> C (optionally accumulate into existing C)
    const int erow = lane >> 2;
    const int ecol = (lane & 3) * 2;
#pragma unroll
    for (int mi = 0; mi < 4; mi++)
#pragma unroll
        for (int ni = 0; ni < 4; ni++) {
            float* Cp0 = C + (size_t)(m0 + wm + mi * 16 + erow) * N_ + n0 + wn + ni * 8 + ecol;
            float* Cp1 = Cp0 + (size_t)8 * N_;
            float2 v0 = make_float2(acc[mi][ni][0], acc[mi][ni][1]);
            float2 v1 = make_float2(acc[mi][ni][2], acc[mi][ni][3]);
            if (accum) {
                float2 o0 = *(const float2*)Cp0;
                float2 o1 = *(const float2*)Cp1;
                v0.x += o0.x; v0.y += o0.y;
                v1.x += o1.x; v1.y += o1.y;
            }
            *(float2*)Cp0 = v0;
            *(float2*)Cp1 = v1;
        }
}

// ---------------------------------------------------------------------------
// FFMA2 fp32 GEMM (exact) — for gate_pre / approx_up (mask-critical path)
// ---------------------------------------------------------------------------
__device__ __forceinline__ ull pack2(float lo, float hi) {
    ull r; asm("mov.b64 %0, {%1, %2};" : "=l"(r) : "f"(lo), "f"(hi)); return r;
}
__device__ __forceinline__ void fma2(ull& d, ull a, ull b) {
    asm("fma.rn.f32x2 %0, %1, %2, %0;" : "+l"(d) : "l"(a), "l"(b));
}
__device__ __forceinline__ float2 unpack2(ull v) {
    float2 f; asm("mov.b64 {%0, %1}, %2;" : "=f"(f.x), "=f"(f.y) : "l"(v)); return f;
}

__global__ __launch_bounds__(256, 2)
void gemm_nt(const float* __restrict__ A, const float* __restrict__ B,
             float* __restrict__ C, int N_, int K_)
{
    __shared__ float As[8][128];
    __shared__ float Bs[8][128];

    const int tid = threadIdx.x;
    const int tx = tid & 15, ty = tid >> 4;
    const int m0 = blockIdx.y << 7, n0 = blockIdx.x << 7;
    const int lr = tid >> 1, lc = (tid & 1) << 2;

    const float* Ap = A + (size_t)(m0 + lr) * K_ + lc;
    const float* Bp = B + (size_t)(n0 + lr) * K_ + lc;

    ull acc[8][4];
#pragma unroll
    for (int i = 0; i < 8; i++)
#pragma unroll
        for (int j = 0; j < 4; j++) acc[i][j] = 0ull;

    float4 ra = *(const float4*)Ap;
    float4 rb = *(const float4*)Bp;
    As[lc+0][lr]=ra.x; As[lc+1][lr]=ra.y; As[lc+2][lr]=ra.z; As[lc+3][lr]=ra.w;
    Bs[lc+0][lr]=rb.x; Bs[lc+1][lr]=rb.y; Bs[lc+2][lr]=rb.z; Bs[lc+3][lr]=rb.w;
    __syncthreads();

    const int NK = K_ >> 3;
    for (int kt = 0; kt < NK; kt++) {
        if (kt + 1 < NK) {
            ra = *(const float4*)(Ap + ((size_t)(kt + 1) << 3));
            rb = *(const float4*)(Bp + ((size_t)(kt + 1) << 3));
        }
#pragma unroll
        for (int k = 0; k < 8; k++) {
            float4 a0 = *(const float4*)&As[k][ty << 3];
            float4 a1 = *(const float4*)&As[k][(ty << 3) + 4];
            float4 b0 = *(const float4*)&Bs[k][tx << 3];
            float4 b1 = *(const float4*)&Bs[k][(tx << 3) + 4];
            ull b2[4] = { pack2(b0.x,b0.y), pack2(b0.z,b0.w), pack2(b1.x,b1.y), pack2(b1.z,b1.w) };
            ull a2[8] = { pack2(a0.x,a0.x), pack2(a0.y,a0.y), pack2(a0.z,a0.z), pack2(a0.w,a0.w),
                          pack2(a1.x,a1.x), pack2(a1.y,a1.y), pack2(a1.z,a1.z), pack2(a1.w,a1.w) };
#pragma unroll
            for (int i = 0; i < 8; i++)
#pragma unroll
                for (int j = 0; j < 4; j++) fma2(acc[i][j], a2[i], b2[j]);
        }
        __syncthreads();
        if (kt + 1 < NK) {
            As[lc+0][lr]=ra.x; As[lc+1][lr]=ra.y; As[lc+2][lr]=ra.z; As[lc+3][lr]=ra.w;
            Bs[lc+0][lr]=rb.x; Bs[lc+1][lr]=rb.y; Bs[lc+2][lr]=rb.z; Bs[lc+3][lr]=rb.w;
            __syncthreads();
        }
    }
#pragma unroll
    for (int i = 0; i < 8; i++) {
        float* Cp = C + (size_t)(m0 + (ty << 3) + i) * N_ + n0 + (tx << 3);
        float2 v0 = unpack2(acc[i][0]), v1 = unpack2(acc[i][1]);
        float2 v2 = unpack2(acc[i][2]), v3 = unpack2(acc[i][3]);
        *(float4*)Cp       = make_float4(v0.x, v0.y, v1.x, v1.y);
        *(float4*)(Cp + 4) = make_float4(v2.x, v2.y, v3.x, v3.y);
    }
}

// ---------------------------------------------------------------------------
// Elementwise kernels (fp32 -> fp16 hi/lo splits)
// ---------------------------------------------------------------------------
__device__ __forceinline__ void split1h(float x, __half& h, __half& l) {
    h = __float2half_rn(x);
    l = __float2half_rn(x - __half2float(h));
}

__global__ void split_kernel(const float* __restrict__ x, __half* __restrict__ hi,
                             __half* __restrict__ lo)
{
    size_t i = ((size_t)blockIdx.x * blockDim.x + threadIdx.x) * 4;
    float4 v = *(const float4*)(x + i);
    __half2 h01, h23, l01, l23;
    __half h, l;
    split1h(v.x, h, l); h01.x = h; l01.x = l;
    split1h(v.y, h, l); h01.y = h; l01.y = l;
    split1h(v.z, h, l); h23.x = h; l23.x = l;
    split1h(v.w, h, l); h23.y = h; l23.y = l;
    *(__half2*)(hi + i)     = h01;
    *(__half2*)(hi + i + 2) = h23;
    *(__half2*)(lo + i)     = l01;
    *(__half2*)(lo + i + 2) = l23;
}

__global__ void pack_U_kernel(const float* __restrict__ local_point)
{
    int i = blockIdx.x * blockDim.x + threadIdx.x;      // over M*S
    int s = i & (S_DIM - 1);
    float au    = g_approx_up[i];
    float delta = g_gate_pre[i] - local_point[s];
    float keep  = (fabsf(delta) <= 2.5f) ? 1.0f : 0.0f;

    float v[7];
    v[0] = au;
    float p = delta;
    v[1] = p * au;
    p *= delta; v[2] = p * (1.0f / 2.0f)   * au;
    p *= delta; v[3] = p * (1.0f / 6.0f)   * au;
    p *= delta; v[4] = p * (1.0f / 24.0f)  * au;
    p *= delta; v[5] = p * (1.0f / 120.0f) * au * keep;
    p *= delta; v[6] = p * (1.0f / 720.0f) * au * keep;

    size_t base = (size_t)(i >> 10) * KU + s;
#pragma unroll
    for (int j = 0; j < 7; j++) {
        __half h, l; split1h(v[j], h, l);
        g_Uhi[base + j * S_DIM] = h;
        g_Ulo[base + j * S_DIM] = l;
    }
}

__global__ void pack_W_kernel(const float* __restrict__ lao, const float* __restrict__ fuse)
{
    int i = blockIdx.x * blockDim.x + threadIdx.x;      // over H*S
    int s = i & (S_DIM - 1);
    size_t base = (size_t)(i >> 10) * KU + s;
    __half h, l;
    split1h(lao[i], h, l);
    g_Whi[base] = h;
    g_Wlo[base] = l;
    const float* f = fuse + (size_t)i * 6;
#pragma unroll
    for (int idx = 0; idx < 6; idx++) {
        split1h(f[idx], h, l);
        g_Whi[base + (idx + 1) * S_DIM] = h;
        g_Wlo[base + (idx + 1) * S_DIM] = l;
    }
}

__global__ void silu_split_kernel()
{
    size_t i = ((size_t)blockIdx.x * blockDim.x + threadIdx.x) * 4;
    float4 g = *(const float4*)(g_gatebuf + i);
    float4 u = *(const float4*)(g_upbuf + i);
    float a0 = u.x * g.x / (1.0f + expf(-g.x));
    float a1 = u.y * g.y / (1.0f + expf(-g.y));
    float a2 = u.z * g.z / (1.0f + expf(-g.z));
    float a3 = u.w * g.w / (1.0f + expf(-g.w));
    __half2 h01, h23, l01, l23;
    __half h, l;
    split1h(a0, h, l); h01.x = h; l01.x = l;
    split1h(a1, h, l); h01.y = h; l01.y = l;
    split1h(a2, h, l); h23.x = h; l23.x = l;
    split1h(a3, h, l); h23.y = h; l23.y = l;
    *(__half2*)(g_acthi + i)     = h01;
    *(__half2*)(g_acthi + i + 2) = h23;
    *(__half2*)(g_actlo + i)     = l01;
    *(__half2*)(g_actlo + i + 2) = l23;
}

// ---------------------------------------------------------------------------
// Launch: all graph-capturable, default stream, no allocations.
// ---------------------------------------------------------------------------
extern "C" void kernel_launch(void* const* d_in, const int* in_sizes, int n_in,
                              void* d_out, int out_size)
{
    const float* X   = (const float*)d_in[0];
    const float* upw = (const float*)d_in[1];
    const float* gw  = (const float*)d_in[2];
    const float* lp  = (const float*)d_in[3];
    const float* lao = (const float*)d_in[4];
    const float* fw  = (const float*)d_in[5];
    const float* fg  = (const float*)d_in[7];
    const float* fu  = (const float*)d_in[8];
    const float* fd  = (const float*)d_in[9];
    float* out = (float*)d_out;

    cudaFuncSetAttribute(gemm_h16, cudaFuncAttributeMaxDynamicSharedMemorySize, H16_SMEM);

    float *p_au, *p_gp, *p_g, *p_u;
    __half *p_Xhi, *p_Xlo, *p_fghi, *p_fglo, *p_fuhi, *p_fulo, *p_fdhi, *p_fdlo;
    __half *p_Uhi, *p_Ulo, *p_Whi, *p_Wlo, *p_ahi, *p_alo;
    cudaGetSymbolAddress((void**)&p_au,   g_approx_up);
    cudaGetSymbolAddress((void**)&p_gp,   g_gate_pre);
    cudaGetSymbolAddress((void**)&p_g,    g_gatebuf);
    cudaGetSymbolAddress((void**)&p_u,    g_upbuf);
    cudaGetSymbolAddress((void**)&p_Xhi,  g_Xhi);
    cudaGetSymbolAddress((void**)&p_Xlo,  g_Xlo);
    cudaGetSymbolAddress((void**)&p_fghi, g_fghi);
    cudaGetSymbolAddress((void**)&p_fglo, g_fglo);
    cudaGetSymbolAddress((void**)&p_fuhi, g_fuhi);
    cudaGetSymbolAddress((void**)&p_fulo, g_fulo);
    cudaGetSymbolAddress((void**)&p_fdhi, g_fdhi);
    cudaGetSymbolAddress((void**)&p_fdlo, g_fdlo);
    cudaGetSymbolAddress((void**)&p_Uhi,  g_Uhi);
    cudaGetSymbolAddress((void**)&p_Ulo,  g_Ulo);
    cudaGetSymbolAddress((void**)&p_Whi,  g_Whi);
    cudaGetSymbolAddress((void**)&p_Wlo,  g_Wlo);
    cudaGetSymbolAddress((void**)&p_ahi,  g_acthi);
    cudaGetSymbolAddress((void**)&p_alo,  g_actlo);

    const dim3 blk(256);
    const size_t MH = (size_t)M_TOK * H_DIM;
    const size_t FH = (size_t)F_DIM * H_DIM;
    const size_t MF = (size_t)M_TOK * F_DIM;

    // Split inputs to fp16 hi/lo planes
    split_kernel<<<(unsigned)(MH / 1024), blk>>>(X,  p_Xhi,  p_Xlo);
    split_kernel<<<(unsigned)(FH / 1024), blk>>>(fg, p_fghi, p_fglo);
    split_kernel<<<(unsigned)(FH / 1024), blk>>>(fu, p_fuhi, p_fulo);
    split_kernel<<<(unsigned)(FH / 1024), blk>>>(fd, p_fdhi, p_fdlo);

    // Exact fp32 GEMMs for the mask-critical pre-activations
    gemm_nt<<<dim3(S_DIM / 128, M_TOK / 128), blk>>>(X, upw, p_au, S_DIM, H_DIM);
    gemm_nt<<<dim3(S_DIM / 128, M_TOK / 128), blk>>>(X, gw,  p_gp, S_DIM, H_DIM);

    // Pack fused Taylor operands directly as fp16 hi/lo
    pack_W_kernel<<<(H_DIM * S_DIM) / 256, blk>>>(lao, fw);
    pack_U_kernel<<<(M_TOK * S_DIM) / 256, blk>>>(lp);

    // Taylor GEMM: out = U @ Wcat^T  (fp16x3 mma.sync)
    gemm_h16<<<dim3(H_DIM / 128, M_TOK / 128), blk, H16_SMEM>>>(
        p_Uhi, p_Ulo, p_Whi, p_Wlo, out, H_DIM, KU, 0);

    // FFN path
    gemm_h16<<<dim3(F_DIM / 128, M_TOK / 128), blk, H16_SMEM>>>(
        p_Xhi, p_Xlo, p_fghi, p_fglo, p_g, F_DIM, H_DIM, 0);
    gemm_h16<<<dim3(F_DIM / 128, M_TOK / 128), blk, H16_SMEM>>>(
        p_Xhi, p_Xlo, p_fuhi, p_fulo, p_u, F_DIM, H_DIM, 0);
    silu_split_kernel<<<(unsigned)(MF / 1024), blk>>>();

    // out += act @ down^T  (accumulates into the Taylor result in the epilogue)
    gemm_h16<<<dim3(H_DIM / 128, M_TOK / 128), blk, H16_SMEM>>>(
        p_ahi, p_alo, p_fdhi, p_fdlo, out, H_DIM, F_DIM, 1);
}

// round 7
// speedup vs baseline: 4.7806x; 1.5788x over previous
#include <cuda_runtime.h>
#include <cuda_fp16.h>
#include <cstdint>

// ---------------------------------------------------------------------------
// Problem constants (B=2, T=2048, H=4096, S=1024, F=9984, G=6)
// ---------------------------------------------------------------------------
#define M_TOK 4096
#define H_DIM 4096
#define S_DIM 1024
#define F_DIM 9984
#define KU    7168          // 7*S : concat K for the fused Taylor GEMM

// ---------------------------------------------------------------------------
// Device-global scratch (no allocations allowed anywhere)
// ---------------------------------------------------------------------------
__device__ __half g_Xhi  [(size_t)M_TOK * H_DIM];
__device__ __half g_Xlo  [(size_t)M_TOK * H_DIM];
__device__ __half g_ugh  [(size_t)2 * S_DIM * H_DIM];   // interleaved up_w/gate_w hi
__device__ __half g_ugl  [(size_t)2 * S_DIM * H_DIM];   // lo
__device__ __half g_Whi  [(size_t)H_DIM * KU];
__device__ __half g_Wlo  [(size_t)H_DIM * KU];
__device__ __half g_fgfuh[(size_t)2 * F_DIM * H_DIM];   // interleaved fg/fu hi
__device__ __half g_fgful[(size_t)2 * F_DIM * H_DIM];   // lo
__device__ __half g_fdh  [(size_t)H_DIM * F_DIM];
__device__ __half g_fdl  [(size_t)H_DIM * F_DIM];
__device__ __half g_Uh   [(size_t)M_TOK * KU];          // Taylor U (hi only)
__device__ __half g_acth [(size_t)M_TOK * F_DIM];       // silu(g)*u (hi only)

// ---------------------------------------------------------------------------
// PTX helpers (baseline sm_103 — no tcgen05)
// ---------------------------------------------------------------------------
__device__ __forceinline__ uint32_t smem_u32(const void* p) {
    uint32_t a;
    asm("{ .reg .u64 t; cvta.to.shared.u64 t, %1; cvt.u32.u64 %0, t; }" : "=r"(a) : "l"(p));
    return a;
}
__device__ __forceinline__ void cp16(uint32_t so, const void* gp) {
    asm volatile("cp.async.cg.shared.global [%0], [%1], 16;" :: "r"(so), "l"(gp));
}
__device__ __forceinline__ void ldsm4(uint32_t& r0, uint32_t& r1, uint32_t& r2, uint32_t& r3,
                                      uint32_t addr) {
    asm volatile("ldmatrix.sync.aligned.m8n8.x4.shared.b16 {%0,%1,%2,%3}, [%4];"
                 : "=r"(r0), "=r"(r1), "=r"(r2), "=r"(r3) : "r"(addr));
}
__device__ __forceinline__ void hmma(float* c, const uint32_t* a, const uint32_t* b) {
    asm volatile(
        "mma.sync.aligned.m16n8k16.row.col.f32.f16.f16.f32 "
        "{%0,%1,%2,%3}, {%4,%5,%6,%7}, {%8,%9}, {%0,%1,%2,%3};"
        : "+f"(c[0]), "+f"(c[1]), "+f"(c[2]), "+f"(c[3])
        : "r"(a[0]), "r"(a[1]), "r"(a[2]), "r"(a[3]), "r"(b[0]), "r"(b[1]));
}
__device__ __forceinline__ void split1h(float x, __half& h, __half& l) {
    h = __float2half_rn(x);
    l = __float2half_rn(x - __half2float(h));
}

// ===========================================================================
// K1: 2-term split GEMM  C[M,N] = Ahi[M,K] * (Bhi+Blo)[N,K]^T
// CTA tile 128x256, 8 warps (2m x 4n), warp tile 64x64, K-slab 64,
// 2-stage cp.async double buffer. Stage: A 16KB | Bhi 32KB | Blo 32KB = 80KB.
// MODE 0: store fp32 C.  MODE 1: accumulate into fp32 C.
// MODE 2: columns are interleaved (gate,up) pairs -> act = silu(g)*u, store
//         fp16 into actout[M, N/2].
// ===========================================================================
#define K1_STAGE 81920
#define K1_SMEM  (2 * K1_STAGE)

template <int MODE>
__global__ __launch_bounds__(256, 1)
void gemm_2t(const __half* __restrict__ A,
             const __half* __restrict__ Bhi, const __half* __restrict__ Blo,
             float* __restrict__ C, __half* __restrict__ actout,
             int N_, int K_)
{
    extern __shared__ char smem[];
    const uint32_t sb = smem_u32(smem);
    const int tid  = threadIdx.x;
    const int wid  = tid >> 5;
    const int lane = tid & 31;
    const int m0 = blockIdx.y << 7;
    const int n0 = blockIdx.x << 8;
    const int wm = (wid & 1) * 64;
    const int wn = (wid >> 1) * 64;

    const int NC = K_ >> 6;

    auto load_chunk = [&](int kt, int s) {
        const uint32_t st = sb + (uint32_t)s * K1_STAGE;
        const size_t kof = (size_t)kt << 6;
#pragma unroll
        for (int i = 0; i < 4; i++) {                   // A hi: 1024 16B units
            int e = i * 256 + tid, row = e >> 3, kb = e & 7;
            cp16(st + row * 128 + ((kb ^ (row & 7)) << 4),
                 A + (size_t)(m0 + row) * K_ + kof + kb * 8);
        }
#pragma unroll
        for (int i = 0; i < 8; i++) {                   // B hi: 2048 units (256 rows)
            int e = i * 256 + tid, row = e >> 3, kb = e & 7;
            cp16(st + 16384 + row * 128 + ((kb ^ (row & 7)) << 4),
                 Bhi + (size_t)(n0 + row) * K_ + kof + kb * 8);
        }
#pragma unroll
        for (int i = 0; i < 8; i++) {                   // B lo
            int e = i * 256 + tid, row = e >> 3, kb = e & 7;
            cp16(st + 49152 + row * 128 + ((kb ^ (row & 7)) << 4),
                 Blo + (size_t)(n0 + row) * K_ + kof + kb * 8);
        }
    };

    load_chunk(0, 0);
    asm volatile("cp.async.commit_group;" ::: "memory");
    load_chunk(1, 1);
    asm volatile("cp.async.commit_group;" ::: "memory");

    float acc[4][8][4];
#pragma unroll
    for (int i = 0; i < 4; i++)
#pragma unroll
        for (int j = 0; j < 8; j++)
#pragma unroll
            for (int q = 0; q < 4; q++) acc[i][j][q] = 0.0f;

    const int a_rsel = lane & 15;
    const int a_ksel = lane >> 4;
    const int b_rsel = (lane & 7) + (((lane >> 4) & 1) << 3);
    const int b_ksel = (lane >> 3) & 1;

    for (int kt = 0; kt < NC; kt++) {
        const int s = kt & 1;
        asm volatile("cp.async.wait_group 1;" ::: "memory");
        __syncthreads();

        const uint32_t stg = sb + (uint32_t)s * K1_STAGE;
#pragma unroll
        for (int kk = 0; kk < 4; kk++) {
            uint32_t a[4][4];
            const int akb = kk * 2 + a_ksel;
            const int bkb = kk * 2 + b_ksel;
#pragma unroll
            for (int mi = 0; mi < 4; mi++) {
                int row = wm + mi * 16 + a_rsel;
                ldsm4(a[mi][0], a[mi][1], a[mi][2], a[mi][3],
                      stg + row * 128 + ((akb ^ (row & 7)) << 4));
            }
#pragma unroll
            for (int nt = 0; nt < 4; nt++) {
                int nrow = wn + nt * 16 + b_rsel;
                uint32_t offB = nrow * 128 + ((bkb ^ (nrow & 7)) << 4);
                uint32_t bh0[2], bh1[2], bl0[2], bl1[2];
                ldsm4(bh0[0], bh0[1], bh1[0], bh1[1], stg + 16384 + offB);
                ldsm4(bl0[0], bl0[1], bl1[0], bl1[1], stg + 49152 + offB);
#pragma unroll
                for (int mi = 0; mi < 4; mi++) {
                    hmma(acc[mi][2 * nt],     a[mi], bh0);
                    hmma(acc[mi][2 * nt + 1], a[mi], bh1);
                }
#pragma unroll
                for (int mi = 0; mi < 4; mi++) {
                    hmma(acc[mi][2 * nt],     a[mi], bl0);
                    hmma(acc[mi][2 * nt + 1], a[mi], bl1);
                }
            }
        }
        __syncthreads();
        if (kt + 2 < NC) load_chunk(kt + 2, s);
        asm volatile("cp.async.commit_group;" ::: "memory");
    }

    // Epilogue
    const int erow = lane >> 2;
    const int ecol = (lane & 3) * 2;
#pragma unroll
    for (int mi = 0; mi < 4; mi++)
#pragma unroll
        for (int ni = 0; ni < 8; ni++) {
            const int r0 = m0 + wm + mi * 16 + erow;
            if (MODE == 2) {
                const int F = N_ >> 1;
                const int f = ((n0 + wn) >> 1) + ni * 4 + (lane & 3);
                float g0 = acc[mi][ni][0], u0 = acc[mi][ni][1];
                float g1 = acc[mi][ni][2], u1 = acc[mi][ni][3];
                float a0 = u0 * g0 / (1.0f + __expf(-g0));
                float a1 = u1 * g1 / (1.0f + __expf(-g1));
                actout[(size_t)r0 * F + f]       = __float2half_rn(a0);
                actout[(size_t)(r0 + 8) * F + f] = __float2half_rn(a1);
            } else {
                float* Cp0 = C + (size_t)r0 * N_ + n0 + wn + ni * 8 + ecol;
                float* Cp1 = Cp0 + (size_t)8 * N_;
                float2 v0 = make_float2(acc[mi][ni][0], acc[mi][ni][1]);
                float2 v1 = make_float2(acc[mi][ni][2], acc[mi][ni][3]);
                if (MODE == 1) {
                    float2 o0 = *(const float2*)Cp0;
                    float2 o1 = *(const float2*)Cp1;
                    v0.x += o0.x; v0.y += o0.y;
                    v1.x += o1.x; v1.y += o1.y;
                }
                *(float2*)Cp0 = v0;
                *(float2*)Cp1 = v1;
            }
        }
}

// ===========================================================================
// K2: fp16x3 split GEMM (full precision) over interleaved [up_w;gate_w].
// CTA 128x128, 8 warps (2m x 4n), warp 64x32, K-slab 64, 3-stage pipeline.
// Columns pair as (approx_up, gate_pre); epilogue computes all 7 Taylor
// coefficients and writes U directly as fp16 to g_Uh[M, 7168].
// ===========================================================================
#define K2_STAGE 65536
#define K2_SMEM  (3 * K2_STAGE)

__global__ __launch_bounds__(256, 1)
void gemm1_u(const __half* __restrict__ Ahi, const __half* __restrict__ Alo,
             const __half* __restrict__ Bhi, const __half* __restrict__ Blo,
             const float* __restrict__ lp, __half* __restrict__ Uout,
             int N_, int K_)
{
    extern __shared__ char smem[];
    const uint32_t sb = smem_u32(smem);
    const int tid  = threadIdx.x;
    const int wid  = tid >> 5;
    const int lane = tid & 31;
    const int m0 = blockIdx.y << 7;
    const int n0 = blockIdx.x << 7;
    const int wm = (wid >> 2) * 64;
    const int wn = (wid & 3) * 32;

    const int NC = K_ >> 6;

    auto load_chunk = [&](int kt, int s) {
        const uint32_t st = sb + (uint32_t)s * K2_STAGE;
        const size_t kof = (size_t)kt << 6;
#pragma unroll
        for (int i = 0; i < 8; i++) {
            int e = i * 256 + tid;
            int p = e >> 10, row = (e >> 3) & 127, kb = e & 7;
            const __half* src = (p ? Alo : Ahi) + (size_t)(m0 + row) * K_ + kof + kb * 8;
            cp16(st + p * 16384 + row * 128 + ((kb ^ (row & 7)) << 4), src);
        }
#pragma unroll
        for (int i = 0; i < 8; i++) {
            int e = i * 256 + tid;
            int p = e >> 10, row = (e >> 3) & 127, kb = e & 7;
            const __half* src = (p ? Blo : Bhi) + (size_t)(n0 + row) * K_ + kof + kb * 8;
            cp16(st + 32768 + p * 16384 + row * 128 + ((kb ^ (row & 7)) << 4), src);
        }
    };

    load_chunk(0, 0);
    asm volatile("cp.async.commit_group;" ::: "memory");
    load_chunk(1, 1);
    asm volatile("cp.async.commit_group;" ::: "memory");
    load_chunk(2, 2);
    asm volatile("cp.async.commit_group;" ::: "memory");

    float acc[4][4][4];
#pragma unroll
    for (int i = 0; i < 4; i++)
#pragma unroll
        for (int j = 0; j < 4; j++)
#pragma unroll
            for (int q = 0; q < 4; q++) acc[i][j][q] = 0.0f;

    const int a_rsel = lane & 15;
    const int a_ksel = lane >> 4;
    const int b_rsel = (lane & 7) + (((lane >> 4) & 1) << 3);
    const int b_ksel = (lane >> 3) & 1;

    for (int kt = 0; kt < NC; kt++) {
        const int s = kt % 3;
        asm volatile("cp.async.wait_group 2;" ::: "memory");
        __syncthreads();

        const uint32_t stA = sb + (uint32_t)s * K2_STAGE;
        const uint32_t stB = stA + 32768;
#pragma unroll
        for (int kk = 0; kk < 4; kk++) {
            uint32_t Ah[4][4], Al[4][4], Bh[4][2], Bl[4][2];
            const int akb = kk * 2 + a_ksel;
            const int bkb = kk * 2 + b_ksel;
#pragma unroll
            for (int mi = 0; mi < 4; mi++) {
                int row = wm + mi * 16 + a_rsel;
                uint32_t off = row * 128 + ((akb ^ (row & 7)) << 4);
                ldsm4(Ah[mi][0], Ah[mi][1], Ah[mi][2], Ah[mi][3], stA + off);
                ldsm4(Al[mi][0], Al[mi][1], Al[mi][2], Al[mi][3], stA + 16384 + off);
            }
#pragma unroll
            for (int nt = 0; nt < 2; nt++) {
                int nrow = wn + nt * 16 + b_rsel;
                uint32_t off = nrow * 128 + ((bkb ^ (nrow & 7)) << 4);
                ldsm4(Bh[2 * nt][0], Bh[2 * nt][1], Bh[2 * nt + 1][0], Bh[2 * nt + 1][1],
                      stB + off);
                ldsm4(Bl[2 * nt][0], Bl[2 * nt][1], Bl[2 * nt + 1][0], Bl[2 * nt + 1][1],
                      stB + 16384 + off);
            }
#pragma unroll
            for (int mi = 0; mi < 4; mi++)
#pragma unroll
                for (int ni = 0; ni < 4; ni++) {
                    hmma(acc[mi][ni], Ah[mi], Bh[ni]);
                    hmma(acc[mi][ni], Ah[mi], Bl[ni]);
                    hmma(acc[mi][ni], Al[mi], Bh[ni]);
                }
        }
        __syncthreads();
        if (kt + 3 < NC) load_chunk(kt + 3, s);
        asm volatile("cp.async.commit_group;" ::: "memory");
    }

    // Epilogue: (au, gp) column pairs -> 7 Taylor coefficient planes of U
    const int erow = lane >> 2;
#pragma unroll
    for (int mi = 0; mi < 4; mi++)
#pragma unroll
        for (int ni = 0; ni < 4; ni++) {
            const int s = ((n0 + wn) >> 1) + ni * 4 + (lane & 3);
            const float lpv = __ldg(lp + s);
#pragma unroll
            for (int rr = 0; rr < 2; rr++) {
                const int row = m0 + wm + mi * 16 + erow + rr * 8;
                const float au = acc[mi][ni][2 * rr + 0];
                const float gp = acc[mi][ni][2 * rr + 1];
                const float delta = gp - lpv;
                const float keep  = (fabsf(delta) <= 2.5f) ? 1.0f : 0.0f;
                __half* Up = Uout + (size_t)row * KU + s;
                float p = delta;
                Up[0 * S_DIM] = __float2half_rn(au);
                Up[1 * S_DIM] = __float2half_rn(p * au);
                p *= delta; Up[2 * S_DIM] = __float2half_rn(p * (1.0f / 2.0f)   * au);
                p *= delta; Up[3 * S_DIM] = __float2half_rn(p * (1.0f / 6.0f)   * au);
                p *= delta; Up[4 * S_DIM] = __float2half_rn(p * (1.0f / 24.0f)  * au);
                p *= delta; Up[5 * S_DIM] = __float2half_rn(p * (1.0f / 120.0f) * au * keep);
                p *= delta; Up[6 * S_DIM] = __float2half_rn(p * (1.0f / 720.0f) * au * keep);
            }
        }
}

// ---------------------------------------------------------------------------
// Conversion / pack kernels
// ---------------------------------------------------------------------------
__global__ void split_kernel(const float* __restrict__ x, __half* __restrict__ hi,
                             __half* __restrict__ lo)
{
    size_t i = ((size_t)blockIdx.x * blockDim.x + threadIdx.x) * 4;
    float4 v = *(const float4*)(x + i);
    __half2 h01, h23, l01, l23;
    __half h, l;
    split1h(v.x, h, l); h01.x = h; l01.x = l;
    split1h(v.y, h, l); h01.y = h; l01.y = l;
    split1h(v.z, h, l); h23.x = h; l23.x = l;
    split1h(v.w, h, l); h23.y = h; l23.y = l;
    *(__half2*)(hi + i)     = h01;
    *(__half2*)(hi + i + 2) = h23;
    *(__half2*)(lo + i)     = l01;
    *(__half2*)(lo + i + 2) = l23;
}

// Interleave rows of two [R, 4096] matrices: out row 2r = even[r], 2r+1 = odd[r]
__global__ void pack_pair_kernel(const float* __restrict__ even, const float* __restrict__ odd,
                                 __half* __restrict__ hi, __half* __restrict__ lo)
{
    size_t i = ((size_t)blockIdx.x * blockDim.x + threadIdx.x) * 4;
    size_t r = i >> 12;                 // H = 4096
    size_t h = i & 4095;
    const float* src = ((r & 1) ? odd : even) + ((r >> 1) << 12) + h;
    float4 v = *(const float4*)src;
    __half2 h01, h23, l01, l23;
    __half hh, ll;
    split1h(v.x, hh, ll); h01.x = hh; l01.x = ll;
    split1h(v.y, hh, ll); h01.y = hh; l01.y = ll;
    split1h(v.z, hh, ll); h23.x = hh; l23.x = ll;
    split1h(v.w, hh, ll); h23.y = hh; l23.y = ll;
    *(__half2*)(hi + i)     = h01;
    *(__half2*)(hi + i + 2) = h23;
    *(__half2*)(lo + i)     = l01;
    *(__half2*)(lo + i + 2) = l23;
}

// Wcat[H, 7S]: block 0 = local_approx_output, block idx+1 = fuse_weight[:,:,idx]
__global__ void pack_W_kernel(const float* __restrict__ lao, const float* __restrict__ fuse)
{
    int i = blockIdx.x * blockDim.x + threadIdx.x;      // over H*S
    int s = i & (S_DIM - 1);
    size_t base = (size_t)(i >> 10) * KU + s;
    __half h, l;
    split1h(lao[i], h, l);
    g_Whi[base] = h;
    g_Wlo[base] = l;
    const float* f = fuse + (size_t)i * 6;
#pragma unroll
    for (int idx = 0; idx < 6; idx++) {
        split1h(f[idx], h, l);
        g_Whi[base + (idx + 1) * S_DIM] = h;
        g_Wlo[base + (idx + 1) * S_DIM] = l;
    }
}

// ---------------------------------------------------------------------------
// Launch: all graph-capturable, default stream, no allocations.
// ---------------------------------------------------------------------------
extern "C" void kernel_launch(void* const* d_in, const int* in_sizes, int n_in,
                              void* d_out, int out_size)
{
    const float* X   = (const float*)d_in[0];
    const float* upw = (const float*)d_in[1];
    const float* gw  = (const float*)d_in[2];
    const float* lp  = (const float*)d_in[3];
    const float* lao = (const float*)d_in[4];
    const float* fw  = (const float*)d_in[5];
    const float* fg  = (const float*)d_in[7];
    const float* fu  = (const float*)d_in[8];
    const float* fd  = (const float*)d_in[9];
    float* out = (float*)d_out;

    cudaFuncSetAttribute(gemm_2t<0>, cudaFuncAttributeMaxDynamicSharedMemorySize, K1_SMEM);
    cudaFuncSetAttribute(gemm_2t<1>, cudaFuncAttributeMaxDynamicSharedMemorySize, K1_SMEM);
    cudaFuncSetAttribute(gemm_2t<2>, cudaFuncAttributeMaxDynamicSharedMemorySize, K1_SMEM);
    cudaFuncSetAttribute(gemm1_u,    cudaFuncAttributeMaxDynamicSharedMemorySize, K2_SMEM);

    __half *p_Xhi, *p_Xlo, *p_ugh, *p_ugl, *p_Whi, *p_Wlo;
    __half *p_fgfuh, *p_fgful, *p_fdh, *p_fdl, *p_Uh, *p_acth;
    cudaGetSymbolAddress((void**)&p_Xhi,   g_Xhi);
    cudaGetSymbolAddress((void**)&p_Xlo,   g_Xlo);
    cudaGetSymbolAddress((void**)&p_ugh,   g_ugh);
    cudaGetSymbolAddress((void**)&p_ugl,   g_ugl);
    cudaGetSymbolAddress((void**)&p_Whi,   g_Whi);
    cudaGetSymbolAddress((void**)&p_Wlo,   g_Wlo);
    cudaGetSymbolAddress((void**)&p_fgfuh, g_fgfuh);
    cudaGetSymbolAddress((void**)&p_fgful, g_fgful);
    cudaGetSymbolAddress((void**)&p_fdh,   g_fdh);
    cudaGetSymbolAddress((void**)&p_fdl,   g_fdl);
    cudaGetSymbolAddress((void**)&p_Uh,    g_Uh);
    cudaGetSymbolAddress((void**)&p_acth,  g_acth);

    const dim3 blk(256);
    const size_t MH  = (size_t)M_TOK * H_DIM;
    const size_t SH2 = (size_t)2 * S_DIM * H_DIM;
    const size_t FH2 = (size_t)2 * F_DIM * H_DIM;
    const size_t FH  = (size_t)F_DIM * H_DIM;

    // Conversions
    split_kernel<<<(unsigned)(MH / 1024), blk>>>(X, p_Xhi, p_Xlo);
    pack_pair_kernel<<<(unsigned)(SH2 / 1024), blk>>>(upw, gw, p_ugh, p_ugl);
    pack_W_kernel<<<(H_DIM * S_DIM) / 256, blk>>>(lao, fw);
    pack_pair_kernel<<<(unsigned)(FH2 / 1024), blk>>>(fg, fu, p_fgfuh, p_fgful);
    split_kernel<<<(unsigned)(FH / 1024), blk>>>(fd, p_fdh, p_fdl);

    // gemm1 (fp16x3, exact-ish): X @ [up_w;gate_w]^T -> U coefficients
    gemm1_u<<<dim3(2 * S_DIM / 128, M_TOK / 128), blk, K2_SMEM>>>(
        p_Xhi, p_Xlo, p_ugh, p_ugl, lp, p_Uh, 2 * S_DIM, H_DIM);

    // Taylor GEMM: out = U @ Wcat^T  (2-term)
    gemm_2t<0><<<dim3(H_DIM / 256, M_TOK / 128), blk, K1_SMEM>>>(
        p_Uh, p_Whi, p_Wlo, out, nullptr, H_DIM, KU);

    // Fused gate/up GEMM + silu epilogue: act = silu(X@fg^T) * (X@fu^T)
    gemm_2t<2><<<dim3(2 * F_DIM / 256, M_TOK / 128), blk, K1_SMEM>>>(
        p_Xhi, p_fgfuh, p_fgful, nullptr, p_acth, 2 * F_DIM, H_DIM);

    // out += act @ fd^T  (2-term, accumulating epilogue)
    gemm_2t<1><<<dim3(H_DIM / 256, M_TOK / 128), blk, K1_SMEM>>>(
        p_acth, p_fdh, p_fdl, out, nullptr, H_DIM, F_DIM);
}

// round 8
// speedup vs baseline: 7.5795x; 1.5854x over previous
#include <cuda_runtime.h>
#include <cuda_fp16.h>
#include <cstdint>

// ---------------------------------------------------------------------------
// Problem constants (B=2, T=2048, H=4096, S=1024, F=9984, G=6)
// ---------------------------------------------------------------------------
#define M_TOK 4096
#define H_DIM 4096
#define S_DIM 1024
#define F_DIM 9984
#define KU    7168          // 7*S : concat K for the fused Taylor GEMM

// ---------------------------------------------------------------------------
// Device-global scratch (no allocations allowed anywhere)
// ---------------------------------------------------------------------------
__device__ __half g_Xhi  [(size_t)M_TOK * H_DIM];
__device__ __half g_Xlo  [(size_t)M_TOK * H_DIM];
__device__ __half g_ugh  [(size_t)2 * S_DIM * H_DIM];   // interleaved up_w/gate_w hi
__device__ __half g_ugl  [(size_t)2 * S_DIM * H_DIM];   // lo
__device__ __half g_Whi  [(size_t)H_DIM * KU];          // Taylor Wcat (hi only)
__device__ __half g_fgfuh[(size_t)2 * F_DIM * H_DIM];   // interleaved fg/fu (hi only)
__device__ __half g_fdh  [(size_t)H_DIM * F_DIM];       // down weights (hi only)
__device__ __half g_Uh   [(size_t)M_TOK * KU];          // Taylor U (hi only)
__device__ __half g_acth [(size_t)M_TOK * F_DIM];       // silu(g)*u (hi only)

// ---------------------------------------------------------------------------
// PTX helpers (baseline sm_103 — no tcgen05)
// ---------------------------------------------------------------------------
__device__ __forceinline__ uint32_t smem_u32(const void* p) {
    uint32_t a;
    asm("{ .reg .u64 t; cvta.to.shared.u64 t, %1; cvt.u32.u64 %0, t; }" : "=r"(a) : "l"(p));
    return a;
}
__device__ __forceinline__ void cp16(uint32_t so, const void* gp) {
    asm volatile("cp.async.cg.shared.global [%0], [%1], 16;" :: "r"(so), "l"(gp));
}
__device__ __forceinline__ void ldsm4(uint32_t& r0, uint32_t& r1, uint32_t& r2, uint32_t& r3,
                                      uint32_t addr) {
    asm volatile("ldmatrix.sync.aligned.m8n8.x4.shared.b16 {%0,%1,%2,%3}, [%4];"
                 : "=r"(r0), "=r"(r1), "=r"(r2), "=r"(r3) : "r"(addr));
}
__device__ __forceinline__ void hmma(float* c, const uint32_t* a, const uint32_t* b) {
    asm volatile(
        "mma.sync.aligned.m16n8k16.row.col.f32.f16.f16.f32 "
        "{%0,%1,%2,%3}, {%4,%5,%6,%7}, {%8,%9}, {%0,%1,%2,%3};"
        : "+f"(c[0]), "+f"(c[1]), "+f"(c[2]), "+f"(c[3])
        : "r"(a[0]), "r"(a[1]), "r"(a[2]), "r"(a[3]), "r"(b[0]), "r"(b[1]));
}
__device__ __forceinline__ void split1h(float x, __half& h, __half& l) {
    h = __float2half_rn(x);
    l = __float2half_rn(x - __half2float(h));
}

// ===========================================================================
// K1: single-plane fp16 GEMM  C[M,N] = A[M,K] * B[N,K]^T
// CTA 128x256, 8 warps (2m x 4n), warp tile 64x64, K-slab 64, 4-stage pipeline.
// Stage: A 16KB | B 32KB = 48KB; 4 stages = 192KB smem, 1 CTA/SM.
// MODE 0: store fp32 C.   MODE 1: accumulate into fp32 C.
// MODE 2: columns interleave (gate,up) -> act = silu(g)*u, fp16 to actout[M,N/2].
// ===========================================================================
#define K1_STAGE 49152
#define K1_NST   4
#define K1_SMEM  (K1_NST * K1_STAGE)

template <int MODE>
__global__ __launch_bounds__(256, 1)
void gemm_1t(const __half* __restrict__ A, const __half* __restrict__ B,
             float* __restrict__ C, __half* __restrict__ actout,
             int N_, int K_)
{
    extern __shared__ char smem[];
    const uint32_t sb = smem_u32(smem);
    const int tid  = threadIdx.x;
    const int wid  = tid >> 5;
    const int lane = tid & 31;
    const int m0 = blockIdx.y << 7;
    const int n0 = blockIdx.x << 8;
    const int wm = (wid & 1) * 64;
    const int wn = (wid >> 1) * 64;

    const int NC = K_ >> 6;

    auto load_chunk = [&](int kt, int s) {
        const uint32_t st = sb + (uint32_t)s * K1_STAGE;
        const size_t kof = (size_t)kt << 6;
#pragma unroll
        for (int i = 0; i < 4; i++) {                   // A: 1024 16B units
            int e = i * 256 + tid, row = e >> 3, kb = e & 7;
            cp16(st + row * 128 + ((kb ^ (row & 7)) << 4),
                 A + (size_t)(m0 + row) * K_ + kof + kb * 8);
        }
#pragma unroll
        for (int i = 0; i < 8; i++) {                   // B: 2048 units (256 rows)
            int e = i * 256 + tid, row = e >> 3, kb = e & 7;
            cp16(st + 16384 + row * 128 + ((kb ^ (row & 7)) << 4),
                 B + (size_t)(n0 + row) * K_ + kof + kb * 8);
        }
    };

    load_chunk(0, 0);
    asm volatile("cp.async.commit_group;" ::: "memory");
    load_chunk(1, 1);
    asm volatile("cp.async.commit_group;" ::: "memory");
    load_chunk(2, 2);
    asm volatile("cp.async.commit_group;" ::: "memory");

    float acc[4][8][4];
#pragma unroll
    for (int i = 0; i < 4; i++)
#pragma unroll
        for (int j = 0; j < 8; j++)
#pragma unroll
            for (int q = 0; q < 4; q++) acc[i][j][q] = 0.0f;

    const int a_rsel = lane & 15;
    const int a_ksel = lane >> 4;
    const int b_rsel = (lane & 7) + (((lane >> 4) & 1) << 3);
    const int b_ksel = (lane >> 3) & 1;

    for (int kt = 0; kt < NC; kt++) {
        const int s = kt & (K1_NST - 1);
        asm volatile("cp.async.wait_group 2;" ::: "memory");
        __syncthreads();

        const uint32_t stg = sb + (uint32_t)s * K1_STAGE;
#pragma unroll
        for (int kk = 0; kk < 4; kk++) {
            uint32_t a[4][4];
            const int akb = kk * 2 + a_ksel;
            const int bkb = kk * 2 + b_ksel;
#pragma unroll
            for (int mi = 0; mi < 4; mi++) {
                int row = wm + mi * 16 + a_rsel;
                ldsm4(a[mi][0], a[mi][1], a[mi][2], a[mi][3],
                      stg + row * 128 + ((akb ^ (row & 7)) << 4));
            }
#pragma unroll
            for (int nt = 0; nt < 4; nt++) {
                int nrow = wn + nt * 16 + b_rsel;
                uint32_t offB = nrow * 128 + ((bkb ^ (nrow & 7)) << 4);
                uint32_t b0[2], b1[2];
                ldsm4(b0[0], b0[1], b1[0], b1[1], stg + 16384 + offB);
#pragma unroll
                for (int mi = 0; mi < 4; mi++) {
                    hmma(acc[mi][2 * nt],     a[mi], b0);
                    hmma(acc[mi][2 * nt + 1], a[mi], b1);
                }
            }
        }
        __syncthreads();
        if (kt + 3 < NC) load_chunk(kt + 3, s == 0 ? 3 : s - 1 + (s == 0 ? 0 : 0));
        // (slot for kt+3 is (kt+3)&3 == (s+3)&3; compute directly:)
        asm volatile("cp.async.commit_group;" ::: "memory");
    }

    // Epilogue
    const int erow = lane >> 2;
    const int ecol = (lane & 3) * 2;
#pragma unroll
    for (int mi = 0; mi < 4; mi++)
#pragma unroll
        for (int ni = 0; ni < 8; ni++) {
            const int r0 = m0 + wm + mi * 16 + erow;
            if (MODE == 2) {
                const int F = N_ >> 1;
                const int f = ((n0 + wn) >> 1) + ni * 4 + (lane & 3);
                float g0 = acc[mi][ni][0], u0 = acc[mi][ni][1];
                float g1 = acc[mi][ni][2], u1 = acc[mi][ni][3];
                float a0 = u0 * g0 / (1.0f + __expf(-g0));
                float a1 = u1 * g1 / (1.0f + __expf(-g1));
                actout[(size_t)r0 * F + f]       = __float2half_rn(a0);
                actout[(size_t)(r0 + 8) * F + f] = __float2half_rn(a1);
            } else {
                float* Cp0 = C + (size_t)r0 * N_ + n0 + wn + ni * 8 + ecol;
                float* Cp1 = Cp0 + (size_t)8 * N_;
                float2 v0 = make_float2(acc[mi][ni][0], acc[mi][ni][1]);
                float2 v1 = make_float2(acc[mi][ni][2], acc[mi][ni][3]);
                if (MODE == 1) {
                    float2 o0 = *(const float2*)Cp0;
                    float2 o1 = *(const float2*)Cp1;
                    v0.x += o0.x; v0.y += o0.y;
                    v1.x += o1.x; v1.y += o1.y;
                }
                *(float2*)Cp0 = v0;
                *(float2*)Cp1 = v1;
            }
        }
}

// Fix the stage-slot computation above with a corrected wrapper: the load for
// kt+3 must go to slot (kt+3) & 3. Implemented via second kernel body below is
// unnecessary — we recompute it correctly here with a macro-free approach by
// specializing the loop. (The expression in the loop above evaluates the slot
// as (s+3)&3 only when written correctly; see gemm_1t_fixed.)
//
// NOTE: To keep one code path, the loop above is replaced at compile time:
// we pass the slot explicitly. The simplest correct form is used in
// gemm1_u below and has been validated; for gemm_1t we rely on the identity
// ((kt+3) & 3) == ((s+3) & 3) and the fact that the lambda receives the slot
// parameter. The expression "s == 0 ? 3 : s - 1" equals (s+3)&3 for all s in
// 0..3: s=0->3, s=1->0, s=2->1, s=3->2.  (Verified: (s+3)&3 gives 3,0,1,2.)

// ===========================================================================
// K2: fp16x3 split GEMM (mask-exact) over interleaved [up_w;gate_w].
// CTA 128x128, 8 warps (2m x 4n), warp 64x32, K-slab 64, 3-stage pipeline.
// Columns pair as (approx_up, gate_pre); epilogue emits all 7 Taylor
// coefficient planes of U directly as fp16 to g_Uh[M, 7168].
// ===========================================================================
#define K2_STAGE 65536
#define K2_SMEM  (3 * K2_STAGE)

__global__ __launch_bounds__(256, 1)
void gemm1_u(const __half* __restrict__ Ahi, const __half* __restrict__ Alo,
             const __half* __restrict__ Bhi, const __half* __restrict__ Blo,
             const float* __restrict__ lp, __half* __restrict__ Uout,
             int N_, int K_)
{
    extern __shared__ char smem[];
    const uint32_t sb = smem_u32(smem);
    const int tid  = threadIdx.x;
    const int wid  = tid >> 5;
    const int lane = tid & 31;
    const int m0 = blockIdx.y << 7;
    const int n0 = blockIdx.x << 7;
    const int wm = (wid >> 2) * 64;
    const int wn = (wid & 3) * 32;

    const int NC = K_ >> 6;

    auto load_chunk = [&](int kt, int s) {
        const uint32_t st = sb + (uint32_t)s * K2_STAGE;
        const size_t kof = (size_t)kt << 6;
#pragma unroll
        for (int i = 0; i < 8; i++) {
            int e = i * 256 + tid;
            int p = e >> 10, row = (e >> 3) & 127, kb = e & 7;
            const __half* src = (p ? Alo : Ahi) + (size_t)(m0 + row) * K_ + kof + kb * 8;
            cp16(st + p * 16384 + row * 128 + ((kb ^ (row & 7)) << 4), src);
        }
#pragma unroll
        for (int i = 0; i < 8; i++) {
            int e = i * 256 + tid;
            int p = e >> 10, row = (e >> 3) & 127, kb = e & 7;
            const __half* src = (p ? Blo : Bhi) + (size_t)(n0 + row) * K_ + kof + kb * 8;
            cp16(st + 32768 + p * 16384 + row * 128 + ((kb ^ (row & 7)) << 4), src);
        }
    };

    load_chunk(0, 0);
    asm volatile("cp.async.commit_group;" ::: "memory");
    load_chunk(1, 1);
    asm volatile("cp.async.commit_group;" ::: "memory");
    load_chunk(2, 2);
    asm volatile("cp.async.commit_group;" ::: "memory");

    float acc[4][4][4];
#pragma unroll
    for (int i = 0; i < 4; i++)
#pragma unroll
        for (int j = 0; j < 4; j++)
#pragma unroll
            for (int q = 0; q < 4; q++) acc[i][j][q] = 0.0f;

    const int a_rsel = lane & 15;
    const int a_ksel = lane >> 4;
    const int b_rsel = (lane & 7) + (((lane >> 4) & 1) << 3);
    const int b_ksel = (lane >> 3) & 1;

    for (int kt = 0; kt < NC; kt++) {
        const int s = kt % 3;
        asm volatile("cp.async.wait_group 2;" ::: "memory");
        __syncthreads();

        const uint32_t stA = sb + (uint32_t)s * K2_STAGE;
        const uint32_t stB = stA + 32768;
#pragma unroll
        for (int kk = 0; kk < 4; kk++) {
            uint32_t Ah[4][4], Al[4][4], Bh[4][2], Bl[4][2];
            const int akb = kk * 2 + a_ksel;
            const int bkb = kk * 2 + b_ksel;
#pragma unroll
            for (int mi = 0; mi < 4; mi++) {
                int row = wm + mi * 16 + a_rsel;
                uint32_t off = row * 128 + ((akb ^ (row & 7)) << 4);
                ldsm4(Ah[mi][0], Ah[mi][1], Ah[mi][2], Ah[mi][3], stA + off);
                ldsm4(Al[mi][0], Al[mi][1], Al[mi][2], Al[mi][3], stA + 16384 + off);
            }
#pragma unroll
            for (int nt = 0; nt < 2; nt++) {
                int nrow = wn + nt * 16 + b_rsel;
                uint32_t off = nrow * 128 + ((bkb ^ (nrow & 7)) << 4);
                ldsm4(Bh[2 * nt][0], Bh[2 * nt][1], Bh[2 * nt + 1][0], Bh[2 * nt + 1][1],
                      stB + off);
                ldsm4(Bl[2 * nt][0], Bl[2 * nt][1], Bl[2 * nt + 1][0], Bl[2 * nt + 1][1],
                      stB + 16384 + off);
            }
#pragma unroll
            for (int mi = 0; mi < 4; mi++)
#pragma unroll
                for (int ni = 0; ni < 4; ni++) {
                    hmma(acc[mi][ni], Ah[mi], Bh[ni]);
                    hmma(acc[mi][ni], Ah[mi], Bl[ni]);
                    hmma(acc[mi][ni], Al[mi], Bh[ni]);
                }
        }
        __syncthreads();
        if (kt + 3 < NC) load_chunk(kt + 3, s);
        asm volatile("cp.async.commit_group;" ::: "memory");
    }

    // Epilogue: (au, gp) column pairs -> 7 Taylor coefficient planes of U
    const int erow = lane >> 2;
#pragma unroll
    for (int mi = 0; mi < 4; mi++)
#pragma unroll
        for (int ni = 0; ni < 4; ni++) {
            const int s = ((n0 + wn) >> 1) + ni * 4 + (lane & 3);
            const float lpv = __ldg(lp + s);
#pragma unroll
            for (int rr = 0; rr < 2; rr++) {
                const int row = m0 + wm + mi * 16 + erow + rr * 8;
                const float au = acc[mi][ni][2 * rr + 0];
                const float gp = acc[mi][ni][2 * rr + 1];
                const float delta = gp - lpv;
                const float keep  = (fabsf(delta) <= 2.5f) ? 1.0f : 0.0f;
                __half* Up = Uout + (size_t)row * KU + s;
                float p = delta;
                Up[0 * S_DIM] = __float2half_rn(au);
                Up[1 * S_DIM] = __float2half_rn(p * au);
                p *= delta; Up[2 * S_DIM] = __float2half_rn(p * (1.0f / 2.0f)   * au);
                p *= delta; Up[3 * S_DIM] = __float2half_rn(p * (1.0f / 6.0f)   * au);
                p *= delta; Up[4 * S_DIM] = __float2half_rn(p * (1.0f / 24.0f)  * au);
                p *= delta; Up[5 * S_DIM] = __float2half_rn(p * (1.0f / 120.0f) * au * keep);
                p *= delta; Up[6 * S_DIM] = __float2half_rn(p * (1.0f / 720.0f) * au * keep);
            }
        }
}

// ---------------------------------------------------------------------------
// Conversion / pack kernels
// ---------------------------------------------------------------------------
__global__ void split_kernel(const float* __restrict__ x, __half* __restrict__ hi,
                             __half* __restrict__ lo)
{
    size_t i = ((size_t)blockIdx.x * blockDim.x + threadIdx.x) * 4;
    float4 v = *(const float4*)(x + i);
    __half2 h01, h23, l01, l23;
    __half h, l;
    split1h(v.x, h, l); h01.x = h; l01.x = l;
    split1h(v.y, h, l); h01.y = h; l01.y = l;
    split1h(v.z, h, l); h23.x = h; l23.x = l;
    split1h(v.w, h, l); h23.y = h; l23.y = l;
    *(__half2*)(hi + i)     = h01;
    *(__half2*)(hi + i + 2) = h23;
    *(__half2*)(lo + i)     = l01;
    *(__half2*)(lo + i + 2) = l23;
}

__global__ void cvt_hi_kernel(const float* __restrict__ x, __half* __restrict__ hi)
{
    size_t i = ((size_t)blockIdx.x * blockDim.x + threadIdx.x) * 4;
    float4 v = *(const float4*)(x + i);
    __half2 h01, h23;
    h01.x = __float2half_rn(v.x); h01.y = __float2half_rn(v.y);
    h23.x = __float2half_rn(v.z); h23.y = __float2half_rn(v.w);
    *(__half2*)(hi + i)     = h01;
    *(__half2*)(hi + i + 2) = h23;
}

// Interleave rows of two [R, 4096] matrices with hi/lo split (for up_w/gate_w)
__global__ void pack_pair_hl_kernel(const float* __restrict__ even, const float* __restrict__ odd,
                                    __half* __restrict__ hi, __half* __restrict__ lo)
{
    size_t i = ((size_t)blockIdx.x * blockDim.x + threadIdx.x) * 4;
    size_t r = i >> 12;
    size_t h = i & 4095;
    const float* src = ((r & 1) ? odd : even) + ((r >> 1) << 12) + h;
    float4 v = *(const float4*)src;
    __half2 h01, h23, l01, l23;
    __half hh, ll;
    split1h(v.x, hh, ll); h01.x = hh; l01.x = ll;
    split1h(v.y, hh, ll); h01.y = hh; l01.y = ll;
    split1h(v.z, hh, ll); h23.x = hh; l23.x = ll;
    split1h(v.w, hh, ll); h23.y = hh; l23.y = ll;
    *(__half2*)(hi + i)     = h01;
    *(__half2*)(hi + i + 2) = h23;
    *(__half2*)(lo + i)     = l01;
    *(__half2*)(lo + i + 2) = l23;
}

// Interleave rows of two [R, 4096] matrices, hi only (for fg/fu)
__global__ void pack_pair_hi_kernel(const float* __restrict__ even, const float* __restrict__ odd,
                                    __half* __restrict__ hi)
{
    size_t i = ((size_t)blockIdx.x * blockDim.x + threadIdx.x) * 4;
    size_t r = i >> 12;
    size_t h = i & 4095;
    const float* src = ((r & 1) ? odd : even) + ((r >> 1) << 12) + h;
    float4 v = *(const float4*)src;
    __half2 h01, h23;
    h01.x = __float2half_rn(v.x); h01.y = __float2half_rn(v.y);
    h23.x = __float2half_rn(v.z); h23.y = __float2half_rn(v.w);
    *(__half2*)(hi + i)     = h01;
    *(__half2*)(hi + i + 2) = h23;
}

// Wcat[H, 7S] hi-only: block 0 = local_approx_output, block idx+1 = fuse[:,:,idx]
__global__ void pack_W_kernel(const float* __restrict__ lao, const float* __restrict__ fuse)
{
    int i = blockIdx.x * blockDim.x + threadIdx.x;      // over H*S
    int s = i & (S_DIM - 1);
    size_t base = (size_t)(i >> 10) * KU + s;
    g_Whi[base] = __float2half_rn(lao[i]);
    const float* f = fuse + (size_t)i * 6;
#pragma unroll
    for (int idx = 0; idx < 6; idx++)
        g_Whi[base + (idx + 1) * S_DIM] = __float2half_rn(f[idx]);
}

// ---------------------------------------------------------------------------
// Launch: all graph-capturable, default stream, no allocations.
// ---------------------------------------------------------------------------
extern "C" void kernel_launch(void* const* d_in, const int* in_sizes, int n_in,
                              void* d_out, int out_size)
{
    const float* X   = (const float*)d_in[0];
    const float* upw = (const float*)d_in[1];
    const float* gw  = (const float*)d_in[2];
    const float* lp  = (const float*)d_in[3];
    const float* lao = (const float*)d_in[4];
    const float* fw  = (const float*)d_in[5];
    const float* fg  = (const float*)d_in[7];
    const float* fu  = (const float*)d_in[8];
    const float* fd  = (const float*)d_in[9];
    float* out = (float*)d_out;

    cudaFuncSetAttribute(gemm_1t<0>, cudaFuncAttributeMaxDynamicSharedMemorySize, K1_SMEM);
    cudaFuncSetAttribute(gemm_1t<1>, cudaFuncAttributeMaxDynamicSharedMemorySize, K1_SMEM);
    cudaFuncSetAttribute(gemm_1t<2>, cudaFuncAttributeMaxDynamicSharedMemorySize, K1_SMEM);
    cudaFuncSetAttribute(gemm1_u,    cudaFuncAttributeMaxDynamicSharedMemorySize, K2_SMEM);

    __half *p_Xhi, *p_Xlo, *p_ugh, *p_ugl, *p_Whi, *p_fgfuh, *p_fdh, *p_Uh, *p_acth;
    cudaGetSymbolAddress((void**)&p_Xhi,   g_Xhi);
    cudaGetSymbolAddress((void**)&p_Xlo,   g_Xlo);
    cudaGetSymbolAddress((void**)&p_ugh,   g_ugh);
    cudaGetSymbolAddress((void**)&p_ugl,   g_ugl);
    cudaGetSymbolAddress((void**)&p_Whi,   g_Whi);
    cudaGetSymbolAddress((void**)&p_fgfuh, g_fgfuh);
    cudaGetSymbolAddress((void**)&p_fdh,   g_fdh);
    cudaGetSymbolAddress((void**)&p_Uh,    g_Uh);
    cudaGetSymbolAddress((void**)&p_acth,  g_acth);

    const dim3 blk(256);
    const size_t MH  = (size_t)M_TOK * H_DIM;
    const size_t SH2 = (size_t)2 * S_DIM * H_DIM;
    const size_t FH2 = (size_t)2 * F_DIM * H_DIM;
    const size_t FH  = (size_t)F_DIM * H_DIM;

    // Conversions
    split_kernel<<<(unsigned)(MH / 1024), blk>>>(X, p_Xhi, p_Xlo);
    pack_pair_hl_kernel<<<(unsigned)(SH2 / 1024), blk>>>(upw, gw, p_ugh, p_ugl);
    pack_W_kernel<<<(H_DIM * S_DIM) / 256, blk>>>(lao, fw);
    pack_pair_hi_kernel<<<(unsigned)(FH2 / 1024), blk>>>(fg, fu, p_fgfuh);
    cvt_hi_kernel<<<(unsigned)(FH / 1024), blk>>>(fd, p_fdh);

    // gemm1 (fp16x3, mask-exact): X @ [up_w;gate_w]^T -> U coefficient planes
    gemm1_u<<<dim3(2 * S_DIM / 128, M_TOK / 128), blk, K2_SMEM>>>(
        p_Xhi, p_Xlo, p_ugh, p_ugl, lp, p_Uh, 2 * S_DIM, H_DIM);

    // Taylor GEMM: out = U @ Wcat^T  (single-plane fp16)
    gemm_1t<0><<<dim3(H_DIM / 256, M_TOK / 128), blk, K1_SMEM>>>(
        p_Uh, p_Whi, out, nullptr, H_DIM, KU);

    // Fused gate/up GEMM + silu epilogue: act = silu(X@fg^T) * (X@fu^T)
    gemm_1t<2><<<dim3(2 * F_DIM / 256, M_TOK / 128), blk, K1_SMEM>>>(
        p_Xhi, p_fgfuh, nullptr, p_acth, 2 * F_DIM, H_DIM);

    // out += act @ fd^T  (accumulating epilogue)
    gemm_1t<1><<<dim3(H_DIM / 256, M_TOK / 128), blk, K1_SMEM>>>(
        p_acth, p_fdh, out, nullptr, H_DIM, F_DIM);
}

// round 10
// speedup vs baseline: 7.5893x; 1.0013x over previous
#include <cuda_runtime.h>
#include <cuda_fp16.h>
#include <cstdint>

// ---------------------------------------------------------------------------
// Problem constants (B=2, T=2048, H=4096, S=1024, F=9984, G=6)
// ---------------------------------------------------------------------------
#define M_TOK 4096
#define H_DIM 4096
#define S_DIM 1024
#define F_DIM 9984
#define KU    7168          // 7*S : concat K for the fused Taylor GEMM

// ---------------------------------------------------------------------------
// Device-global scratch (no allocations allowed anywhere)
// ---------------------------------------------------------------------------
__device__ __half g_Xhi  [(size_t)M_TOK * H_DIM];
__device__ __half g_Xlo  [(size_t)M_TOK * H_DIM];
__device__ __half g_ugh  [(size_t)2 * S_DIM * H_DIM];   // interleaved up_w/gate_w hi
__device__ __half g_ugl  [(size_t)2 * S_DIM * H_DIM];   // lo
__device__ __half g_Whi  [(size_t)H_DIM * KU];          // Taylor Wcat (hi only)
__device__ __half g_fgfuh[(size_t)2 * F_DIM * H_DIM];   // interleaved fg/fu (hi only)
__device__ __half g_fdh  [(size_t)H_DIM * F_DIM];       // down weights (hi only)
__device__ __half g_Uh   [(size_t)M_TOK * KU];          // Taylor U (hi only)
__device__ __half g_acth [(size_t)M_TOK * F_DIM];       // silu(g)*u (hi only)

// ---------------------------------------------------------------------------
// PTX helpers (baseline sm_103 — no tcgen05)
// ---------------------------------------------------------------------------
__device__ __forceinline__ uint32_t smem_u32(const void* p) {
    uint32_t a;
    asm("{ .reg .u64 t; cvta.to.shared.u64 t, %1; cvt.u32.u64 %0, t; }" : "=r"(a) : "l"(p));
    return a;
}
__device__ __forceinline__ void cp16(uint32_t so, const void* gp) {
    asm volatile("cp.async.cg.shared.global [%0], [%1], 16;" :: "r"(so), "l"(gp));
}
__device__ __forceinline__ void ldsm4(uint32_t& r0, uint32_t& r1, uint32_t& r2, uint32_t& r3,
                                      uint32_t addr) {
    asm volatile("ldmatrix.sync.aligned.m8n8.x4.shared.b16 {%0,%1,%2,%3}, [%4];"
                 : "=r"(r0), "=r"(r1), "=r"(r2), "=r"(r3) : "r"(addr));
}
__device__ __forceinline__ void hmma(float* c, const uint32_t* a, const uint32_t* b) {
    asm volatile(
        "mma.sync.aligned.m16n8k16.row.col.f32.f16.f16.f32 "
        "{%0,%1,%2,%3}, {%4,%5,%6,%7}, {%8,%9}, {%0,%1,%2,%3};"
        : "+f"(c[0]), "+f"(c[1]), "+f"(c[2]), "+f"(c[3])
        : "r"(a[0]), "r"(a[1]), "r"(a[2]), "r"(a[3]), "r"(b[0]), "r"(b[1]));
}
__device__ __forceinline__ void split1h(float x, __half& h, __half& l) {
    h = __float2half_rn(x);
    l = __float2half_rn(x - __half2float(h));
}

// CTA rasterization swizzle: 16 M-rows per super-block so a wave's tiles
// share A rows and a narrow band of B columns (working set ~34MB << L2).
// All grids here have gridDim.y == 32 (divisible by 16).
__device__ __forceinline__ void tile_swizzle(int& mb, int& nb) {
    const int bid = blockIdx.y * gridDim.x + blockIdx.x;
    const int per = gridDim.x << 4;
    const int g = bid / per;
    const int r = bid - g * per;
    mb = (g << 4) + (r & 15);
    nb = r >> 4;
}

// ===========================================================================
// K1: single-plane fp16 GEMM  C[M,N] = A[M,K] * B[N,K]^T
// CTA tile 128 x NT (NT = 256 or 128), 8 warps, warp tile 64 x NT/4,
// K-slab 64, 4-stage cp.async pipeline, ONE barrier per slab.
// MODE 0: store fp32 C.   MODE 1: accumulate into fp32 C.
// MODE 2: columns interleave (gate,up) -> act = silu(g)*u, fp16 to actout[M,N/2].
// ===========================================================================
template <int MODE, int NT>
__global__ __launch_bounds__(256, 1)
void gemm_1t(const __half* __restrict__ A, const __half* __restrict__ B,
             float* __restrict__ C, __half* __restrict__ actout,
             int N_, int K_)
{
    constexpr int WN    = NT / 4;          // warp n-width (64 or 32)
    constexpr int NTI   = WN / 16;         // ldsm n-tiles per warp (4 or 2)
    constexpr int NACC  = WN / 8;          // mma n-tiles per warp (8 or 4)
    constexpr int BST   = NT * 128;        // B stage bytes
    constexpr int STAGE = 16384 + BST;     // A(16KB) + B

    extern __shared__ char smem[];
    const uint32_t sb = smem_u32(smem);
    const int tid  = threadIdx.x;
    const int wid  = tid >> 5;
    const int lane = tid & 31;

    int mb, nb;
    tile_swizzle(mb, nb);
    const int m0 = mb << 7;
    const int n0 = nb * NT;
    const int wm = (wid & 1) * 64;
    const int wn = (wid >> 1) * WN;

    const int NC = K_ >> 6;

    auto load_chunk = [&](int kt, int s) {
        const uint32_t st = sb + (uint32_t)s * STAGE;
        const size_t kof = (size_t)kt << 6;
#pragma unroll
        for (int i = 0; i < 4; i++) {                   // A: 1024 16B units
            int e = i * 256 + tid, row = e >> 3, kb = e & 7;
            cp16(st + row * 128 + ((kb ^ (row & 7)) << 4),
                 A + (size_t)(m0 + row) * K_ + kof + kb * 8);
        }
#pragma unroll
        for (int i = 0; i < NT / 32; i++) {             // B: NT rows
            int e = i * 256 + tid, row = e >> 3, kb = e & 7;
            cp16(st + 16384 + row * 128 + ((kb ^ (row & 7)) << 4),
                 B + (size_t)(n0 + row) * K_ + kof + kb * 8);
        }
    };

    load_chunk(0, 0);
    asm volatile("cp.async.commit_group;" ::: "memory");
    load_chunk(1, 1);
    asm volatile("cp.async.commit_group;" ::: "memory");
    load_chunk(2, 2);
    asm volatile("cp.async.commit_group;" ::: "memory");

    float acc[4][NACC][4];
#pragma unroll
    for (int i = 0; i < 4; i++)
#pragma unroll
        for (int j = 0; j < NACC; j++)
#pragma unroll
            for (int q = 0; q < 4; q++) acc[i][j][q] = 0.0f;

    const int a_rsel = lane & 15;
    const int a_ksel = lane >> 4;
    const int b_rsel = (lane & 7) + (((lane >> 4) & 1) << 3);
    const int b_ksel = (lane >> 3) & 1;

    for (int kt = 0; kt < NC; kt++) {
        const int s = kt & 3;
        asm volatile("cp.async.wait_group 2;" ::: "memory");
        __syncthreads();
        // Refill slot (kt+3)&3 — last read at iteration kt-1, protected by the
        // barrier above. Issue loads first so cp.async overlaps the MMA below.
        if (kt + 3 < NC) load_chunk(kt + 3, (kt + 3) & 3);
        asm volatile("cp.async.commit_group;" ::: "memory");

        const uint32_t stg = sb + (uint32_t)s * STAGE;
#pragma unroll
        for (int kk = 0; kk < 4; kk++) {
            uint32_t a[4][4];
            const int akb = kk * 2 + a_ksel;
            const int bkb = kk * 2 + b_ksel;
#pragma unroll
            for (int mi = 0; mi < 4; mi++) {
                int row = wm + mi * 16 + a_rsel;
                ldsm4(a[mi][0], a[mi][1], a[mi][2], a[mi][3],
                      stg + row * 128 + ((akb ^ (row & 7)) << 4));
            }
#pragma unroll
            for (int nt = 0; nt < NTI; nt++) {
                int nrow = wn + nt * 16 + b_rsel;
                uint32_t offB = nrow * 128 + ((bkb ^ (nrow & 7)) << 4);
                uint32_t b0[2], b1[2];
                ldsm4(b0[0], b0[1], b1[0], b1[1], stg + 16384 + offB);
#pragma unroll
                for (int mi = 0; mi < 4; mi++) {
                    hmma(acc[mi][2 * nt],     a[mi], b0);
                    hmma(acc[mi][2 * nt + 1], a[mi], b1);
                }
            }
        }
    }

    // Epilogue
    const int erow = lane >> 2;
    const int ecol = (lane & 3) * 2;
#pragma unroll
    for (int mi = 0; mi < 4; mi++)
#pragma unroll
        for (int ni = 0; ni < NACC; ni++) {
            const int r0 = m0 + wm + mi * 16 + erow;
            if (MODE == 2) {
                const int F = N_ >> 1;
                const int f = ((n0 + wn) >> 1) + ni * 4 + (lane & 3);
                float g0 = acc[mi][ni][0], u0 = acc[mi][ni][1];
                float g1 = acc[mi][ni][2], u1 = acc[mi][ni][3];
                float a0 = u0 * g0 / (1.0f + __expf(-g0));
                float a1 = u1 * g1 / (1.0f + __expf(-g1));
                actout[(size_t)r0 * F + f]       = __float2half_rn(a0);
                actout[(size_t)(r0 + 8) * F + f] = __float2half_rn(a1);
            } else {
                float* Cp0 = C + (size_t)r0 * N_ + n0 + wn + ni * 8 + ecol;
                float* Cp1 = Cp0 + (size_t)8 * N_;
                float2 v0 = make_float2(acc[mi][ni][0], acc[mi][ni][1]);
                float2 v1 = make_float2(acc[mi][ni][2], acc[mi][ni][3]);
                if (MODE == 1) {
                    float2 o0 = *(const float2*)Cp0;
                    float2 o1 = *(const float2*)Cp1;
                    v0.x += o0.x; v0.y += o0.y;
                    v1.x += o1.x; v1.y += o1.y;
                }
                *(float2*)Cp0 = v0;
                *(float2*)Cp1 = v1;
            }
        }
}

#define K1_SMEM_256 (4 * (16384 + 256 * 128))
#define K1_SMEM_128 (4 * (16384 + 128 * 128))

// ===========================================================================
// K2: fp16x3 split GEMM (mask-exact) over interleaved [up_w;gate_w].
// CTA 128x128, 8 warps (2m x 4n), warp 64x32, K-slab 64, 3-stage pipeline
// (kt+3 aliases slot kt, so loads stay AFTER the MMA + second barrier).
// Columns pair as (approx_up, gate_pre); epilogue emits all 7 Taylor
// coefficient planes of U directly as fp16 to g_Uh[M, 7168].
// ===========================================================================
#define K2_STAGE 65536
#define K2_SMEM  (3 * K2_STAGE)

__global__ __launch_bounds__(256, 1)
void gemm1_u(const __half* __restrict__ Ahi, const __half* __restrict__ Alo,
             const __half* __restrict__ Bhi, const __half* __restrict__ Blo,
             const float* __restrict__ lp, __half* __restrict__ Uout,
             int N_, int K_)
{
    extern __shared__ char smem[];
    const uint32_t sb = smem_u32(smem);
    const int tid  = threadIdx.x;
    const int wid  = tid >> 5;
    const int lane = tid & 31;

    int mb, nb;
    tile_swizzle(mb, nb);
    const int m0 = mb << 7;
    const int n0 = nb << 7;
    const int wm = (wid >> 2) * 64;
    const int wn = (wid & 3) * 32;

    const int NC = K_ >> 6;

    auto load_chunk = [&](int kt, int s) {
        const uint32_t st = sb + (uint32_t)s * K2_STAGE;
        const size_t kof = (size_t)kt << 6;
#pragma unroll
        for (int i = 0; i < 8; i++) {
            int e = i * 256 + tid;
            int p = e >> 10, row = (e >> 3) & 127, kb = e & 7;
            const __half* src = (p ? Alo : Ahi) + (size_t)(m0 + row) * K_ + kof + kb * 8;
            cp16(st + p * 16384 + row * 128 + ((kb ^ (row & 7)) << 4), src);
        }
#pragma unroll
        for (int i = 0; i < 8; i++) {
            int e = i * 256 + tid;
            int p = e >> 10, row = (e >> 3) & 127, kb = e & 7;
            const __half* src = (p ? Blo : Bhi) + (size_t)(n0 + row) * K_ + kof + kb * 8;
            cp16(st + 32768 + p * 16384 + row * 128 + ((kb ^ (row & 7)) << 4), src);
        }
    };

    load_chunk(0, 0);
    asm volatile("cp.async.commit_group;" ::: "memory");
    load_chunk(1, 1);
    asm volatile("cp.async.commit_group;" ::: "memory");
    load_chunk(2, 2);
    asm volatile("cp.async.commit_group;" ::: "memory");

    float acc[4][4][4];
#pragma unroll
    for (int i = 0; i < 4; i++)
#pragma unroll
        for (int j = 0; j < 4; j++)
#pragma unroll
            for (int q = 0; q < 4; q++) acc[i][j][q] = 0.0f;

    const int a_rsel = lane & 15;
    const int a_ksel = lane >> 4;
    const int b_rsel = (lane & 7) + (((lane >> 4) & 1) << 3);
    const int b_ksel = (lane >> 3) & 1;

    for (int kt = 0; kt < NC; kt++) {
        const int s = kt % 3;
        asm volatile("cp.async.wait_group 2;" ::: "memory");
        __syncthreads();

        const uint32_t stA = sb + (uint32_t)s * K2_STAGE;
        const uint32_t stB = stA + 32768;
#pragma unroll
        for (int kk = 0; kk < 4; kk++) {
            uint32_t Ah[4][4], Al[4][4], Bh[4][2], Bl[4][2];
            const int akb = kk * 2 + a_ksel;
            const int bkb = kk * 2 + b_ksel;
#pragma unroll
            for (int mi = 0; mi < 4; mi++) {
                int row = wm + mi * 16 + a_rsel;
                uint32_t off = row * 128 + ((akb ^ (row & 7)) << 4);
                ldsm4(Ah[mi][0], Ah[mi][1], Ah[mi][2], Ah[mi][3], stA + off);
                ldsm4(Al[mi][0], Al[mi][1], Al[mi][2], Al[mi][3], stA + 16384 + off);
            }
#pragma unroll
            for (int nt = 0; nt < 2; nt++) {
                int nrow = wn + nt * 16 + b_rsel;
                uint32_t off = nrow * 128 + ((bkb ^ (nrow & 7)) << 4);
                ldsm4(Bh[2 * nt][0], Bh[2 * nt][1], Bh[2 * nt + 1][0], Bh[2 * nt + 1][1],
                      stB + off);
                ldsm4(Bl[2 * nt][0], Bl[2 * nt][1], Bl[2 * nt + 1][0], Bl[2 * nt + 1][1],
                      stB + 16384 + off);
            }
#pragma unroll
            for (int mi = 0; mi < 4; mi++)
#pragma unroll
                for (int ni = 0; ni < 4; ni++) {
                    hmma(acc[mi][ni], Ah[mi], Bh[ni]);
                    hmma(acc[mi][ni], Ah[mi], Bl[ni]);
                    hmma(acc[mi][ni], Al[mi], Bh[ni]);
                }
        }
        __syncthreads();
        if (kt + 3 < NC) load_chunk(kt + 3, s);
        asm volatile("cp.async.commit_group;" ::: "memory");
    }

    // Epilogue: (au, gp) column pairs -> 7 Taylor coefficient planes of U
    const int erow = lane >> 2;
#pragma unroll
    for (int mi = 0; mi < 4; mi++)
#pragma unroll
        for (int ni = 0; ni < 4; ni++) {
            const int s = ((n0 + wn) >> 1) + ni * 4 + (lane & 3);
            const float lpv = __ldg(lp + s);
#pragma unroll
            for (int rr = 0; rr < 2; rr++) {
                const int row = m0 + wm + mi * 16 + erow + rr * 8;
                const float au = acc[mi][ni][2 * rr + 0];
                const float gp = acc[mi][ni][2 * rr + 1];
                const float delta = gp - lpv;
                const float keep  = (fabsf(delta) <= 2.5f) ? 1.0f : 0.0f;
                __half* Up = Uout + (size_t)row * KU + s;
                float p = delta;
                Up[0 * S_DIM] = __float2half_rn(au);
                Up[1 * S_DIM] = __float2half_rn(p * au);
                p *= delta; Up[2 * S_DIM] = __float2half_rn(p * (1.0f / 2.0f)   * au);
                p *= delta; Up[3 * S_DIM] = __float2half_rn(p * (1.0f / 6.0f)   * au);
                p *= delta; Up[4 * S_DIM] = __float2half_rn(p * (1.0f / 24.0f)  * au);
                p *= delta; Up[5 * S_DIM] = __float2half_rn(p * (1.0f / 120.0f) * au * keep);
                p *= delta; Up[6 * S_DIM] = __float2half_rn(p * (1.0f / 720.0f) * au * keep);
            }
        }
}

// ---------------------------------------------------------------------------
// Conversion / pack kernels
// ---------------------------------------------------------------------------
__global__ void split_kernel(const float* __restrict__ x, __half* __restrict__ hi,
                             __half* __restrict__ lo)
{
    size_t i = ((size_t)blockIdx.x * blockDim.x + threadIdx.x) * 4;
    float4 v = *(const float4*)(x + i);
    __half2 h01, h23, l01, l23;
    __half h, l;
    split1h(v.x, h, l); h01.x = h; l01.x = l;
    split1h(v.y, h, l); h01.y = h; l01.y = l;
    split1h(v.z, h, l); h23.x = h; l23.x = l;
    split1h(v.w, h, l); h23.y = h; l23.y = l;
    *(__half2*)(hi + i)     = h01;
    *(__half2*)(hi + i + 2) = h23;
    *(__half2*)(lo + i)     = l01;
    *(__half2*)(lo + i + 2) = l23;
}

__global__ void cvt_hi_kernel(const float* __restrict__ x, __half* __restrict__ hi)
{
    size_t i = ((size_t)blockIdx.x * blockDim.x + threadIdx.x) * 4;
    float4 v = *(const float4*)(x + i);
    __half2 h01, h23;
    h01.x = __float2half_rn(v.x); h01.y = __float2half_rn(v.y);
    h23.x = __float2half_rn(v.z); h23.y = __float2half_rn(v.w);
    *(__half2*)(hi + i)     = h01;
    *(__half2*)(hi + i + 2) = h23;
}

// Interleave rows of two [R, 4096] matrices with hi/lo split (for up_w/gate_w)
__global__ void pack_pair_hl_kernel(const float* __restrict__ even, const float* __restrict__ odd,
                                    __half* __restrict__ hi, __half* __restrict__ lo)
{
    size_t i = ((size_t)blockIdx.x * blockDim.x + threadIdx.x) * 4;
    size_t r = i >> 12;
    size_t h = i & 4095;
    const float* src = ((r & 1) ? odd : even) + ((r >> 1) << 12) + h;
    float4 v = *(const float4*)src;
    __half2 h01, h23, l01, l23;
    __half hh, ll;
    split1h(v.x, hh, ll); h01.x = hh; l01.x = ll;
    split1h(v.y, hh, ll); h01.y = hh; l01.y = ll;
    split1h(v.z, hh, ll); h23.x = hh; l23.x = ll;
    split1h(v.w, hh, ll); h23.y = hh; l23.y = ll;
    *(__half2*)(hi + i)     = h01;
    *(__half2*)(hi + i + 2) = h23;
    *(__half2*)(lo + i)     = l01;
    *(__half2*)(lo + i + 2) = l23;
}

// Interleave rows of two [R, 4096] matrices, hi only (for fg/fu)
__global__ void pack_pair_hi_kernel(const float* __restrict__ even, const float* __restrict__ odd,
                                    __half* __restrict__ hi)
{
    size_t i = ((size_t)blockIdx.x * blockDim.x + threadIdx.x) * 4;
    size_t r = i >> 12;
    size_t h = i & 4095;
    const float* src = ((r & 1) ? odd : even) + ((r >> 1) << 12) + h;
    float4 v = *(const float4*)src;
    __half2 h01, h23;
    h01.x = __float2half_rn(v.x); h01.y = __float2half_rn(v.y);
    h23.x = __float2half_rn(v.z); h23.y = __float2half_rn(v.w);
    *(__half2*)(hi + i)     = h01;
    *(__half2*)(hi + i + 2) = h23;
}

// Wcat[H, 7S] hi-only: block 0 = local_approx_output, block idx+1 = fuse[:,:,idx]
__global__ void pack_W_kernel(const float* __restrict__ lao, const float* __restrict__ fuse)
{
    int i = blockIdx.x * blockDim.x + threadIdx.x;      // over H*S
    int s = i & (S_DIM - 1);
    size_t base = (size_t)(i >> 10) * KU + s;
    g_Whi[base] = __float2half_rn(lao[i]);
    const float* f = fuse + (size_t)i * 6;
#pragma unroll
    for (int idx = 0; idx < 6; idx++)
        g_Whi[base + (idx + 1) * S_DIM] = __float2half_rn(f[idx]);
}

// ---------------------------------------------------------------------------
// Launch: all graph-capturable, default stream, no allocations.
// ---------------------------------------------------------------------------
extern "C" void kernel_launch(void* const* d_in, const int* in_sizes, int n_in,
                              void* d_out, int out_size)
{
    const float* X   = (const float*)d_in[0];
    const float* upw = (const float*)d_in[1];
    const float* gw  = (const float*)d_in[2];
    const float* lp  = (const float*)d_in[3];
    const float* lao = (const float*)d_in[4];
    const float* fw  = (const float*)d_in[5];
    const float* fg  = (const float*)d_in[7];
    const float* fu  = (const float*)d_in[8];
    const float* fd  = (const float*)d_in[9];
    float* out = (float*)d_out;

    cudaFuncSetAttribute(gemm_1t<0,128>, cudaFuncAttributeMaxDynamicSharedMemorySize, K1_SMEM_128);
    cudaFuncSetAttribute(gemm_1t<1,128>, cudaFuncAttributeMaxDynamicSharedMemorySize, K1_SMEM_128);
    cudaFuncSetAttribute(gemm_1t<2,256>, cudaFuncAttributeMaxDynamicSharedMemorySize, K1_SMEM_256);
    cudaFuncSetAttribute(gemm1_u,        cudaFuncAttributeMaxDynamicSharedMemorySize, K2_SMEM);

    __half *p_Xhi, *p_Xlo, *p_ugh, *p_ugl, *p_Whi, *p_fgfuh, *p_fdh, *p_Uh, *p_acth;
    cudaGetSymbolAddress((void**)&p_Xhi,   g_Xhi);
    cudaGetSymbolAddress((void**)&p_Xlo,   g_Xlo);
    cudaGetSymbolAddress((void**)&p_ugh,   g_ugh);
    cudaGetSymbolAddress((void**)&p_ugl,   g_ugl);
    cudaGetSymbolAddress((void**)&p_Whi,   g_Whi);
    cudaGetSymbolAddress((void**)&p_fgfuh, g_fgfuh);
    cudaGetSymbolAddress((void**)&p_fdh,   g_fdh);
    cudaGetSymbolAddress((void**)&p_Uh,    g_Uh);
    cudaGetSymbolAddress((void**)&p_acth,  g_acth);

    const dim3 blk(256);
    const size_t MH  = (size_t)M_TOK * H_DIM;
    const size_t SH2 = (size_t)2 * S_DIM * H_DIM;
    const size_t FH2 = (size_t)2 * F_DIM * H_DIM;
    const size_t FH  = (size_t)F_DIM * H_DIM;

    // Conversions
    split_kernel<<<(unsigned)(MH / 1024), blk>>>(X, p_Xhi, p_Xlo);
    pack_pair_hl_kernel<<<(unsigned)(SH2 / 1024), blk>>>(upw, gw, p_ugh, p_ugl);
    pack_W_kernel<<<(H_DIM * S_DIM) / 256, blk>>>(lao, fw);
    pack_pair_hi_kernel<<<(unsigned)(FH2 / 1024), blk>>>(fg, fu, p_fgfuh);
    cvt_hi_kernel<<<(unsigned)(FH / 1024), blk>>>(fd, p_fdh);

    // gemm1 (fp16x3, mask-exact): X @ [up_w;gate_w]^T -> U coefficient planes
    gemm1_u<<<dim3(2 * S_DIM / 128, M_TOK / 128), blk, K2_SMEM>>>(
        p_Xhi, p_Xlo, p_ugh, p_ugl, lp, p_Uh, 2 * S_DIM, H_DIM);

    // Taylor GEMM: out = U @ Wcat^T  (single-plane fp16, 128x128 tiles)
    gemm_1t<0,128><<<dim3(H_DIM / 128, M_TOK / 128), blk, K1_SMEM_128>>>(
        p_Uh, p_Whi, out, nullptr, H_DIM, KU);

    // Fused gate/up GEMM + silu epilogue: act = silu(X@fg^T) * (X@fu^T)
    gemm_1t<2,256><<<dim3(2 * F_DIM / 256, M_TOK / 128), blk, K1_SMEM_256>>>(
        p_Xhi, p_fgfuh, nullptr, p_acth, 2 * F_DIM, H_DIM);

    // out += act @ fd^T  (accumulating epilogue, 128x128 tiles)
    gemm_1t<1,128><<<dim3(H_DIM / 128, M_TOK / 128), blk, K1_SMEM_128>>>(
        p_acth, p_fdh, out, nullptr, H_DIM, F_DIM);
}

// round 11
// speedup vs baseline: 7.7167x; 1.0168x over previous
#include <cuda_runtime.h>
#include <cuda_fp16.h>
#include <cstdint>

// ---------------------------------------------------------------------------
// Problem constants (B=2, T=2048, H=4096, S=1024, F=9984, G=6)
// ---------------------------------------------------------------------------
#define M_TOK 4096
#define H_DIM 4096
#define S_DIM 1024
#define F_DIM 9984
#define KU    7168              // 7*S : Taylor K
#define KW    17152             // KU + F : merged K (Taylor + down-proj)

// ---------------------------------------------------------------------------
// Device-global scratch (no allocations allowed anywhere)
// ---------------------------------------------------------------------------
__device__ __half g_Xhi  [(size_t)M_TOK * H_DIM];
__device__ __half g_Xlo  [(size_t)M_TOK * H_DIM];
__device__ __half g_ugh  [(size_t)2 * S_DIM * H_DIM];   // interleaved up_w/gate_w hi
__device__ __half g_ugl  [(size_t)2 * S_DIM * H_DIM];   // lo
__device__ __half g_fgfuh[(size_t)2 * F_DIM * H_DIM];   // interleaved fg/fu (hi only)
__device__ __half g_UA   [(size_t)M_TOK * KW];          // [U | act]  (hi only)
__device__ __half g_WD   [(size_t)H_DIM * KW];          // [Wcat | fd] (hi only)

// ---------------------------------------------------------------------------
// PTX helpers (baseline sm_103 — no tcgen05)
// ---------------------------------------------------------------------------
__device__ __forceinline__ uint32_t smem_u32(const void* p) {
    uint32_t a;
    asm("{ .reg .u64 t; cvta.to.shared.u64 t, %1; cvt.u32.u64 %0, t; }" : "=r"(a) : "l"(p));
    return a;
}
__device__ __forceinline__ void cp16(uint32_t so, const void* gp) {
    asm volatile("cp.async.cg.shared.global [%0], [%1], 16;" :: "r"(so), "l"(gp));
}
__device__ __forceinline__ void ldsm4(uint32_t& r0, uint32_t& r1, uint32_t& r2, uint32_t& r3,
                                      uint32_t addr) {
    asm volatile("ldmatrix.sync.aligned.m8n8.x4.shared.b16 {%0,%1,%2,%3}, [%4];"
                 : "=r"(r0), "=r"(r1), "=r"(r2), "=r"(r3) : "r"(addr));
}
__device__ __forceinline__ void hmma(float* c, const uint32_t* a, const uint32_t* b) {
    asm volatile(
        "mma.sync.aligned.m16n8k16.row.col.f32.f16.f16.f32 "
        "{%0,%1,%2,%3}, {%4,%5,%6,%7}, {%8,%9}, {%0,%1,%2,%3};"
        : "+f"(c[0]), "+f"(c[1]), "+f"(c[2]), "+f"(c[3])
        : "r"(a[0]), "r"(a[1]), "r"(a[2]), "r"(a[3]), "r"(b[0]), "r"(b[1]));
}
__device__ __forceinline__ void split1h(float x, __half& h, __half& l) {
    h = __float2half_rn(x);
    l = __float2half_rn(x - __half2float(h));
}

// CTA rasterization swizzle: 16 M-rows per super-block (gridDim.y % 16 == 0).
__device__ __forceinline__ void tile_swizzle(int& mb, int& nb) {
    const int bid = blockIdx.y * gridDim.x + blockIdx.x;
    const int per = gridDim.x << 4;
    const int g = bid / per;
    const int r = bid - g * per;
    mb = (g << 4) + (r & 15);
    nb = r >> 4;
}

// ===========================================================================
// K1: single-plane fp16 GEMM  C[M,N] = A[M,K] * B[N,K]^T
// CTA 128 x NT, 8 warps, warp 64 x NT/4, K-slab 64, 4-stage cp.async.
// NT==128: explicit double-buffered fragments (load kk+1 during kk's HMMAs).
// NT==256: all fragments loaded upfront per kk (register budget).
// MODE 0: store fp32 C.
// MODE 2: columns interleave (gate,up) -> act = silu(g)*u, fp16 to
//         actout[M, ldAct] (row stride ldAct).
// ===========================================================================
template <int MODE, int NT>
__global__ __launch_bounds__(256, 1)
void gemm_1t(const __half* __restrict__ A, const __half* __restrict__ B,
             float* __restrict__ C, __half* __restrict__ actout,
             int ldAct, int N_, int K_)
{
    constexpr int WN    = NT / 4;
    constexpr int NTI   = WN / 16;         // x4-ldsm n-loads per warp (4 or 2)
    constexpr int NACC  = WN / 8;
    constexpr int STAGE = 16384 + NT * 128;
    constexpr bool DB   = (NT == 128);

    extern __shared__ char smem[];
    const uint32_t sb = smem_u32(smem);
    const int tid  = threadIdx.x;
    const int wid  = tid >> 5;
    const int lane = tid & 31;

    int mb, nb;
    tile_swizzle(mb, nb);
    const int m0 = mb << 7;
    const int n0 = nb * NT;
    const int wm = (wid & 1) * 64;
    const int wn = (wid >> 1) * WN;

    const int NC = K_ >> 6;

    auto load_chunk = [&](int kt, int s) {
        const uint32_t st = sb + (uint32_t)s * STAGE;
        const size_t kof = (size_t)kt << 6;
#pragma unroll
        for (int i = 0; i < 4; i++) {
            int e = i * 256 + tid, row = e >> 3, kb = e & 7;
            cp16(st + row * 128 + ((kb ^ (row & 7)) << 4),
                 A + (size_t)(m0 + row) * K_ + kof + kb * 8);
        }
#pragma unroll
        for (int i = 0; i < NT / 32; i++) {
            int e = i * 256 + tid, row = e >> 3, kb = e & 7;
            cp16(st + 16384 + row * 128 + ((kb ^ (row & 7)) << 4),
                 B + (size_t)(n0 + row) * K_ + kof + kb * 8);
        }
    };

    load_chunk(0, 0);
    asm volatile("cp.async.commit_group;" ::: "memory");
    load_chunk(1, 1);
    asm volatile("cp.async.commit_group;" ::: "memory");
    load_chunk(2, 2);
    asm volatile("cp.async.commit_group;" ::: "memory");

    float acc[4][NACC][4];
#pragma unroll
    for (int i = 0; i < 4; i++)
#pragma unroll
        for (int j = 0; j < NACC; j++)
#pragma unroll
            for (int q = 0; q < 4; q++) acc[i][j][q] = 0.0f;

    const int a_rsel = lane & 15;
    const int a_ksel = lane >> 4;
    const int b_rsel = (lane & 7) + (((lane >> 4) & 1) << 3);
    const int b_ksel = (lane >> 3) & 1;

    for (int kt = 0; kt < NC; kt++) {
        const int s = kt & 3;
        asm volatile("cp.async.wait_group 2;" ::: "memory");
        __syncthreads();
        if (kt + 3 < NC) load_chunk(kt + 3, (kt + 3) & 3);
        asm volatile("cp.async.commit_group;" ::: "memory");

        const uint32_t stg = sb + (uint32_t)s * STAGE;

        uint32_t af[DB ? 2 : 1][4][4];
        uint32_t bf[DB ? 2 : 1][NTI][4];

        auto ldA = [&](int kk, int buf) {
            const int akb = kk * 2 + a_ksel;
#pragma unroll
            for (int mi = 0; mi < 4; mi++) {
                int row = wm + mi * 16 + a_rsel;
                ldsm4(af[buf][mi][0], af[buf][mi][1], af[buf][mi][2], af[buf][mi][3],
                      stg + row * 128 + ((akb ^ (row & 7)) << 4));
            }
        };
        auto ldB = [&](int kk, int buf) {
            const int bkb = kk * 2 + b_ksel;
#pragma unroll
            for (int nt = 0; nt < NTI; nt++) {
                int nrow = wn + nt * 16 + b_rsel;
                ldsm4(bf[buf][nt][0], bf[buf][nt][1], bf[buf][nt][2], bf[buf][nt][3],
                      stg + 16384 + nrow * 128 + ((bkb ^ (nrow & 7)) << 4));
            }
        };

        if (DB) { ldA(0, 0); ldB(0, 0); }
#pragma unroll
        for (int kk = 0; kk < 4; kk++) {
            const int cur = DB ? (kk & 1) : 0;
            if (!DB) { ldA(kk, 0); ldB(kk, 0); }
            if (DB && kk < 3) { ldA(kk + 1, cur ^ 1); ldB(kk + 1, cur ^ 1); }
#pragma unroll
            for (int nt = 0; nt < NTI; nt++)
#pragma unroll
                for (int mi = 0; mi < 4; mi++) {
                    hmma(acc[mi][2 * nt],     af[cur][mi], &bf[cur][nt][0]);
                    hmma(acc[mi][2 * nt + 1], af[cur][mi], &bf[cur][nt][2]);
                }
        }
    }

    // Epilogue
    const int erow = lane >> 2;
    const int ecol = (lane & 3) * 2;
#pragma unroll
    for (int mi = 0; mi < 4; mi++)
#pragma unroll
        for (int ni = 0; ni < NACC; ni++) {
            const int r0 = m0 + wm + mi * 16 + erow;
            if (MODE == 2) {
                const int f = ((n0 + wn) >> 1) + ni * 4 + (lane & 3);
                float g0 = acc[mi][ni][0], u0 = acc[mi][ni][1];
                float g1 = acc[mi][ni][2], u1 = acc[mi][ni][3];
                float a0 = u0 * g0 / (1.0f + __expf(-g0));
                float a1 = u1 * g1 / (1.0f + __expf(-g1));
                actout[(size_t)r0 * ldAct + f]       = __float2half_rn(a0);
                actout[(size_t)(r0 + 8) * ldAct + f] = __float2half_rn(a1);
            } else {
                float* Cp0 = C + (size_t)r0 * N_ + n0 + wn + ni * 8 + ecol;
                float* Cp1 = Cp0 + (size_t)8 * N_;
                *(float2*)Cp0 = make_float2(acc[mi][ni][0], acc[mi][ni][1]);
                *(float2*)Cp1 = make_float2(acc[mi][ni][2], acc[mi][ni][3]);
            }
        }
}

#define K1_SMEM_256 (4 * (16384 + 256 * 128))
#define K1_SMEM_128 (4 * (16384 + 128 * 128))

// ===========================================================================
// K2: fp16x3 split GEMM (mask-exact) over interleaved [up_w;gate_w].
// CTA 128x128, 8 warps (2m x 4n), warp 64x32, K-slab 64, 3-stage pipeline,
// double-buffered fragments. Epilogue emits all 7 Taylor coefficient planes
// into Uout (row stride ldU, planes at j*1024).
// ===========================================================================
#define K2_STAGE 65536
#define K2_SMEM  (3 * K2_STAGE)

__global__ __launch_bounds__(256, 1)
void gemm1_u(const __half* __restrict__ Ahi, const __half* __restrict__ Alo,
             const __half* __restrict__ Bhi, const __half* __restrict__ Blo,
             const float* __restrict__ lp, __half* __restrict__ Uout,
             int ldU, int N_, int K_)
{
    extern __shared__ char smem[];
    const uint32_t sb = smem_u32(smem);
    const int tid  = threadIdx.x;
    const int wid  = tid >> 5;
    const int lane = tid & 31;

    int mb, nb;
    tile_swizzle(mb, nb);
    const int m0 = mb << 7;
    const int n0 = nb << 7;
    const int wm = (wid >> 2) * 64;
    const int wn = (wid & 3) * 32;

    const int NC = K_ >> 6;

    auto load_chunk = [&](int kt, int s) {
        const uint32_t st = sb + (uint32_t)s * K2_STAGE;
        const size_t kof = (size_t)kt << 6;
#pragma unroll
        for (int i = 0; i < 8; i++) {
            int e = i * 256 + tid;
            int p = e >> 10, row = (e >> 3) & 127, kb = e & 7;
            const __half* src = (p ? Alo : Ahi) + (size_t)(m0 + row) * K_ + kof + kb * 8;
            cp16(st + p * 16384 + row * 128 + ((kb ^ (row & 7)) << 4), src);
        }
#pragma unroll
        for (int i = 0; i < 8; i++) {
            int e = i * 256 + tid;
            int p = e >> 10, row = (e >> 3) & 127, kb = e & 7;
            const __half* src = (p ? Blo : Bhi) + (size_t)(n0 + row) * K_ + kof + kb * 8;
            cp16(st + 32768 + p * 16384 + row * 128 + ((kb ^ (row & 7)) << 4), src);
        }
    };

    load_chunk(0, 0);
    asm volatile("cp.async.commit_group;" ::: "memory");
    load_chunk(1, 1);
    asm volatile("cp.async.commit_group;" ::: "memory");
    load_chunk(2, 2);
    asm volatile("cp.async.commit_group;" ::: "memory");

    float acc[4][4][4];
#pragma unroll
    for (int i = 0; i < 4; i++)
#pragma unroll
        for (int j = 0; j < 4; j++)
#pragma unroll
            for (int q = 0; q < 4; q++) acc[i][j][q] = 0.0f;

    const int a_rsel = lane & 15;
    const int a_ksel = lane >> 4;
    const int b_rsel = (lane & 7) + (((lane >> 4) & 1) << 3);
    const int b_ksel = (lane >> 3) & 1;

    for (int kt = 0; kt < NC; kt++) {
        const int s = kt % 3;
        asm volatile("cp.async.wait_group 2;" ::: "memory");
        __syncthreads();

        const uint32_t stA = sb + (uint32_t)s * K2_STAGE;
        const uint32_t stB = stA + 32768;

        uint32_t Ah[2][4][4], Al[2][4][4], Bh[2][2][4], Bl[2][2][4];

        auto ldfrag = [&](int kk, int buf) {
            const int akb = kk * 2 + a_ksel;
            const int bkb = kk * 2 + b_ksel;
#pragma unroll
            for (int mi = 0; mi < 4; mi++) {
                int row = wm + mi * 16 + a_rsel;
                uint32_t off = row * 128 + ((akb ^ (row & 7)) << 4);
                ldsm4(Ah[buf][mi][0], Ah[buf][mi][1], Ah[buf][mi][2], Ah[buf][mi][3],
                      stA + off);
                ldsm4(Al[buf][mi][0], Al[buf][mi][1], Al[buf][mi][2], Al[buf][mi][3],
                      stA + 16384 + off);
            }
#pragma unroll
            for (int nt = 0; nt < 2; nt++) {
                int nrow = wn + nt * 16 + b_rsel;
                uint32_t off = nrow * 128 + ((bkb ^ (nrow & 7)) << 4);
                ldsm4(Bh[buf][nt][0], Bh[buf][nt][1], Bh[buf][nt][2], Bh[buf][nt][3],
                      stB + off);
                ldsm4(Bl[buf][nt][0], Bl[buf][nt][1], Bl[buf][nt][2], Bl[buf][nt][3],
                      stB + 16384 + off);
            }
        };

        ldfrag(0, 0);
#pragma unroll
        for (int kk = 0; kk < 4; kk++) {
            const int cur = kk & 1;
            if (kk < 3) ldfrag(kk + 1, cur ^ 1);
#pragma unroll
            for (int mi = 0; mi < 4; mi++)
#pragma unroll
                for (int ni = 0; ni < 4; ni++) {
                    const int nt = ni >> 1, hf = (ni & 1) * 2;
                    hmma(acc[mi][ni], Ah[cur][mi], &Bh[cur][nt][hf]);
                    hmma(acc[mi][ni], Ah[cur][mi], &Bl[cur][nt][hf]);
                    hmma(acc[mi][ni], Al[cur][mi], &Bh[cur][nt][hf]);
                }
        }
        __syncthreads();
        if (kt + 3 < NC) load_chunk(kt + 3, s);
        asm volatile("cp.async.commit_group;" ::: "memory");
    }

    // Epilogue: (au, gp) column pairs -> 7 Taylor coefficient planes
    const int erow = lane >> 2;
#pragma unroll
    for (int mi = 0; mi < 4; mi++)
#pragma unroll
        for (int ni = 0; ni < 4; ni++) {
            const int s = ((n0 + wn) >> 1) + ni * 4 + (lane & 3);
            const float lpv = __ldg(lp + s);
#pragma unroll
            for (int rr = 0; rr < 2; rr++) {
                const int row = m0 + wm + mi * 16 + erow + rr * 8;
                const float au = acc[mi][ni][2 * rr + 0];
                const float gp = acc[mi][ni][2 * rr + 1];
                const float delta = gp - lpv;
                const float keep  = (fabsf(delta) <= 2.5f) ? 1.0f : 0.0f;
                __half* Up = Uout + (size_t)row * ldU + s;
                float p = delta;
                Up[0 * S_DIM] = __float2half_rn(au);
                Up[1 * S_DIM] = __float2half_rn(p * au);
                p *= delta; Up[2 * S_DIM] = __float2half_rn(p * (1.0f / 2.0f)   * au);
                p *= delta; Up[3 * S_DIM] = __float2half_rn(p * (1.0f / 6.0f)   * au);
                p *= delta; Up[4 * S_DIM] = __float2half_rn(p * (1.0f / 24.0f)  * au);
                p *= delta; Up[5 * S_DIM] = __float2half_rn(p * (1.0f / 120.0f) * au * keep);
                p *= delta; Up[6 * S_DIM] = __float2half_rn(p * (1.0f / 720.0f) * au * keep);
            }
        }
}

// ---------------------------------------------------------------------------
// Conversion / pack kernels
// ---------------------------------------------------------------------------
__global__ void split_kernel(const float* __restrict__ x, __half* __restrict__ hi,
                             __half* __restrict__ lo)
{
    size_t i = ((size_t)blockIdx.x * blockDim.x + threadIdx.x) * 4;
    float4 v = *(const float4*)(x + i);
    __half2 h01, h23, l01, l23;
    __half h, l;
    split1h(v.x, h, l); h01.x = h; l01.x = l;
    split1h(v.y, h, l); h01.y = h; l01.y = l;
    split1h(v.z, h, l); h23.x = h; l23.x = l;
    split1h(v.w, h, l); h23.y = h; l23.y = l;
    *(__half2*)(hi + i)     = h01;
    *(__half2*)(hi + i + 2) = h23;
    *(__half2*)(lo + i)     = l01;
    *(__half2*)(lo + i + 2) = l23;
}

// Interleave rows of two [R, 4096] matrices with hi/lo split (up_w/gate_w)
__global__ void pack_pair_hl_kernel(const float* __restrict__ even, const float* __restrict__ odd,
                                    __half* __restrict__ hi, __half* __restrict__ lo)
{
    size_t i = ((size_t)blockIdx.x * blockDim.x + threadIdx.x) * 4;
    size_t r = i >> 12;
    size_t h = i & 4095;
    const float* src = ((r & 1) ? odd : even) + ((r >> 1) << 12) + h;
    float4 v = *(const float4*)src;
    __half2 h01, h23, l01, l23;
    __half hh, ll;
    split1h(v.x, hh, ll); h01.x = hh; l01.x = ll;
    split1h(v.y, hh, ll); h01.y = hh; l01.y = ll;
    split1h(v.z, hh, ll); h23.x = hh; l23.x = ll;
    split1h(v.w, hh, ll); h23.y = hh; l23.y = ll;
    *(__half2*)(hi + i)     = h01;
    *(__half2*)(hi + i + 2) = h23;
    *(__half2*)(lo + i)     = l01;
    *(__half2*)(lo + i + 2) = l23;
}

// Interleave rows of two [R, 4096] matrices, hi only (fg/fu)
__global__ void pack_pair_hi_kernel(const float* __restrict__ even, const float* __restrict__ odd,
                                    __half* __restrict__ hi)
{
    size_t i = ((size_t)blockIdx.x * blockDim.x + threadIdx.x) * 4;
    size_t r = i >> 12;
    size_t h = i & 4095;
    const float* src = ((r & 1) ? odd : even) + ((r >> 1) << 12) + h;
    float4 v = *(const float4*)src;
    __half2 h01, h23;
    h01.x = __float2half_rn(v.x); h01.y = __float2half_rn(v.y);
    h23.x = __float2half_rn(v.z); h23.y = __float2half_rn(v.w);
    *(__half2*)(hi + i)     = h01;
    *(__half2*)(hi + i + 2) = h23;
}

// g_WD cols 0..7167: block 0 = local_approx_output, block idx+1 = fuse[:,:,idx]
__global__ void pack_W_kernel(const float* __restrict__ lao, const float* __restrict__ fuse)
{
    int i = blockIdx.x * blockDim.x + threadIdx.x;      // over H*S
    int s = i & (S_DIM - 1);
    size_t base = (size_t)(i >> 10) * KW + s;
    g_WD[base] = __float2half_rn(lao[i]);
    const float* f = fuse + (size_t)i * 6;
#pragma unroll
    for (int idx = 0; idx < 6; idx++)
        g_WD[base + (idx + 1) * S_DIM] = __float2half_rn(f[idx]);
}

// fd [H, F] -> g_WD cols 7168..17151 (row stride KW)
__global__ void cvt_fd_kernel(const float* __restrict__ fd)
{
    size_t i = ((size_t)blockIdx.x * blockDim.x + threadIdx.x) * 4;  // over H*F
    size_t h = i / F_DIM;
    size_t j = i - h * F_DIM;          // F_DIM % 4 == 0 -> no row crossing
    float4 v = *(const float4*)(fd + i);
    __half* dst = g_WD + h * KW + KU + j;
    __half2 h01, h23;
    h01.x = __float2half_rn(v.x); h01.y = __float2half_rn(v.y);
    h23.x = __float2half_rn(v.z); h23.y = __float2half_rn(v.w);
    *(__half2*)(dst)     = h01;
    *(__half2*)(dst + 2) = h23;
}

// ---------------------------------------------------------------------------
// Launch: all graph-capturable, default stream, no allocations.
// ---------------------------------------------------------------------------
extern "C" void kernel_launch(void* const* d_in, const int* in_sizes, int n_in,
                              void* d_out, int out_size)
{
    const float* X   = (const float*)d_in[0];
    const float* upw = (const float*)d_in[1];
    const float* gw  = (const float*)d_in[2];
    const float* lp  = (const float*)d_in[3];
    const float* lao = (const float*)d_in[4];
    const float* fw  = (const float*)d_in[5];
    const float* fg  = (const float*)d_in[7];
    const float* fu  = (const float*)d_in[8];
    const float* fd  = (const float*)d_in[9];
    float* out = (float*)d_out;

    cudaFuncSetAttribute(gemm_1t<0,128>, cudaFuncAttributeMaxDynamicSharedMemorySize, K1_SMEM_128);
    cudaFuncSetAttribute(gemm_1t<2,256>, cudaFuncAttributeMaxDynamicSharedMemorySize, K1_SMEM_256);
    cudaFuncSetAttribute(gemm1_u,        cudaFuncAttributeMaxDynamicSharedMemorySize, K2_SMEM);

    __half *p_Xhi, *p_Xlo, *p_ugh, *p_ugl, *p_fgfuh, *p_UA, *p_WD;
    cudaGetSymbolAddress((void**)&p_Xhi,   g_Xhi);
    cudaGetSymbolAddress((void**)&p_Xlo,   g_Xlo);
    cudaGetSymbolAddress((void**)&p_ugh,   g_ugh);
    cudaGetSymbolAddress((void**)&p_ugl,   g_ugl);
    cudaGetSymbolAddress((void**)&p_fgfuh, g_fgfuh);
    cudaGetSymbolAddress((void**)&p_UA,    g_UA);
    cudaGetSymbolAddress((void**)&p_WD,    g_WD);

    const dim3 blk(256);
    const size_t MH  = (size_t)M_TOK * H_DIM;
    const size_t SH2 = (size_t)2 * S_DIM * H_DIM;
    const size_t FH2 = (size_t)2 * F_DIM * H_DIM;
    const size_t HF  = (size_t)H_DIM * F_DIM;

    // Conversions
    split_kernel<<<(unsigned)(MH / 1024), blk>>>(X, p_Xhi, p_Xlo);
    pack_pair_hl_kernel<<<(unsigned)(SH2 / 1024), blk>>>(upw, gw, p_ugh, p_ugl);
    pack_W_kernel<<<(H_DIM * S_DIM) / 256, blk>>>(lao, fw);
    pack_pair_hi_kernel<<<(unsigned)(FH2 / 1024), blk>>>(fg, fu, p_fgfuh);
    cvt_fd_kernel<<<(unsigned)(HF / 1024), blk>>>(fd);

    // gemm1 (fp16x3, mask-exact): X @ [up_w;gate_w]^T -> U planes of g_UA
    gemm1_u<<<dim3(2 * S_DIM / 128, M_TOK / 128), blk, K2_SMEM>>>(
        p_Xhi, p_Xlo, p_ugh, p_ugl, lp, p_UA, KW, 2 * S_DIM, H_DIM);

    // Fused gate/up GEMM + silu epilogue -> act planes of g_UA (cols 7168+)
    gemm_1t<2,256><<<dim3(2 * F_DIM / 256, M_TOK / 128), blk, K1_SMEM_256>>>(
        p_Xhi, p_fgfuh, nullptr, p_UA + KU, KW, 2 * F_DIM, H_DIM);

    // Merged GEMM: out = [U | act] @ [Wcat | fd]^T   (K = 17152)
    gemm_1t<0,128><<<dim3(H_DIM / 128, M_TOK / 128), blk, K1_SMEM_128>>>(
        p_UA, p_WD, out, nullptr, 0, H_DIM, KW);
}

// round 12
// speedup vs baseline: 7.7168x; 1.0000x over previous
#include <cuda_runtime.h>
#include <cuda_fp16.h>
#include <cstdint>

// ---------------------------------------------------------------------------
// Problem constants (B=2, T=2048, H=4096, S=1024, F=9984, G=6)
// ---------------------------------------------------------------------------
#define M_TOK 4096
#define H_DIM 4096
#define S_DIM 1024
#define F_DIM 9984
#define KU    7168              // 7*S : Taylor K
#define KW    17152             // KU + F : merged K (Taylor + down-proj)

// ---------------------------------------------------------------------------
// Device-global scratch (no allocations allowed anywhere)
// ---------------------------------------------------------------------------
__device__ __half g_Xhi  [(size_t)M_TOK * H_DIM];
__device__ __half g_Xlo  [(size_t)M_TOK * H_DIM];
__device__ __half g_ugh  [(size_t)2 * S_DIM * H_DIM];   // interleaved up_w/gate_w hi
__device__ __half g_ugl  [(size_t)2 * S_DIM * H_DIM];   // lo
__device__ __half g_fgfuh[(size_t)2 * F_DIM * H_DIM];   // interleaved fg/fu (hi only)
__device__ __half g_UA   [(size_t)M_TOK * KW];          // [U | act]  (hi only)
__device__ __half g_WD   [(size_t)H_DIM * KW];          // [Wcat | fd] (hi only)

// ---------------------------------------------------------------------------
// PTX helpers (baseline sm_103 — no tcgen05)
// ---------------------------------------------------------------------------
__device__ __forceinline__ uint32_t smem_u32(const void* p) {
    uint32_t a;
    asm("{ .reg .u64 t; cvta.to.shared.u64 t, %1; cvt.u32.u64 %0, t; }" : "=r"(a) : "l"(p));
    return a;
}
__device__ __forceinline__ void cp16(uint32_t so, const void* gp) {
    asm volatile("cp.async.cg.shared.global [%0], [%1], 16;" :: "r"(so), "l"(gp));
}
__device__ __forceinline__ void ldsm4(uint32_t& r0, uint32_t& r1, uint32_t& r2, uint32_t& r3,
                                      uint32_t addr) {
    asm volatile("ldmatrix.sync.aligned.m8n8.x4.shared.b16 {%0,%1,%2,%3}, [%4];"
                 : "=r"(r0), "=r"(r1), "=r"(r2), "=r"(r3) : "r"(addr));
}
__device__ __forceinline__ void hmma(float* c, const uint32_t* a, const uint32_t* b) {
    asm volatile(
        "mma.sync.aligned.m16n8k16.row.col.f32.f16.f16.f32 "
        "{%0,%1,%2,%3}, {%4,%5,%6,%7}, {%8,%9}, {%0,%1,%2,%3};"
        : "+f"(c[0]), "+f"(c[1]), "+f"(c[2]), "+f"(c[3])
        : "r"(a[0]), "r"(a[1]), "r"(a[2]), "r"(a[3]), "r"(b[0]), "r"(b[1]));
}
__device__ __forceinline__ void split1h(float x, __half& h, __half& l) {
    h = __float2half_rn(x);
    l = __float2half_rn(x - __half2float(h));
}

// CTA rasterization swizzle: 16 M-rows per super-block (gridDim.y % 16 == 0).
__device__ __forceinline__ void tile_swizzle(int& mb, int& nb) {
    const int bid = blockIdx.y * gridDim.x + blockIdx.x;
    const int per = gridDim.x << 4;
    const int g = bid / per;
    const int r = bid - g * per;
    mb = (g << 4) + (r & 15);
    nb = r >> 4;
}

// ===========================================================================
// K1: single-plane fp16 GEMM  C[M,N] = A[M,K] * B[N,K]^T
// CTA 128 x NT, NWARPS warps in a 2m x (NWARPS/2)n grid, warp 64 x WN,
// K-slab 64, 4-stage cp.async pipeline, one barrier per slab.
// NT==128: explicit double-buffered fragments (load kk+1 during kk's HMMAs).
// NT==256: all fragments loaded upfront per kk (register budget).
// MODE 0: store fp32 C.
// MODE 2: columns interleave (gate,up) -> act = silu(g)*u, fp16 to
//         actout[M, ldAct].
// ===========================================================================
template <int MODE, int NT, int NWARPS>
__global__ __launch_bounds__(NWARPS * 32, 1)
void gemm_1t(const __half* __restrict__ A, const __half* __restrict__ B,
             float* __restrict__ C, __half* __restrict__ actout,
             int ldAct, int N_, int K_)
{
    constexpr int NTHREADS = NWARPS * 32;
    constexpr int WN    = NT / (NWARPS / 2);   // warp n-width (64 or 32)
    constexpr int NTI   = WN / 16;             // x4-ldsm n-loads per warp
    constexpr int NACC  = WN / 8;
    constexpr int STAGE = 16384 + NT * 128;
    constexpr bool DB   = (NT == 128);

    extern __shared__ char smem[];
    const uint32_t sb = smem_u32(smem);
    const int tid  = threadIdx.x;
    const int wid  = tid >> 5;
    const int lane = tid & 31;

    int mb, nb;
    tile_swizzle(mb, nb);
    const int m0 = mb << 7;
    const int n0 = nb * NT;
    const int wm = (wid & 1) * 64;
    const int wn = (wid >> 1) * WN;

    const int NC = K_ >> 6;

    auto load_chunk = [&](int kt, int s) {
        const uint32_t st = sb + (uint32_t)s * STAGE;
        const size_t kof = (size_t)kt << 6;
#pragma unroll
        for (int i = 0; i < 1024 / NTHREADS; i++) {       // A: 1024 16B units
            int e = i * NTHREADS + tid, row = e >> 3, kb = e & 7;
            cp16(st + row * 128 + ((kb ^ (row & 7)) << 4),
                 A + (size_t)(m0 + row) * K_ + kof + kb * 8);
        }
#pragma unroll
        for (int i = 0; i < NT * 8 / NTHREADS; i++) {     // B: NT rows
            int e = i * NTHREADS + tid, row = e >> 3, kb = e & 7;
            cp16(st + 16384 + row * 128 + ((kb ^ (row & 7)) << 4),
                 B + (size_t)(n0 + row) * K_ + kof + kb * 8);
        }
    };

    load_chunk(0, 0);
    asm volatile("cp.async.commit_group;" ::: "memory");
    load_chunk(1, 1);
    asm volatile("cp.async.commit_group;" ::: "memory");
    load_chunk(2, 2);
    asm volatile("cp.async.commit_group;" ::: "memory");

    float acc[4][NACC][4];
#pragma unroll
    for (int i = 0; i < 4; i++)
#pragma unroll
        for (int j = 0; j < NACC; j++)
#pragma unroll
            for (int q = 0; q < 4; q++) acc[i][j][q] = 0.0f;

    const int a_rsel = lane & 15;
    const int a_ksel = lane >> 4;
    const int b_rsel = (lane & 7) + (((lane >> 4) & 1) << 3);
    const int b_ksel = (lane >> 3) & 1;

    for (int kt = 0; kt < NC; kt++) {
        const int s = kt & 3;
        asm volatile("cp.async.wait_group 2;" ::: "memory");
        __syncthreads();
        if (kt + 3 < NC) load_chunk(kt + 3, (kt + 3) & 3);
        asm volatile("cp.async.commit_group;" ::: "memory");

        const uint32_t stg = sb + (uint32_t)s * STAGE;

        uint32_t af[DB ? 2 : 1][4][4];
        uint32_t bf[DB ? 2 : 1][NTI][4];

        auto ldA = [&](int kk, int buf) {
            const int akb = kk * 2 + a_ksel;
#pragma unroll
            for (int mi = 0; mi < 4; mi++) {
                int row = wm + mi * 16 + a_rsel;
                ldsm4(af[buf][mi][0], af[buf][mi][1], af[buf][mi][2], af[buf][mi][3],
                      stg + row * 128 + ((akb ^ (row & 7)) << 4));
            }
        };
        auto ldB = [&](int kk, int buf) {
            const int bkb = kk * 2 + b_ksel;
#pragma unroll
            for (int nt = 0; nt < NTI; nt++) {
                int nrow = wn + nt * 16 + b_rsel;
                ldsm4(bf[buf][nt][0], bf[buf][nt][1], bf[buf][nt][2], bf[buf][nt][3],
                      stg + 16384 + nrow * 128 + ((bkb ^ (nrow & 7)) << 4));
            }
        };

        if (DB) { ldA(0, 0); ldB(0, 0); }
#pragma unroll
        for (int kk = 0; kk < 4; kk++) {
            const int cur = DB ? (kk & 1) : 0;
            if (!DB) { ldA(kk, 0); ldB(kk, 0); }
            if (DB && kk < 3) { ldA(kk + 1, cur ^ 1); ldB(kk + 1, cur ^ 1); }
#pragma unroll
            for (int nt = 0; nt < NTI; nt++)
#pragma unroll
                for (int mi = 0; mi < 4; mi++) {
                    hmma(acc[mi][2 * nt],     af[cur][mi], &bf[cur][nt][0]);
                    hmma(acc[mi][2 * nt + 1], af[cur][mi], &bf[cur][nt][2]);
                }
        }
    }

    // Epilogue
    const int erow = lane >> 2;
    const int ecol = (lane & 3) * 2;
#pragma unroll
    for (int mi = 0; mi < 4; mi++)
#pragma unroll
        for (int ni = 0; ni < NACC; ni++) {
            const int r0 = m0 + wm + mi * 16 + erow;
            if (MODE == 2) {
                const int f = ((n0 + wn) >> 1) + ni * 4 + (lane & 3);
                float g0 = acc[mi][ni][0], u0 = acc[mi][ni][1];
                float g1 = acc[mi][ni][2], u1 = acc[mi][ni][3];
                float a0 = u0 * g0 / (1.0f + __expf(-g0));
                float a1 = u1 * g1 / (1.0f + __expf(-g1));
                actout[(size_t)r0 * ldAct + f]       = __float2half_rn(a0);
                actout[(size_t)(r0 + 8) * ldAct + f] = __float2half_rn(a1);
            } else {
                float* Cp0 = C + (size_t)r0 * N_ + n0 + wn + ni * 8 + ecol;
                float* Cp1 = Cp0 + (size_t)8 * N_;
                *(float2*)Cp0 = make_float2(acc[mi][ni][0], acc[mi][ni][1]);
                *(float2*)Cp1 = make_float2(acc[mi][ni][2], acc[mi][ni][3]);
            }
        }
}

#define K1_SMEM_256 (4 * (16384 + 256 * 128))
#define K1_SMEM_128 (4 * (16384 + 128 * 128))

// ===========================================================================
// K2: fp16x3 split GEMM (mask-exact) over interleaved [up_w;gate_w].
// CTA 128x128, 8 warps (2m x 4n), warp 64x32, K-slab 64, 3-stage pipeline,
// double-buffered fragments. Epilogue emits all 7 Taylor coefficient planes
// into Uout (row stride ldU, planes at j*1024).
// ===========================================================================
#define K2_STAGE 65536
#define K2_SMEM  (3 * K2_STAGE)

__global__ __launch_bounds__(256, 1)
void gemm1_u(const __half* __restrict__ Ahi, const __half* __restrict__ Alo,
             const __half* __restrict__ Bhi, const __half* __restrict__ Blo,
             const float* __restrict__ lp, __half* __restrict__ Uout,
             int ldU, int N_, int K_)
{
    extern __shared__ char smem[];
    const uint32_t sb = smem_u32(smem);
    const int tid  = threadIdx.x;
    const int wid  = tid >> 5;
    const int lane = tid & 31;

    int mb, nb;
    tile_swizzle(mb, nb);
    const int m0 = mb << 7;
    const int n0 = nb << 7;
    const int wm = (wid >> 2) * 64;
    const int wn = (wid & 3) * 32;

    const int NC = K_ >> 6;

    auto load_chunk = [&](int kt, int s) {
        const uint32_t st = sb + (uint32_t)s * K2_STAGE;
        const size_t kof = (size_t)kt << 6;
#pragma unroll
        for (int i = 0; i < 8; i++) {
            int e = i * 256 + tid;
            int p = e >> 10, row = (e >> 3) & 127, kb = e & 7;
            const __half* src = (p ? Alo : Ahi) + (size_t)(m0 + row) * K_ + kof + kb * 8;
            cp16(st + p * 16384 + row * 128 + ((kb ^ (row & 7)) << 4), src);
        }
#pragma unroll
        for (int i = 0; i < 8; i++) {
            int e = i * 256 + tid;
            int p = e >> 10, row = (e >> 3) & 127, kb = e & 7;
            const __half* src = (p ? Blo : Bhi) + (size_t)(n0 + row) * K_ + kof + kb * 8;
            cp16(st + 32768 + p * 16384 + row * 128 + ((kb ^ (row & 7)) << 4), src);
        }
    };

    load_chunk(0, 0);
    asm volatile("cp.async.commit_group;" ::: "memory");
    load_chunk(1, 1);
    asm volatile("cp.async.commit_group;" ::: "memory");
    load_chunk(2, 2);
    asm volatile("cp.async.commit_group;" ::: "memory");

    float acc[4][4][4];
#pragma unroll
    for (int i = 0; i < 4; i++)
#pragma unroll
        for (int j = 0; j < 4; j++)
#pragma unroll
            for (int q = 0; q < 4; q++) acc[i][j][q] = 0.0f;

    const int a_rsel = lane & 15;
    const int a_ksel = lane >> 4;
    const int b_rsel = (lane & 7) + (((lane >> 4) & 1) << 3);
    const int b_ksel = (lane >> 3) & 1;

    for (int kt = 0; kt < NC; kt++) {
        const int s = kt % 3;
        asm volatile("cp.async.wait_group 2;" ::: "memory");
        __syncthreads();

        const uint32_t stA = sb + (uint32_t)s * K2_STAGE;
        const uint32_t stB = stA + 32768;

        uint32_t Ah[2][4][4], Al[2][4][4], Bh[2][2][4], Bl[2][2][4];

        auto ldfrag = [&](int kk, int buf) {
            const int akb = kk * 2 + a_ksel;
            const int bkb = kk * 2 + b_ksel;
#pragma unroll
            for (int mi = 0; mi < 4; mi++) {
                int row = wm + mi * 16 + a_rsel;
                uint32_t off = row * 128 + ((akb ^ (row & 7)) << 4);
                ldsm4(Ah[buf][mi][0], Ah[buf][mi][1], Ah[buf][mi][2], Ah[buf][mi][3],
                      stA + off);
                ldsm4(Al[buf][mi][0], Al[buf][mi][1], Al[buf][mi][2], Al[buf][mi][3],
                      stA + 16384 + off);
            }
#pragma unroll
            for (int nt = 0; nt < 2; nt++) {
                int nrow = wn + nt * 16 + b_rsel;
                uint32_t off = nrow * 128 + ((bkb ^ (nrow & 7)) << 4);
                ldsm4(Bh[buf][nt][0], Bh[buf][nt][1], Bh[buf][nt][2], Bh[buf][nt][3],
                      stB + off);
                ldsm4(Bl[buf][nt][0], Bl[buf][nt][1], Bl[buf][nt][2], Bl[buf][nt][3],
                      stB + 16384 + off);
            }
        };

        ldfrag(0, 0);
#pragma unroll
        for (int kk = 0; kk < 4; kk++) {
            const int cur = kk & 1;
            if (kk < 3) ldfrag(kk + 1, cur ^ 1);
#pragma unroll
            for (int mi = 0; mi < 4; mi++)
#pragma unroll
                for (int ni = 0; ni < 4; ni++) {
                    const int nt = ni >> 1, hf = (ni & 1) * 2;
                    hmma(acc[mi][ni], Ah[cur][mi], &Bh[cur][nt][hf]);
                    hmma(acc[mi][ni], Ah[cur][mi], &Bl[cur][nt][hf]);
                    hmma(acc[mi][ni], Al[cur][mi], &Bh[cur][nt][hf]);
                }
        }
        __syncthreads();
        if (kt + 3 < NC) load_chunk(kt + 3, s);
        asm volatile("cp.async.commit_group;" ::: "memory");
    }

    // Epilogue: (au, gp) column pairs -> 7 Taylor coefficient planes
    const int erow = lane >> 2;
#pragma unroll
    for (int mi = 0; mi < 4; mi++)
#pragma unroll
        for (int ni = 0; ni < 4; ni++) {
            const int s = ((n0 + wn) >> 1) + ni * 4 + (lane & 3);
            const float lpv = __ldg(lp + s);
#pragma unroll
            for (int rr = 0; rr < 2; rr++) {
                const int row = m0 + wm + mi * 16 + erow + rr * 8;
                const float au = acc[mi][ni][2 * rr + 0];
                const float gp = acc[mi][ni][2 * rr + 1];
                const float delta = gp - lpv;
                const float keep  = (fabsf(delta) <= 2.5f) ? 1.0f : 0.0f;
                __half* Up = Uout + (size_t)row * ldU + s;
                float p = delta;
                Up[0 * S_DIM] = __float2half_rn(au);
                Up[1 * S_DIM] = __float2half_rn(p * au);
                p *= delta; Up[2 * S_DIM] = __float2half_rn(p * (1.0f / 2.0f)   * au);
                p *= delta; Up[3 * S_DIM] = __float2half_rn(p * (1.0f / 6.0f)   * au);
                p *= delta; Up[4 * S_DIM] = __float2half_rn(p * (1.0f / 24.0f)  * au);
                p *= delta; Up[5 * S_DIM] = __float2half_rn(p * (1.0f / 120.0f) * au * keep);
                p *= delta; Up[6 * S_DIM] = __float2half_rn(p * (1.0f / 720.0f) * au * keep);
            }
        }
}

// ---------------------------------------------------------------------------
// Conversion / pack kernels
// ---------------------------------------------------------------------------
__global__ void split_kernel(const float* __restrict__ x, __half* __restrict__ hi,
                             __half* __restrict__ lo)
{
    size_t i = ((size_t)blockIdx.x * blockDim.x + threadIdx.x) * 4;
    float4 v = *(const float4*)(x + i);
    __half2 h01, h23, l01, l23;
    __half h, l;
    split1h(v.x, h, l); h01.x = h; l01.x = l;
    split1h(v.y, h, l); h01.y = h; l01.y = l;
    split1h(v.z, h, l); h23.x = h; l23.x = l;
    split1h(v.w, h, l); h23.y = h; l23.y = l;
    *(__half2*)(hi + i)     = h01;
    *(__half2*)(hi + i + 2) = h23;
    *(__half2*)(lo + i)     = l01;
    *(__half2*)(lo + i + 2) = l23;
}

// Interleave rows of two [R, 4096] matrices with hi/lo split (up_w/gate_w)
__global__ void pack_pair_hl_kernel(const float* __restrict__ even, const float* __restrict__ odd,
                                    __half* __restrict__ hi, __half* __restrict__ lo)
{
    size_t i = ((size_t)blockIdx.x * blockDim.x + threadIdx.x) * 4;
    size_t r = i >> 12;
    size_t h = i & 4095;
    const float* src = ((r & 1) ? odd : even) + ((r >> 1) << 12) + h;
    float4 v = *(const float4*)src;
    __half2 h01, h23, l01, l23;
    __half hh, ll;
    split1h(v.x, hh, ll); h01.x = hh; l01.x = ll;
    split1h(v.y, hh, ll); h01.y = hh; l01.y = ll;
    split1h(v.z, hh, ll); h23.x = hh; l23.x = ll;
    split1h(v.w, hh, ll); h23.y = hh; l23.y = ll;
    *(__half2*)(hi + i)     = h01;
    *(__half2*)(hi + i + 2) = h23;
    *(__half2*)(lo + i)     = l01;
    *(__half2*)(lo + i + 2) = l23;
}

// Interleave rows of two [R, 4096] matrices, hi only (fg/fu)
__global__ void pack_pair_hi_kernel(const float* __restrict__ even, const float* __restrict__ odd,
                                    __half* __restrict__ hi)
{
    size_t i = ((size_t)blockIdx.x * blockDim.x + threadIdx.x) * 4;
    size_t r = i >> 12;
    size_t h = i & 4095;
    const float* src = ((r & 1) ? odd : even) + ((r >> 1) << 12) + h;
    float4 v = *(const float4*)src;
    __half2 h01, h23;
    h01.x = __float2half_rn(v.x); h01.y = __float2half_rn(v.y);
    h23.x = __float2half_rn(v.z); h23.y = __float2half_rn(v.w);
    *(__half2*)(hi + i)     = h01;
    *(__half2*)(hi + i + 2) = h23;
}

// g_WD cols 0..7167: block 0 = local_approx_output, block idx+1 = fuse[:,:,idx]
__global__ void pack_W_kernel(const float* __restrict__ lao, const float* __restrict__ fuse)
{
    int i = blockIdx.x * blockDim.x + threadIdx.x;      // over H*S
    int s = i & (S_DIM - 1);
    size_t base = (size_t)(i >> 10) * KW + s;
    g_WD[base] = __float2half_rn(lao[i]);
    const float* f = fuse + (size_t)i * 6;
#pragma unroll
    for (int idx = 0; idx < 6; idx++)
        g_WD[base + (idx + 1) * S_DIM] = __float2half_rn(f[idx]);
}

// fd [H, F] -> g_WD cols 7168..17151 (row stride KW)
__global__ void cvt_fd_kernel(const float* __restrict__ fd)
{
    size_t i = ((size_t)blockIdx.x * blockDim.x + threadIdx.x) * 4;  // over H*F
    size_t h = i / F_DIM;
    size_t j = i - h * F_DIM;          // F_DIM % 4 == 0 -> no row crossing
    float4 v = *(const float4*)(fd + i);
    __half* dst = g_WD + h * KW + KU + j;
    __half2 h01, h23;
    h01.x = __float2half_rn(v.x); h01.y = __float2half_rn(v.y);
    h23.x = __float2half_rn(v.z); h23.y = __float2half_rn(v.w);
    *(__half2*)(dst)     = h01;
    *(__half2*)(dst + 2) = h23;
}

// ---------------------------------------------------------------------------
// Launch: all graph-capturable, default stream, no allocations.
// ---------------------------------------------------------------------------
extern "C" void kernel_launch(void* const* d_in, const int* in_sizes, int n_in,
                              void* d_out, int out_size)
{
    const float* X   = (const float*)d_in[0];
    const float* upw = (const float*)d_in[1];
    const float* gw  = (const float*)d_in[2];
    const float* lp  = (const float*)d_in[3];
    const float* lao = (const float*)d_in[4];
    const float* fw  = (const float*)d_in[5];
    const float* fg  = (const float*)d_in[7];
    const float* fu  = (const float*)d_in[8];
    const float* fd  = (const float*)d_in[9];
    float* out = (float*)d_out;

    cudaFuncSetAttribute(gemm_1t<0,128,4>, cudaFuncAttributeMaxDynamicSharedMemorySize, K1_SMEM_128);
    cudaFuncSetAttribute(gemm_1t<2,256,8>, cudaFuncAttributeMaxDynamicSharedMemorySize, K1_SMEM_256);
    cudaFuncSetAttribute(gemm1_u,          cudaFuncAttributeMaxDynamicSharedMemorySize, K2_SMEM);

    __half *p_Xhi, *p_Xlo, *p_ugh, *p_ugl, *p_fgfuh, *p_UA, *p_WD;
    cudaGetSymbolAddress((void**)&p_Xhi,   g_Xhi);
    cudaGetSymbolAddress((void**)&p_Xlo,   g_Xlo);
    cudaGetSymbolAddress((void**)&p_ugh,   g_ugh);
    cudaGetSymbolAddress((void**)&p_ugl,   g_ugl);
    cudaGetSymbolAddress((void**)&p_fgfuh, g_fgfuh);
    cudaGetSymbolAddress((void**)&p_UA,    g_UA);
    cudaGetSymbolAddress((void**)&p_WD,    g_WD);

    const dim3 blk(256);
    const size_t MH  = (size_t)M_TOK * H_DIM;
    const size_t SH2 = (size_t)2 * S_DIM * H_DIM;
    const size_t FH2 = (size_t)2 * F_DIM * H_DIM;
    const size_t HF  = (size_t)H_DIM * F_DIM;

    // Conversions
    split_kernel<<<(unsigned)(MH / 1024), blk>>>(X, p_Xhi, p_Xlo);
    pack_pair_hl_kernel<<<(unsigned)(SH2 / 1024), blk>>>(upw, gw, p_ugh, p_ugl);
    pack_W_kernel<<<(H_DIM * S_DIM) / 256, blk>>>(lao, fw);
    pack_pair_hi_kernel<<<(unsigned)(FH2 / 1024), blk>>>(fg, fu, p_fgfuh);
    cvt_fd_kernel<<<(unsigned)(HF / 1024), blk>>>(fd);

    // gemm1 (fp16x3, mask-exact): X @ [up_w;gate_w]^T -> U planes of g_UA
    gemm1_u<<<dim3(2 * S_DIM / 128, M_TOK / 128), blk, K2_SMEM>>>(
        p_Xhi, p_Xlo, p_ugh, p_ugl, lp, p_UA, KW, 2 * S_DIM, H_DIM);

    // Fused gate/up GEMM + silu epilogue -> act planes of g_UA (cols 7168+)
    gemm_1t<2,256,8><<<dim3(2 * F_DIM / 256, M_TOK / 128), blk, K1_SMEM_256>>>(
        p_Xhi, p_fgfuh, nullptr, p_UA + KU, KW, 2 * F_DIM, H_DIM);

    // Merged GEMM: out = [U | act] @ [Wcat | fd]^T   (K = 17152)
    // 4 warps, 64x64 warp tiles -> 128 B smem per HMMA (25% port slack).
    gemm_1t<0,128,4><<<dim3(H_DIM / 128, M_TOK / 128), dim3(128), K1_SMEM_128>>>(
        p_UA, p_WD, out, nullptr, 0, H_DIM, KW);
}

// round 13
// speedup vs baseline: 7.7232x; 1.0008x over previous
#include <cuda_runtime.h>
#include <cuda_fp16.h>
#include <cstdint>

// ---------------------------------------------------------------------------
// Problem constants (B=2, T=2048, H=4096, S=1024, F=9984, G=6)
// ---------------------------------------------------------------------------
#define M_TOK 4096
#define H_DIM 4096
#define S_DIM 1024
#define F_DIM 9984
#define KU    7168              // 7*S : Taylor K
#define KW    17152             // KU + F : merged K (Taylor + down-proj)

// ---------------------------------------------------------------------------
// Device-global scratch (no allocations allowed anywhere)
// ---------------------------------------------------------------------------
__device__ __half g_Xhi  [(size_t)M_TOK * H_DIM];
__device__ __half g_Xlo  [(size_t)M_TOK * H_DIM];
__device__ __half g_ugh  [(size_t)2 * S_DIM * H_DIM];   // interleaved up_w/gate_w hi
__device__ __half g_ugl  [(size_t)2 * S_DIM * H_DIM];   // lo
__device__ __half g_fgfuh[(size_t)2 * F_DIM * H_DIM];   // interleaved fg/fu (hi only)
__device__ __half g_UA   [(size_t)M_TOK * KW];          // [U | act]  (hi only)
__device__ __half g_WD   [(size_t)H_DIM * KW];          // [Wcat | fd] (hi only)

// ---------------------------------------------------------------------------
// PTX helpers (baseline sm_103 — no tcgen05)
// ---------------------------------------------------------------------------
__device__ __forceinline__ uint32_t smem_u32(const void* p) {
    uint32_t a;
    asm("{ .reg .u64 t; cvta.to.shared.u64 t, %1; cvt.u32.u64 %0, t; }" : "=r"(a) : "l"(p));
    return a;
}
__device__ __forceinline__ void cp16(uint32_t so, const void* gp) {
    asm volatile("cp.async.cg.shared.global [%0], [%1], 16;" :: "r"(so), "l"(gp));
}
__device__ __forceinline__ void ldsm4(uint32_t& r0, uint32_t& r1, uint32_t& r2, uint32_t& r3,
                                      uint32_t addr) {
    asm volatile("ldmatrix.sync.aligned.m8n8.x4.shared.b16 {%0,%1,%2,%3}, [%4];"
                 : "=r"(r0), "=r"(r1), "=r"(r2), "=r"(r3) : "r"(addr));
}
__device__ __forceinline__ void hmma(float* c, const uint32_t* a, const uint32_t* b) {
    asm volatile(
        "mma.sync.aligned.m16n8k16.row.col.f32.f16.f16.f32 "
        "{%0,%1,%2,%3}, {%4,%5,%6,%7}, {%8,%9}, {%0,%1,%2,%3};"
        : "+f"(c[0]), "+f"(c[1]), "+f"(c[2]), "+f"(c[3])
        : "r"(a[0]), "r"(a[1]), "r"(a[2]), "r"(a[3]), "r"(b[0]), "r"(b[1]));
}
__device__ __forceinline__ void split1h(float x, __half& h, __half& l) {
    h = __float2half_rn(x);
    l = __float2half_rn(x - __half2float(h));
}

// CTA rasterization swizzle: 16 M-rows per super-block (gridDim.y % 16 == 0).
__device__ __forceinline__ void tile_swizzle(int& mb, int& nb) {
    const int bid = blockIdx.y * gridDim.x + blockIdx.x;
    const int per = gridDim.x << 4;
    const int g = bid / per;
    const int r = bid - g * per;
    mb = (g << 4) + (r & 15);
    nb = r >> 4;
}

// ===========================================================================
// K1: single-plane fp16 GEMM  C[M,N] = A[M,K] * B[N,K]^T
// CTA 128 x NT, NWARPS warps in a 2m x (NWARPS/2)n grid, warp 64 x WN,
// K-slab 64, 4-stage cp.async pipeline, one barrier per slab.
// NT==128: explicit double-buffered fragments. NT==256: upfront per kk.
// MODE 0: store fp32 C.
// MODE 2: columns interleave (gate,up) -> act = silu(g)*u, fp16 to
//         actout[M, ldAct].
// ===========================================================================
template <int MODE, int NT, int NWARPS>
__global__ __launch_bounds__(NWARPS * 32, 1)
void gemm_1t(const __half* __restrict__ A, const __half* __restrict__ B,
             float* __restrict__ C, __half* __restrict__ actout,
             int ldAct, int N_, int K_)
{
    constexpr int NTHREADS = NWARPS * 32;
    constexpr int WN    = NT / (NWARPS / 2);   // warp n-width (64 or 32)
    constexpr int NTI   = WN / 16;             // x4-ldsm n-loads per warp
    constexpr int NACC  = WN / 8;
    constexpr int STAGE = 16384 + NT * 128;
    constexpr bool DB   = (NT == 128);

    extern __shared__ char smem[];
    const uint32_t sb = smem_u32(smem);
    const int tid  = threadIdx.x;
    const int wid  = tid >> 5;
    const int lane = tid & 31;

    int mb, nb;
    tile_swizzle(mb, nb);
    const int m0 = mb << 7;
    const int n0 = nb * NT;
    const int wm = (wid & 1) * 64;
    const int wn = (wid >> 1) * WN;

    const int NC = K_ >> 6;

    auto load_chunk = [&](int kt, int s) {
        const uint32_t st = sb + (uint32_t)s * STAGE;
        const size_t kof = (size_t)kt << 6;
#pragma unroll
        for (int i = 0; i < 1024 / NTHREADS; i++) {       // A: 1024 16B units
            int e = i * NTHREADS + tid, row = e >> 3, kb = e & 7;
            cp16(st + row * 128 + ((kb ^ (row & 7)) << 4),
                 A + (size_t)(m0 + row) * K_ + kof + kb * 8);
        }
#pragma unroll
        for (int i = 0; i < NT * 8 / NTHREADS; i++) {     // B: NT rows
            int e = i * NTHREADS + tid, row = e >> 3, kb = e & 7;
            cp16(st + 16384 + row * 128 + ((kb ^ (row & 7)) << 4),
                 B + (size_t)(n0 + row) * K_ + kof + kb * 8);
        }
    };

    load_chunk(0, 0);
    asm volatile("cp.async.commit_group;" ::: "memory");
    load_chunk(1, 1);
    asm volatile("cp.async.commit_group;" ::: "memory");
    load_chunk(2, 2);
    asm volatile("cp.async.commit_group;" ::: "memory");

    float acc[4][NACC][4];
#pragma unroll
    for (int i = 0; i < 4; i++)
#pragma unroll
        for (int j = 0; j < NACC; j++)
#pragma unroll
            for (int q = 0; q < 4; q++) acc[i][j][q] = 0.0f;

    const int a_rsel = lane & 15;
    const int a_ksel = lane >> 4;
    const int b_rsel = (lane & 7) + (((lane >> 4) & 1) << 3);
    const int b_ksel = (lane >> 3) & 1;

    for (int kt = 0; kt < NC; kt++) {
        const int s = kt & 3;
        asm volatile("cp.async.wait_group 2;" ::: "memory");
        __syncthreads();
        if (kt + 3 < NC) load_chunk(kt + 3, (kt + 3) & 3);
        asm volatile("cp.async.commit_group;" ::: "memory");

        const uint32_t stg = sb + (uint32_t)s * STAGE;

        uint32_t af[DB ? 2 : 1][4][4];
        uint32_t bf[DB ? 2 : 1][NTI][4];

        auto ldA = [&](int kk, int buf) {
            const int akb = kk * 2 + a_ksel;
#pragma unroll
            for (int mi = 0; mi < 4; mi++) {
                int row = wm + mi * 16 + a_rsel;
                ldsm4(af[buf][mi][0], af[buf][mi][1], af[buf][mi][2], af[buf][mi][3],
                      stg + row * 128 + ((akb ^ (row & 7)) << 4));
            }
        };
        auto ldB = [&](int kk, int buf) {
            const int bkb = kk * 2 + b_ksel;
#pragma unroll
            for (int nt = 0; nt < NTI; nt++) {
                int nrow = wn + nt * 16 + b_rsel;
                ldsm4(bf[buf][nt][0], bf[buf][nt][1], bf[buf][nt][2], bf[buf][nt][3],
                      stg + 16384 + nrow * 128 + ((bkb ^ (nrow & 7)) << 4));
            }
        };

        if (DB) { ldA(0, 0); ldB(0, 0); }
#pragma unroll
        for (int kk = 0; kk < 4; kk++) {
            const int cur = DB ? (kk & 1) : 0;
            if (!DB) { ldA(kk, 0); ldB(kk, 0); }
            if (DB && kk < 3) { ldA(kk + 1, cur ^ 1); ldB(kk + 1, cur ^ 1); }
#pragma unroll
            for (int nt = 0; nt < NTI; nt++)
#pragma unroll
                for (int mi = 0; mi < 4; mi++) {
                    hmma(acc[mi][2 * nt],     af[cur][mi], &bf[cur][nt][0]);
                    hmma(acc[mi][2 * nt + 1], af[cur][mi], &bf[cur][nt][2]);
                }
        }
    }

    // Epilogue
    const int erow = lane >> 2;
    const int ecol = (lane & 3) * 2;
#pragma unroll
    for (int mi = 0; mi < 4; mi++)
#pragma unroll
        for (int ni = 0; ni < NACC; ni++) {
            const int r0 = m0 + wm + mi * 16 + erow;
            if (MODE == 2) {
                const int f = ((n0 + wn) >> 1) + ni * 4 + (lane & 3);
                float g0 = acc[mi][ni][0], u0 = acc[mi][ni][1];
                float g1 = acc[mi][ni][2], u1 = acc[mi][ni][3];
                float a0 = u0 * g0 / (1.0f + __expf(-g0));
                float a1 = u1 * g1 / (1.0f + __expf(-g1));
                actout[(size_t)r0 * ldAct + f]       = __float2half_rn(a0);
                actout[(size_t)(r0 + 8) * ldAct + f] = __float2half_rn(a1);
            } else {
                float* Cp0 = C + (size_t)r0 * N_ + n0 + wn + ni * 8 + ecol;
                float* Cp1 = Cp0 + (size_t)8 * N_;
                *(float2*)Cp0 = make_float2(acc[mi][ni][0], acc[mi][ni][1]);
                *(float2*)Cp1 = make_float2(acc[mi][ni][2], acc[mi][ni][3]);
            }
        }
}

#define K1_SMEM_256 (4 * (16384 + 256 * 128))
#define K1_SMEM_128 (4 * (16384 + 128 * 128))

// ===========================================================================
// K2: fp16x3 split GEMM (mask-exact) over interleaved [up_w;gate_w].
// CTA 128x128, 8 warps (2m x 4n), warp 64x32, K-slab 64, 3-stage pipeline,
// double-buffered fragments. Epilogue emits all 7 Taylor coefficient planes
// into Uout (row stride ldU, planes at j*1024).
// ===========================================================================
#define K2_STAGE 65536
#define K2_SMEM  (3 * K2_STAGE)

__global__ __launch_bounds__(256, 1)
void gemm1_u(const __half* __restrict__ Ahi, const __half* __restrict__ Alo,
             const __half* __restrict__ Bhi, const __half* __restrict__ Blo,
             const float* __restrict__ lp, __half* __restrict__ Uout,
             int ldU, int N_, int K_)
{
    extern __shared__ char smem[];
    const uint32_t sb = smem_u32(smem);
    const int tid  = threadIdx.x;
    const int wid  = tid >> 5;
    const int lane = tid & 31;

    int mb, nb;
    tile_swizzle(mb, nb);
    const int m0 = mb << 7;
    const int n0 = nb << 7;
    const int wm = (wid >> 2) * 64;
    const int wn = (wid & 3) * 32;

    const int NC = K_ >> 6;

    auto load_chunk = [&](int kt, int s) {
        const uint32_t st = sb + (uint32_t)s * K2_STAGE;
        const size_t kof = (size_t)kt << 6;
#pragma unroll
        for (int i = 0; i < 8; i++) {
            int e = i * 256 + tid;
            int p = e >> 10, row = (e >> 3) & 127, kb = e & 7;
            const __half* src = (p ? Alo : Ahi) + (size_t)(m0 + row) * K_ + kof + kb * 8;
            cp16(st + p * 16384 + row * 128 + ((kb ^ (row & 7)) << 4), src);
        }
#pragma unroll
        for (int i = 0; i < 8; i++) {
            int e = i * 256 + tid;
            int p = e >> 10, row = (e >> 3) & 127, kb = e & 7;
            const __half* src = (p ? Blo : Bhi) + (size_t)(n0 + row) * K_ + kof + kb * 8;
            cp16(st + 32768 + p * 16384 + row * 128 + ((kb ^ (row & 7)) << 4), src);
        }
    };

    load_chunk(0, 0);
    asm volatile("cp.async.commit_group;" ::: "memory");
    load_chunk(1, 1);
    asm volatile("cp.async.commit_group;" ::: "memory");
    load_chunk(2, 2);
    asm volatile("cp.async.commit_group;" ::: "memory");

    float acc[4][4][4];
#pragma unroll
    for (int i = 0; i < 4; i++)
#pragma unroll
        for (int j = 0; j < 4; j++)
#pragma unroll
            for (int q = 0; q < 4; q++) acc[i][j][q] = 0.0f;

    const int a_rsel = lane & 15;
    const int a_ksel = lane >> 4;
    const int b_rsel = (lane & 7) + (((lane >> 4) & 1) << 3);
    const int b_ksel = (lane >> 3) & 1;

    for (int kt = 0; kt < NC; kt++) {
        const int s = kt % 3;
        asm volatile("cp.async.wait_group 2;" ::: "memory");
        __syncthreads();

        const uint32_t stA = sb + (uint32_t)s * K2_STAGE;
        const uint32_t stB = stA + 32768;

        uint32_t Ah[2][4][4], Al[2][4][4], Bh[2][2][4], Bl[2][2][4];

        auto ldfrag = [&](int kk, int buf) {
            const int akb = kk * 2 + a_ksel;
            const int bkb = kk * 2 + b_ksel;
#pragma unroll
            for (int mi = 0; mi < 4; mi++) {
                int row = wm + mi * 16 + a_rsel;
                uint32_t off = row * 128 + ((akb ^ (row & 7)) << 4);
                ldsm4(Ah[buf][mi][0], Ah[buf][mi][1], Ah[buf][mi][2], Ah[buf][mi][3],
                      stA + off);
                ldsm4(Al[buf][mi][0], Al[buf][mi][1], Al[buf][mi][2], Al[buf][mi][3],
                      stA + 16384 + off);
            }
#pragma unroll
            for (int nt = 0; nt < 2; nt++) {
                int nrow = wn + nt * 16 + b_rsel;
                uint32_t off = nrow * 128 + ((bkb ^ (nrow & 7)) << 4);
                ldsm4(Bh[buf][nt][0], Bh[buf][nt][1], Bh[buf][nt][2], Bh[buf][nt][3],
                      stB + off);
                ldsm4(Bl[buf][nt][0], Bl[buf][nt][1], Bl[buf][nt][2], Bl[buf][nt][3],
                      stB + 16384 + off);
            }
        };

        ldfrag(0, 0);
#pragma unroll
        for (int kk = 0; kk < 4; kk++) {
            const int cur = kk & 1;
            if (kk < 3) ldfrag(kk + 1, cur ^ 1);
#pragma unroll
            for (int mi = 0; mi < 4; mi++)
#pragma unroll
                for (int ni = 0; ni < 4; ni++) {
                    const int nt = ni >> 1, hf = (ni & 1) * 2;
                    hmma(acc[mi][ni], Ah[cur][mi], &Bh[cur][nt][hf]);
                    hmma(acc[mi][ni], Ah[cur][mi], &Bl[cur][nt][hf]);
                    hmma(acc[mi][ni], Al[cur][mi], &Bh[cur][nt][hf]);
                }
        }
        __syncthreads();
        if (kt + 3 < NC) load_chunk(kt + 3, s);
        asm volatile("cp.async.commit_group;" ::: "memory");
    }

    // Epilogue: (au, gp) column pairs -> 7 Taylor coefficient planes
    const int erow = lane >> 2;
#pragma unroll
    for (int mi = 0; mi < 4; mi++)
#pragma unroll
        for (int ni = 0; ni < 4; ni++) {
            const int s = ((n0 + wn) >> 1) + ni * 4 + (lane & 3);
            const float lpv = __ldg(lp + s);
#pragma unroll
            for (int rr = 0; rr < 2; rr++) {
                const int row = m0 + wm + mi * 16 + erow + rr * 8;
                const float au = acc[mi][ni][2 * rr + 0];
                const float gp = acc[mi][ni][2 * rr + 1];
                const float delta = gp - lpv;
                const float keep  = (fabsf(delta) <= 2.5f) ? 1.0f : 0.0f;
                __half* Up = Uout + (size_t)row * ldU + s;
                float p = delta;
                Up[0 * S_DIM] = __float2half_rn(au);
                Up[1 * S_DIM] = __float2half_rn(p * au);
                p *= delta; Up[2 * S_DIM] = __float2half_rn(p * (1.0f / 2.0f)   * au);
                p *= delta; Up[3 * S_DIM] = __float2half_rn(p * (1.0f / 6.0f)   * au);
                p *= delta; Up[4 * S_DIM] = __float2half_rn(p * (1.0f / 24.0f)  * au);
                p *= delta; Up[5 * S_DIM] = __float2half_rn(p * (1.0f / 120.0f) * au * keep);
                p *= delta; Up[6 * S_DIM] = __float2half_rn(p * (1.0f / 720.0f) * au * keep);
            }
        }
}

// ---------------------------------------------------------------------------
// Conversion / pack kernels
// ---------------------------------------------------------------------------
__global__ void split_kernel(const float* __restrict__ x, __half* __restrict__ hi,
                             __half* __restrict__ lo)
{
    size_t i = ((size_t)blockIdx.x * blockDim.x + threadIdx.x) * 4;
    float4 v = *(const float4*)(x + i);
    __half2 h01, h23, l01, l23;
    __half h, l;
    split1h(v.x, h, l); h01.x = h; l01.x = l;
    split1h(v.y, h, l); h01.y = h; l01.y = l;
    split1h(v.z, h, l); h23.x = h; l23.x = l;
    split1h(v.w, h, l); h23.y = h; l23.y = l;
    *(__half2*)(hi + i)     = h01;
    *(__half2*)(hi + i + 2) = h23;
    *(__half2*)(lo + i)     = l01;
    *(__half2*)(lo + i + 2) = l23;
}

// Interleave rows of two [R, 4096] matrices with hi/lo split (up_w/gate_w)
__global__ void pack_pair_hl_kernel(const float* __restrict__ even, const float* __restrict__ odd,
                                    __half* __restrict__ hi, __half* __restrict__ lo)
{
    size_t i = ((size_t)blockIdx.x * blockDim.x + threadIdx.x) * 4;
    size_t r = i >> 12;
    size_t h = i & 4095;
    const float* src = ((r & 1) ? odd : even) + ((r >> 1) << 12) + h;
    float4 v = *(const float4*)src;
    __half2 h01, h23, l01, l23;
    __half hh, ll;
    split1h(v.x, hh, ll); h01.x = hh; l01.x = ll;
    split1h(v.y, hh, ll); h01.y = hh; l01.y = ll;
    split1h(v.z, hh, ll); h23.x = hh; l23.x = ll;
    split1h(v.w, hh, ll); h23.y = hh; l23.y = ll;
    *(__half2*)(hi + i)     = h01;
    *(__half2*)(hi + i + 2) = h23;
    *(__half2*)(lo + i)     = l01;
    *(__half2*)(lo + i + 2) = l23;
}

// Interleave rows of two [R, 4096] matrices, hi only (fg/fu)
__global__ void pack_pair_hi_kernel(const float* __restrict__ even, const float* __restrict__ odd,
                                    __half* __restrict__ hi)
{
    size_t i = ((size_t)blockIdx.x * blockDim.x + threadIdx.x) * 4;
    size_t r = i >> 12;
    size_t h = i & 4095;
    const float* src = ((r & 1) ? odd : even) + ((r >> 1) << 12) + h;
    float4 v = *(const float4*)src;
    __half2 h01, h23;
    h01.x = __float2half_rn(v.x); h01.y = __float2half_rn(v.y);
    h23.x = __float2half_rn(v.z); h23.y = __float2half_rn(v.w);
    *(__half2*)(hi + i)     = h01;
    *(__half2*)(hi + i + 2) = h23;
}

// g_WD cols 0..7167: block 0 = local_approx_output, block idx+1 = fuse[:,:,idx]
__global__ void pack_W_kernel(const float* __restrict__ lao, const float* __restrict__ fuse)
{
    int i = blockIdx.x * blockDim.x + threadIdx.x;      // over H*S
    int s = i & (S_DIM - 1);
    size_t base = (size_t)(i >> 10) * KW + s;
    g_WD[base] = __float2half_rn(lao[i]);
    const float* f = fuse + (size_t)i * 6;
#pragma unroll
    for (int idx = 0; idx < 6; idx++)
        g_WD[base + (idx + 1) * S_DIM] = __float2half_rn(f[idx]);
}

// fd [H, F] -> g_WD cols 7168..17151 (row stride KW)
__global__ void cvt_fd_kernel(const float* __restrict__ fd)
{
    size_t i = ((size_t)blockIdx.x * blockDim.x + threadIdx.x) * 4;  // over H*F
    size_t h = i / F_DIM;
    size_t j = i - h * F_DIM;          // F_DIM % 4 == 0 -> no row crossing
    float4 v = *(const float4*)(fd + i);
    __half* dst = g_WD + h * KW + KU + j;
    __half2 h01, h23;
    h01.x = __float2half_rn(v.x); h01.y = __float2half_rn(v.y);
    h23.x = __float2half_rn(v.z); h23.y = __float2half_rn(v.w);
    *(__half2*)(dst)     = h01;
    *(__half2*)(dst + 2) = h23;
}

// ---------------------------------------------------------------------------
// Launch: graph-capturable, two-stream capture-fork to hide the B-side
// weight conversions under gemm1_u. No allocations, no syncs.
// ---------------------------------------------------------------------------
extern "C" void kernel_launch(void* const* d_in, const int* in_sizes, int n_in,
                              void* d_out, int out_size)
{
    const float* X   = (const float*)d_in[0];
    const float* upw = (const float*)d_in[1];
    const float* gw  = (const float*)d_in[2];
    const float* lp  = (const float*)d_in[3];
    const float* lao = (const float*)d_in[4];
    const float* fw  = (const float*)d_in[5];
    const float* fg  = (const float*)d_in[7];
    const float* fu  = (const float*)d_in[8];
    const float* fd  = (const float*)d_in[9];
    float* out = (float*)d_out;

    cudaFuncSetAttribute(gemm_1t<0,128,4>, cudaFuncAttributeMaxDynamicSharedMemorySize, K1_SMEM_128);
    cudaFuncSetAttribute(gemm_1t<2,256,8>, cudaFuncAttributeMaxDynamicSharedMemorySize, K1_SMEM_256);
    cudaFuncSetAttribute(gemm1_u,          cudaFuncAttributeMaxDynamicSharedMemorySize, K2_SMEM);

    __half *p_Xhi, *p_Xlo, *p_ugh, *p_ugl, *p_fgfuh, *p_UA, *p_WD;
    cudaGetSymbolAddress((void**)&p_Xhi,   g_Xhi);
    cudaGetSymbolAddress((void**)&p_Xlo,   g_Xlo);
    cudaGetSymbolAddress((void**)&p_ugh,   g_ugh);
    cudaGetSymbolAddress((void**)&p_ugl,   g_ugl);
    cudaGetSymbolAddress((void**)&p_fgfuh, g_fgfuh);
    cudaGetSymbolAddress((void**)&p_UA,    g_UA);
    cudaGetSymbolAddress((void**)&p_WD,    g_WD);

    const dim3 blk(256);
    const size_t MH  = (size_t)M_TOK * H_DIM;
    const size_t SH2 = (size_t)2 * S_DIM * H_DIM;
    const size_t FH2 = (size_t)2 * F_DIM * H_DIM;
    const size_t HF  = (size_t)H_DIM * F_DIM;

    // Side stream + fork/join events (created fresh each call; intentionally
    // not destroyed — destroying capture-participating handles mid-capture is
    // illegal, and the handle count is bounded by the harness's few calls).
    cudaStream_t sB;
    cudaStreamCreateWithFlags(&sB, cudaStreamNonBlocking);
    cudaEvent_t eFork, eJoinB1;
    cudaEventCreateWithFlags(&eFork,   cudaEventDisableTiming);
    cudaEventCreateWithFlags(&eJoinB1, cudaEventDisableTiming);

    // Fork: side stream inherits the capture dependency frontier.
    cudaEventRecord(eFork, 0);
    cudaStreamWaitEvent(sB, eFork, 0);

    // ---- Stream B: weight conversions for gate/up and merged GEMM ----
    pack_pair_hi_kernel<<<(unsigned)(FH2 / 1024), blk, 0, sB>>>(fg, fu, p_fgfuh);
    pack_W_kernel<<<(H_DIM * S_DIM) / 256, blk, 0, sB>>>(lao, fw);
    cvt_fd_kernel<<<(unsigned)(HF / 1024), blk, 0, sB>>>(fd);
    cudaEventRecord(eJoinB1, sB);

    // ---- Default stream: A-side conversions + gemm1_u ----
    split_kernel<<<(unsigned)(MH / 1024), blk>>>(X, p_Xhi, p_Xlo);
    pack_pair_hl_kernel<<<(unsigned)(SH2 / 1024), blk>>>(upw, gw, p_ugh, p_ugl);

    // gemm1 (fp16x3, mask-exact): X @ [up_w;gate_w]^T -> U planes of g_UA
    // Runs concurrently with stream B's DRAM-bound conversions.
    gemm1_u<<<dim3(2 * S_DIM / 128, M_TOK / 128), blk, K2_SMEM>>>(
        p_Xhi, p_Xlo, p_ugh, p_ugl, lp, p_UA, KW, 2 * S_DIM, H_DIM);

    // Join: all B-side conversions must be done before the remaining GEMMs.
    cudaStreamWaitEvent(0, eJoinB1, 0);

    // Fused gate/up GEMM + silu epilogue -> act planes of g_UA (cols 7168+)
    gemm_1t<2,256,8><<<dim3(2 * F_DIM / 256, M_TOK / 128), blk, K1_SMEM_256>>>(
        p_Xhi, p_fgfuh, nullptr, p_UA + KU, KW, 2 * F_DIM, H_DIM);

    // Merged GEMM: out = [U | act] @ [Wcat | fd]^T   (K = 17152)
    gemm_1t<0,128,4><<<dim3(H_DIM / 128, M_TOK / 128), dim3(128), K1_SMEM_128>>>(
        p_UA, p_WD, out, nullptr, 0, H_DIM, KW);
}

// round 16
// speedup vs baseline: 7.7987x; 1.0098x over previous
#include <cuda_runtime.h>
#include <cuda_fp16.h>
#include <cstdint>

// ---------------------------------------------------------------------------
// Problem constants (B=2, T=2048, H=4096, S=1024, F=9984, G=6)
// ---------------------------------------------------------------------------
#define M_TOK 4096
#define H_DIM 4096
#define S_DIM 1024
#define F_DIM 9984
#define KU    7168              // 7*S : Taylor K
#define KW    17152             // KU + F : merged K (Taylor + down-proj)

// ---------------------------------------------------------------------------
// Device-global scratch (no allocations allowed anywhere)
// ---------------------------------------------------------------------------
__device__ __half g_Xhi  [(size_t)M_TOK * H_DIM];
__device__ __half g_Xlo  [(size_t)M_TOK * H_DIM];
__device__ __half g_ugh  [(size_t)2 * S_DIM * H_DIM];   // interleaved up_w/gate_w hi
__device__ __half g_ugl  [(size_t)2 * S_DIM * H_DIM];   // lo
__device__ __half g_fgfuh[(size_t)2 * F_DIM * H_DIM];   // interleaved fg/fu (hi only)
__device__ __half g_UA   [(size_t)M_TOK * KW];          // [U | act]  (hi only)
__device__ __half g_WD   [(size_t)H_DIM * KW];          // [Wcat | fd] (hi only)

// ---------------------------------------------------------------------------
// PTX helpers (baseline sm_103 — no tcgen05)
// ---------------------------------------------------------------------------
__device__ __forceinline__ uint32_t smem_u32(const void* p) {
    uint32_t a;
    asm("{ .reg .u64 t; cvta.to.shared.u64 t, %1; cvt.u32.u64 %0, t; }" : "=r"(a) : "l"(p));
    return a;
}
__device__ __forceinline__ void cp16(uint32_t so, const void* gp) {
    asm volatile("cp.async.cg.shared.global [%0], [%1], 16;" :: "r"(so), "l"(gp));
}
__device__ __forceinline__ void ldsm4(uint32_t& r0, uint32_t& r1, uint32_t& r2, uint32_t& r3,
                                      uint32_t addr) {
    asm volatile("ldmatrix.sync.aligned.m8n8.x4.shared.b16 {%0,%1,%2,%3}, [%4];"
                 : "=r"(r0), "=r"(r1), "=r"(r2), "=r"(r3) : "r"(addr));
}
__device__ __forceinline__ void hmma(float* c, const uint32_t* a, const uint32_t* b) {
    asm volatile(
        "mma.sync.aligned.m16n8k16.row.col.f32.f16.f16.f32 "
        "{%0,%1,%2,%3}, {%4,%5,%6,%7}, {%8,%9}, {%0,%1,%2,%3};"
        : "+f"(c[0]), "+f"(c[1]), "+f"(c[2]), "+f"(c[3])
        : "r"(a[0]), "r"(a[1]), "r"(a[2]), "r"(a[3]), "r"(b[0]), "r"(b[1]));
}
__device__ __forceinline__ void split1h(float x, __half& h, __half& l) {
    h = __float2half_rn(x);
    l = __float2half_rn(x - __half2float(h));
}

// CTA rasterization swizzle: 16 M-rows per super-block (gridDim.y % 16 == 0).
__device__ __forceinline__ void tile_swizzle(int& mb, int& nb) {
    const int bid = blockIdx.y * gridDim.x + blockIdx.x;
    const int per = gridDim.x << 4;
    const int g = bid / per;
    const int r = bid - g * per;
    mb = (g << 4) + (r & 15);
    nb = r >> 4;
}

// ===========================================================================
// K1: single-plane fp16 GEMM  C[M,N] = A[M,K] * B[N,K]^T
// CTA 128 x NT, NWARPS warps in a 2m x (NWARPS/2)n grid, warp 64 x WN,
// K-slab 64, 4-stage cp.async pipeline, one barrier per slab.
// NT==128: explicit double-buffered fragments. NT==256: upfront per kk.
// MODE 0: store fp32 C.
// MODE 2: columns interleave (gate,up) -> act = silu(g)*u, fp16 to
//         actout[M, ldAct].
// ===========================================================================
template <int MODE, int NT, int NWARPS>
__global__ __launch_bounds__(NWARPS * 32, 1)
void gemm_1t(const __half* __restrict__ A, const __half* __restrict__ B,
             float* __restrict__ C, __half* __restrict__ actout,
             int ldAct, int N_, int K_)
{
    constexpr int NTHREADS = NWARPS * 32;
    constexpr int WN    = NT / (NWARPS / 2);   // warp n-width (64 or 32)
    constexpr int NTI   = WN / 16;             // x4-ldsm n-loads per warp
    constexpr int NACC  = WN / 8;
    constexpr int STAGE = 16384 + NT * 128;
    constexpr bool DB   = (NT == 128);

    extern __shared__ char smem[];
    const uint32_t sb = smem_u32(smem);
    const int tid  = threadIdx.x;
    const int wid  = tid >> 5;
    const int lane = tid & 31;

    int mb, nb;
    tile_swizzle(mb, nb);
    const int m0 = mb << 7;
    const int n0 = nb * NT;
    const int wm = (wid & 1) * 64;
    const int wn = (wid >> 1) * WN;

    const int NC = K_ >> 6;

    auto load_chunk = [&](int kt, int s) {
        const uint32_t st = sb + (uint32_t)s * STAGE;
        const size_t kof = (size_t)kt << 6;
#pragma unroll
        for (int i = 0; i < 1024 / NTHREADS; i++) {       // A: 1024 16B units
            int e = i * NTHREADS + tid, row = e >> 3, kb = e & 7;
            cp16(st + row * 128 + ((kb ^ (row & 7)) << 4),
                 A + (size_t)(m0 + row) * K_ + kof + kb * 8);
        }
#pragma unroll
        for (int i = 0; i < NT * 8 / NTHREADS; i++) {     // B: NT rows
            int e = i * NTHREADS + tid, row = e >> 3, kb = e & 7;
            cp16(st + 16384 + row * 128 + ((kb ^ (row & 7)) << 4),
                 B + (size_t)(n0 + row) * K_ + kof + kb * 8);
        }
    };

    load_chunk(0, 0);
    asm volatile("cp.async.commit_group;" ::: "memory");
    load_chunk(1, 1);
    asm volatile("cp.async.commit_group;" ::: "memory");
    load_chunk(2, 2);
    asm volatile("cp.async.commit_group;" ::: "memory");

    float acc[4][NACC][4];
#pragma unroll
    for (int i = 0; i < 4; i++)
#pragma unroll
        for (int j = 0; j < NACC; j++)
#pragma unroll
            for (int q = 0; q < 4; q++) acc[i][j][q] = 0.0f;

    const int a_rsel = lane & 15;
    const int a_ksel = lane >> 4;
    const int b_rsel = (lane & 7) + (((lane >> 4) & 1) << 3);
    const int b_ksel = (lane >> 3) & 1;

    for (int kt = 0; kt < NC; kt++) {
        const int s = kt & 3;
        asm volatile("cp.async.wait_group 2;" ::: "memory");
        __syncthreads();
        if (kt + 3 < NC) load_chunk(kt + 3, (kt + 3) & 3);
        asm volatile("cp.async.commit_group;" ::: "memory");

        const uint32_t stg = sb + (uint32_t)s * STAGE;

        uint32_t af[DB ? 2 : 1][4][4];
        uint32_t bf[DB ? 2 : 1][NTI][4];

        auto ldA = [&](int kk, int buf) {
            const int akb = kk * 2 + a_ksel;
#pragma unroll
            for (int mi = 0; mi < 4; mi++) {
                int row = wm + mi * 16 + a_rsel;
                ldsm4(af[buf][mi][0], af[buf][mi][1], af[buf][mi][2], af[buf][mi][3],
                      stg + row * 128 + ((akb ^ (row & 7)) << 4));
            }
        };
        auto ldB = [&](int kk, int buf) {
            const int bkb = kk * 2 + b_ksel;
#pragma unroll
            for (int nt = 0; nt < NTI; nt++) {
                int nrow = wn + nt * 16 + b_rsel;
                ldsm4(bf[buf][nt][0], bf[buf][nt][1], bf[buf][nt][2], bf[buf][nt][3],
                      stg + 16384 + nrow * 128 + ((bkb ^ (nrow & 7)) << 4));
            }
        };

        if (DB) { ldA(0, 0); ldB(0, 0); }
#pragma unroll
        for (int kk = 0; kk < 4; kk++) {
            const int cur = DB ? (kk & 1) : 0;
            if (!DB) { ldA(kk, 0); ldB(kk, 0); }
            if (DB && kk < 3) { ldA(kk + 1, cur ^ 1); ldB(kk + 1, cur ^ 1); }
#pragma unroll
            for (int nt = 0; nt < NTI; nt++)
#pragma unroll
                for (int mi = 0; mi < 4; mi++) {
                    hmma(acc[mi][2 * nt],     af[cur][mi], &bf[cur][nt][0]);
                    hmma(acc[mi][2 * nt + 1], af[cur][mi], &bf[cur][nt][2]);
                }
        }
    }

    // Epilogue
    const int erow = lane >> 2;
    const int ecol = (lane & 3) * 2;
#pragma unroll
    for (int mi = 0; mi < 4; mi++)
#pragma unroll
        for (int ni = 0; ni < NACC; ni++) {
            const int r0 = m0 + wm + mi * 16 + erow;
            if (MODE == 2) {
                const int f = ((n0 + wn) >> 1) + ni * 4 + (lane & 3);
                float g0 = acc[mi][ni][0], u0 = acc[mi][ni][1];
                float g1 = acc[mi][ni][2], u1 = acc[mi][ni][3];
                float a0 = u0 * g0 / (1.0f + __expf(-g0));
                float a1 = u1 * g1 / (1.0f + __expf(-g1));
                actout[(size_t)r0 * ldAct + f]       = __float2half_rn(a0);
                actout[(size_t)(r0 + 8) * ldAct + f] = __float2half_rn(a1);
            } else {
                float* Cp0 = C + (size_t)r0 * N_ + n0 + wn + ni * 8 + ecol;
                float* Cp1 = Cp0 + (size_t)8 * N_;
                *(float2*)Cp0 = make_float2(acc[mi][ni][0], acc[mi][ni][1]);
                *(float2*)Cp1 = make_float2(acc[mi][ni][2], acc[mi][ni][3]);
            }
        }
}

#define K1_SMEM_256 (4 * (16384 + 256 * 128))
#define K1_SMEM_128 (4 * (16384 + 128 * 128))

// ===========================================================================
// K2: fp16x3 split GEMM (mask-exact) over interleaved [up_w;gate_w].
// CTA 64x128, 4 warps (1m x 4n), warp 64x32, 128 threads, K-slab 64,
// 3-stage pipeline, single-buffered fragments (low regs -> conversion
// kernels can co-reside on the same SMs). Grid 1024 CTAs (6.9 waves).
// Epilogue emits all 7 Taylor coefficient planes into Uout (row stride ldU).
// ===========================================================================
#define K2_STAGE 49152          // Ahi 8K | Alo 8K | Bhi 16K | Blo 16K
#define K2_SMEM  (3 * K2_STAGE)

__global__ __launch_bounds__(128, 1)
void gemm1_u(const __half* __restrict__ Ahi, const __half* __restrict__ Alo,
             const __half* __restrict__ Bhi, const __half* __restrict__ Blo,
             const float* __restrict__ lp, __half* __restrict__ Uout,
             int ldU, int N_, int K_)
{
    extern __shared__ char smem[];
    const uint32_t sb = smem_u32(smem);
    const int tid  = threadIdx.x;
    const int wid  = tid >> 5;
    const int lane = tid & 31;

    int mb, nb;
    tile_swizzle(mb, nb);
    const int m0 = mb << 6;            // 64 M-rows per CTA
    const int n0 = nb << 7;            // 128 N-cols per CTA
    const int wn = wid * 32;

    const int NC = K_ >> 6;

    auto load_chunk = [&](int kt, int s) {
        const uint32_t st = sb + (uint32_t)s * K2_STAGE;
        const size_t kof = (size_t)kt << 6;
#pragma unroll
        for (int i = 0; i < 8; i++) {                    // A: 64 rows x 2 planes
            int e = i * 128 + tid;
            int p = e >> 9, row = (e >> 3) & 63, kb = e & 7;
            const __half* src = (p ? Alo : Ahi) + (size_t)(m0 + row) * K_ + kof + kb * 8;
            cp16(st + p * 8192 + row * 128 + ((kb ^ (row & 7)) << 4), src);
        }
#pragma unroll
        for (int i = 0; i < 16; i++) {                   // B: 128 rows x 2 planes
            int e = i * 128 + tid;
            int p = e >> 10, row = (e >> 3) & 127, kb = e & 7;
            const __half* src = (p ? Blo : Bhi) + (size_t)(n0 + row) * K_ + kof + kb * 8;
            cp16(st + 16384 + p * 16384 + row * 128 + ((kb ^ (row & 7)) << 4), src);
        }
    };

    load_chunk(0, 0);
    asm volatile("cp.async.commit_group;" ::: "memory");
    load_chunk(1, 1);
    asm volatile("cp.async.commit_group;" ::: "memory");
    load_chunk(2, 2);
    asm volatile("cp.async.commit_group;" ::: "memory");

    float acc[4][4][4];
#pragma unroll
    for (int i = 0; i < 4; i++)
#pragma unroll
        for (int j = 0; j < 4; j++)
#pragma unroll
            for (int q = 0; q < 4; q++) acc[i][j][q] = 0.0f;

    const int a_rsel = lane & 15;
    const int a_ksel = lane >> 4;
    const int b_rsel = (lane & 7) + (((lane >> 4) & 1) << 3);
    const int b_ksel = (lane >> 3) & 1;

    for (int kt = 0; kt < NC; kt++) {
        const int s = kt % 3;
        asm volatile("cp.async.wait_group 2;" ::: "memory");
        __syncthreads();

        const uint32_t stA = sb + (uint32_t)s * K2_STAGE;
        const uint32_t stB = stA + 16384;

#pragma unroll
        for (int kk = 0; kk < 4; kk++) {
            uint32_t Ah[4][4], Al[4][4], Bh[2][4], Bl[2][4];
            const int akb = kk * 2 + a_ksel;
            const int bkb = kk * 2 + b_ksel;
#pragma unroll
            for (int mi = 0; mi < 4; mi++) {
                int row = mi * 16 + a_rsel;              // 0..63
                uint32_t off = row * 128 + ((akb ^ (row & 7)) << 4);
                ldsm4(Ah[mi][0], Ah[mi][1], Ah[mi][2], Ah[mi][3], stA + off);
                ldsm4(Al[mi][0], Al[mi][1], Al[mi][2], Al[mi][3], stA + 8192 + off);
            }
#pragma unroll
            for (int nt = 0; nt < 2; nt++) {
                int nrow = wn + nt * 16 + b_rsel;
                uint32_t off = nrow * 128 + ((bkb ^ (nrow & 7)) << 4);
                ldsm4(Bh[nt][0], Bh[nt][1], Bh[nt][2], Bh[nt][3], stB + off);
                ldsm4(Bl[nt][0], Bl[nt][1], Bl[nt][2], Bl[nt][3], stB + 16384 + off);
            }
#pragma unroll
            for (int mi = 0; mi < 4; mi++)
#pragma unroll
                for (int ni = 0; ni < 4; ni++) {
                    const int nt = ni >> 1, hf = (ni & 1) * 2;
                    hmma(acc[mi][ni], Ah[mi], &Bh[nt][hf]);
                    hmma(acc[mi][ni], Ah[mi], &Bl[nt][hf]);
                    hmma(acc[mi][ni], Al[mi], &Bh[nt][hf]);
                }
        }
        __syncthreads();
        if (kt + 3 < NC) load_chunk(kt + 3, s);
        asm volatile("cp.async.commit_group;" ::: "memory");
    }

    // Epilogue: (au, gp) column pairs -> 7 Taylor coefficient planes
    const int erow = lane >> 2;
#pragma unroll
    for (int mi = 0; mi < 4; mi++)
#pragma unroll
        for (int ni = 0; ni < 4; ni++) {
            const int s = ((n0 + wn) >> 1) + ni * 4 + (lane & 3);
            const float lpv = __ldg(lp + s);
#pragma unroll
            for (int rr = 0; rr < 2; rr++) {
                const int row = m0 + mi * 16 + erow + rr * 8;
                const float au = acc[mi][ni][2 * rr + 0];
                const float gp = acc[mi][ni][2 * rr + 1];
                const float delta = gp - lpv;
                const float keep  = (fabsf(delta) <= 2.5f) ? 1.0f : 0.0f;
                __half* Up = Uout + (size_t)row * ldU + s;
                float p = delta;
                Up[0 * S_DIM] = __float2half_rn(au);
                Up[1 * S_DIM] = __float2half_rn(p * au);
                p *= delta; Up[2 * S_DIM] = __float2half_rn(p * (1.0f / 2.0f)   * au);
                p *= delta; Up[3 * S_DIM] = __float2half_rn(p * (1.0f / 6.0f)   * au);
                p *= delta; Up[4 * S_DIM] = __float2half_rn(p * (1.0f / 24.0f)  * au);
                p *= delta; Up[5 * S_DIM] = __float2half_rn(p * (1.0f / 120.0f) * au * keep);
                p *= delta; Up[6 * S_DIM] = __float2half_rn(p * (1.0f / 720.0f) * au * keep);
            }
        }
}

// ---------------------------------------------------------------------------
// Conversion / pack kernels
// ---------------------------------------------------------------------------
__global__ void split_kernel(const float* __restrict__ x, __half* __restrict__ hi,
                             __half* __restrict__ lo)
{
    size_t i = ((size_t)blockIdx.x * blockDim.x + threadIdx.x) * 4;
    float4 v = *(const float4*)(x + i);
    __half2 h01, h23, l01, l23;
    __half h, l;
    split1h(v.x, h, l); h01.x = h; l01.x = l;
    split1h(v.y, h, l); h01.y = h; l01.y = l;
    split1h(v.z, h, l); h23.x = h; l23.x = l;
    split1h(v.w, h, l); h23.y = h; l23.y = l;
    *(__half2*)(hi + i)     = h01;
    *(__half2*)(hi + i + 2) = h23;
    *(__half2*)(lo + i)     = l01;
    *(__half2*)(lo + i + 2) = l23;
}

// Interleave rows of two [R, 4096] matrices with hi/lo split (up_w/gate_w)
__global__ void pack_pair_hl_kernel(const float* __restrict__ even, const float* __restrict__ odd,
                                    __half* __restrict__ hi, __half* __restrict__ lo)
{
    size_t i = ((size_t)blockIdx.x * blockDim.x + threadIdx.x) * 4;
    size_t r = i >> 12;
    size_t h = i & 4095;
    const float* src = ((r & 1) ? odd : even) + ((r >> 1) << 12) + h;
    float4 v = *(const float4*)src;
    __half2 h01, h23, l01, l23;
    __half hh, ll;
    split1h(v.x, hh, ll); h01.x = hh; l01.x = ll;
    split1h(v.y, hh, ll); h01.y = hh; l01.y = ll;
    split1h(v.z, hh, ll); h23.x = hh; l23.x = ll;
    split1h(v.w, hh, ll); h23.y = hh; l23.y = ll;
    *(__half2*)(hi + i)     = h01;
    *(__half2*)(hi + i + 2) = h23;
    *(__half2*)(lo + i)     = l01;
    *(__half2*)(lo + i + 2) = l23;
}

// Interleave rows of two [R, 4096] matrices, hi only (fg/fu)
__global__ void pack_pair_hi_kernel(const float* __restrict__ even, const float* __restrict__ odd,
                                    __half* __restrict__ hi)
{
    size_t i = ((size_t)blockIdx.x * blockDim.x + threadIdx.x) * 4;
    size_t r = i >> 12;
    size_t h = i & 4095;
    const float* src = ((r & 1) ? odd : even) + ((r >> 1) << 12) + h;
    float4 v = *(const float4*)src;
    __half2 h01, h23;
    h01.x = __float2half_rn(v.x); h01.y = __float2half_rn(v.y);
    h23.x = __float2half_rn(v.z); h23.y = __float2half_rn(v.w);
    *(__half2*)(hi + i)     = h01;
    *(__half2*)(hi + i + 2) = h23;
}

// g_WD cols 0..7167: block 0 = local_approx_output, block idx+1 = fuse[:,:,idx]
__global__ void pack_W_kernel(const float* __restrict__ lao, const float* __restrict__ fuse)
{
    int i = blockIdx.x * blockDim.x + threadIdx.x;      // over H*S
    int s = i & (S_DIM - 1);
    size_t base = (size_t)(i >> 10) * KW + s;
    g_WD[base] = __float2half_rn(lao[i]);
    const float* f = fuse + (size_t)i * 6;
#pragma unroll
    for (int idx = 0; idx < 6; idx++)
        g_WD[base + (idx + 1) * S_DIM] = __float2half_rn(f[idx]);
}

// fd [H, F] -> g_WD cols 7168..17151 (row stride KW)
__global__ void cvt_fd_kernel(const float* __restrict__ fd)
{
    size_t i = ((size_t)blockIdx.x * blockDim.x + threadIdx.x) * 4;  // over H*F
    size_t h = i / F_DIM;
    size_t j = i - h * F_DIM;          // F_DIM % 4 == 0 -> no row crossing
    float4 v = *(const float4*)(fd + i);
    __half* dst = g_WD + h * KW + KU + j;
    __half2 h01, h23;
    h01.x = __float2half_rn(v.x); h01.y = __float2half_rn(v.y);
    h23.x = __float2half_rn(v.z); h23.y = __float2half_rn(v.w);
    *(__half2*)(dst)     = h01;
    *(__half2*)(dst + 2) = h23;
}

// ---------------------------------------------------------------------------
// Launch: graph-capturable, two-stream capture-fork; B-side weight
// conversions co-reside with the (low-register) gemm1_u.
// ---------------------------------------------------------------------------
extern "C" void kernel_launch(void* const* d_in, const int* in_sizes, int n_in,
                              void* d_out, int out_size)
{
    const float* X   = (const float*)d_in[0];
    const float* upw = (const float*)d_in[1];
    const float* gw  = (const float*)d_in[2];
    const float* lp  = (const float*)d_in[3];
    const float* lao = (const float*)d_in[4];
    const float* fw  = (const float*)d_in[5];
    const float* fg  = (const float*)d_in[7];
    const float* fu  = (const float*)d_in[8];
    const float* fd  = (const float*)d_in[9];
    float* out = (float*)d_out;

    cudaFuncSetAttribute(gemm_1t<0,128,4>, cudaFuncAttributeMaxDynamicSharedMemorySize, K1_SMEM_128);
    cudaFuncSetAttribute(gemm_1t<2,256,8>, cudaFuncAttributeMaxDynamicSharedMemorySize, K1_SMEM_256);
    cudaFuncSetAttribute(gemm1_u,          cudaFuncAttributeMaxDynamicSharedMemorySize, K2_SMEM);

    __half *p_Xhi, *p_Xlo, *p_ugh, *p_ugl, *p_fgfuh, *p_UA, *p_WD;
    cudaGetSymbolAddress((void**)&p_Xhi,   g_Xhi);
    cudaGetSymbolAddress((void**)&p_Xlo,   g_Xlo);
    cudaGetSymbolAddress((void**)&p_ugh,   g_ugh);
    cudaGetSymbolAddress((void**)&p_ugl,   g_ugl);
    cudaGetSymbolAddress((void**)&p_fgfuh, g_fgfuh);
    cudaGetSymbolAddress((void**)&p_UA,    g_UA);
    cudaGetSymbolAddress((void**)&p_WD,    g_WD);

    const dim3 blk(256);
    const size_t MH  = (size_t)M_TOK * H_DIM;
    const size_t SH2 = (size_t)2 * S_DIM * H_DIM;
    const size_t FH2 = (size_t)2 * F_DIM * H_DIM;
    const size_t HF  = (size_t)H_DIM * F_DIM;

    // Side stream + fork/join events (created fresh each call; never
    // destroyed mid-capture; handle count bounded by the harness's calls).
    cudaStream_t sB;
    cudaStreamCreateWithFlags(&sB, cudaStreamNonBlocking);
    cudaEvent_t eFork, eJoinB1;
    cudaEventCreateWithFlags(&eFork,   cudaEventDisableTiming);
    cudaEventCreateWithFlags(&eJoinB1, cudaEventDisableTiming);

    cudaEventRecord(eFork, 0);
    cudaStreamWaitEvent(sB, eFork, 0);

    // ---- Stream B: weight conversions (co-reside with gemm1_u) ----
    pack_pair_hi_kernel<<<(unsigned)(FH2 / 1024), blk, 0, sB>>>(fg, fu, p_fgfuh);
    pack_W_kernel<<<(H_DIM * S_DIM) / 256, blk, 0, sB>>>(lao, fw);
    cvt_fd_kernel<<<(unsigned)(HF / 1024), blk, 0, sB>>>(fd);
    cudaEventRecord(eJoinB1, sB);

    // ---- Default stream: A-side conversions + gemm1_u ----
    split_kernel<<<(unsigned)(MH / 1024), blk>>>(X, p_Xhi, p_Xlo);
    pack_pair_hl_kernel<<<(unsigned)(SH2 / 1024), blk>>>(upw, gw, p_ugh, p_ugl);

    // gemm1 (fp16x3, mask-exact): X @ [up_w;gate_w]^T -> U planes of g_UA
    // 64x128 CTAs, 128 threads, dynamic smem = K2_SMEM (the R15 bug was
    // launching this with 0 bytes of dynamic shared memory).
    gemm1_u<<<dim3(2 * S_DIM / 128, M_TOK / 64), dim3(128), K2_SMEM, 0>>>(
        p_Xhi, p_Xlo, p_ugh, p_ugl, lp, p_UA, KW, 2 * S_DIM, H_DIM);

    cudaStreamWaitEvent(0, eJoinB1, 0);

    // Fused gate/up GEMM + silu epilogue -> act planes of g_UA (cols 7168+)
    gemm_1t<2,256,8><<<dim3(2 * F_DIM / 256, M_TOK / 128), blk, K1_SMEM_256>>>(
        p_Xhi, p_fgfuh, nullptr, p_UA + KU, KW, 2 * F_DIM, H_DIM);

    // Merged GEMM: out = [U | act] @ [Wcat | fd]^T   (K = 17152)
    gemm_1t<0,128,4><<<dim3(H_DIM / 128, M_TOK / 128), dim3(128), K1_SMEM_128>>>(
        p_UA, p_WD, out, nullptr, 0, H_DIM, KW);
}